// round 1
// baseline (speedup 1.0000x reference)
#include <cuda_runtime.h>
#include <math.h>

// ---------------- problem constants ----------------
#define BB    2
#define QQ    300
#define TSEQ  25
#define CDIM  256
#define NHEADS 8
#define HDIM  32
#define NL    4
#define NP    4
#define DFF   1024
#define LQTOT 7500            // Q*T
#define NTOK  15000           // B*LQ
#define NSEQ  600             // B*Q
#define SVAL  21760           // sum of level sizes

// ---------------- scratch (device globals; no allocation at run time) ----------
__device__ __align__(16) float g_qksum[NTOK * CDIM];
__device__ __align__(16) float g_qk[NTOK * 512];
__device__ __align__(16) float g_v[NTOK * CDIM];
__device__ __align__(16) float g_attn[NTOK * CDIM];
__device__ __align__(16) float g_res1[NTOK * CDIM];
__device__ __align__(16) float g_ln1[NTOK * CDIM];
__device__ __align__(16) float g_query[NTOK * CDIM];
__device__ __align__(16) float g_off[NTOK * CDIM];
__device__ __align__(16) float g_aw[NTOK * 128];
__device__ __align__(16) float g_value[(size_t)BB * SVAL * CDIM];
__device__ __align__(16) float g_accum[NTOK * CDIM];
__device__ __align__(16) float g_res2[NTOK * CDIM];
__device__ __align__(16) float g_ln2[NTOK * CDIM];
__device__ __align__(16) float g_ffn1[NTOK * DFF];
__device__ __align__(16) float g_res3[NTOK * CDIM];

// ---------------- elementwise add ----------------
__global__ void add_kernel(const float* __restrict__ a, const float* __restrict__ b,
                           float* __restrict__ out, int n) {
    int i = blockIdx.x * blockDim.x + threadIdx.x;
    if (i < n) out[i] = a[i] + b[i];
}

// ---------------- tiled SGEMM: C[M,N] = A[M,K] @ B[N,K]^T + bias (+epilogue) ---
// EPI: 0 = bias only, 1 = bias + relu, 2 = bias + residual
template <int EPI>
__global__ void sgemm_kernel(const float* __restrict__ A, const float* __restrict__ B,
                             const float* __restrict__ bias, const float* __restrict__ res,
                             float* __restrict__ Cm, int M, int N, int K) {
    __shared__ float As[16][64];
    __shared__ float Bs[16][64];
    const int bm = blockIdx.y * 64;
    const int bn = blockIdx.x * 64;
    const int tx = threadIdx.x & 15;
    const int ty = threadIdx.x >> 4;

    float acc[4][4];
#pragma unroll
    for (int i = 0; i < 4; i++)
#pragma unroll
        for (int j = 0; j < 4; j++) acc[i][j] = 0.f;

    const int lrow = threadIdx.x >> 2;        // 0..63
    const int lk   = (threadIdx.x & 3) * 4;   // 0,4,8,12

    for (int k0 = 0; k0 < K; k0 += 16) {
        int ar = bm + lrow;
        float4 av = make_float4(0.f, 0.f, 0.f, 0.f);
        if (ar < M) av = *(const float4*)(A + (size_t)ar * K + k0 + lk);
        As[lk + 0][lrow] = av.x; As[lk + 1][lrow] = av.y;
        As[lk + 2][lrow] = av.z; As[lk + 3][lrow] = av.w;

        int br = bn + lrow;   // N is always a multiple of 64 here
        float4 bv = *(const float4*)(B + (size_t)br * K + k0 + lk);
        Bs[lk + 0][lrow] = bv.x; Bs[lk + 1][lrow] = bv.y;
        Bs[lk + 2][lrow] = bv.z; Bs[lk + 3][lrow] = bv.w;
        __syncthreads();

#pragma unroll
        for (int k = 0; k < 16; k++) {
            float4 a4 = *(const float4*)&As[k][ty * 4];
            float4 b4 = *(const float4*)&Bs[k][tx * 4];
            float a[4] = {a4.x, a4.y, a4.z, a4.w};
            float b[4] = {b4.x, b4.y, b4.z, b4.w};
#pragma unroll
            for (int i = 0; i < 4; i++)
#pragma unroll
                for (int j = 0; j < 4; j++) acc[i][j] = fmaf(a[i], b[j], acc[i][j]);
        }
        __syncthreads();
    }

#pragma unroll
    for (int i = 0; i < 4; i++) {
        int r = bm + ty * 4 + i;
        if (r >= M) continue;
#pragma unroll
        for (int j = 0; j < 4; j++) {
            int c = bn + tx * 4 + j;
            float v = acc[i][j] + bias[c];
            if (EPI == 1) v = fmaxf(v, 0.f);
            if (EPI == 2) v += res[(size_t)r * N + c];
            Cm[(size_t)r * N + c] = v;
        }
    }
}

// ---------------- self-attention: one warp per (seq, head) ----------------
// qk: [NTOK,512] (Q in 0..255, K in 256..511), v: [NTOK,256] -> out [NTOK,256]
__global__ void attn_kernel(const float* __restrict__ qk, const float* __restrict__ v,
                            float* __restrict__ out) {
    const int seq  = blockIdx.x >> 1;               // 0..599
    const int w    = threadIdx.x >> 5;              // warp-in-block 0..3
    const int h    = ((blockIdx.x & 1) << 2) + w;   // head 0..7
    const int lane = threadIdx.x & 31;

    __shared__ float Ks[4][25][32];
    __shared__ float Vs[4][25][32];
    __shared__ float qs[4][32];
    __shared__ float ps[4][32];

    const size_t tokbase = (size_t)seq * TSEQ;
    for (int i = lane; i < TSEQ * 32; i += 32) {
        int r = i >> 5;
        Ks[w][r][lane] = qk[(tokbase + r) * 512 + 256 + h * 32 + lane];
        Vs[w][r][lane] = v[(tokbase + r) * 256 + h * 32 + lane];
    }
    __syncwarp();

    const float scale = 0.1767766952966369f;  // 1/sqrt(32)
    for (int i = 0; i < TSEQ; i++) {
        qs[w][lane] = qk[(tokbase + i) * 512 + h * 32 + lane];
        __syncwarp();
        float s = -1e30f;
        if (lane < TSEQ) {
            float a = 0.f;
#pragma unroll
            for (int d = 0; d < 32; d++) a = fmaf(qs[w][d], Ks[w][lane][d], a);
            s = a * scale;
        }
        float m = s;
#pragma unroll
        for (int o = 16; o; o >>= 1) m = fmaxf(m, __shfl_xor_sync(~0u, m, o));
        float p = (lane < TSEQ) ? expf(s - m) : 0.f;
        float sum = p;
#pragma unroll
        for (int o = 16; o; o >>= 1) sum += __shfl_xor_sync(~0u, sum, o);
        ps[w][lane] = p / sum;
        __syncwarp();
        float o = 0.f;
#pragma unroll
        for (int j = 0; j < TSEQ; j++) o = fmaf(ps[w][j], Vs[w][j][lane], o);
        out[(tokbase + i) * 256 + h * 32 + lane] = o;
        __syncwarp();
    }
}

// ---------------- layernorm over C=256 (block per row) ----------------
// optionally emits y2 = y + pos
__global__ void ln_kernel(const float* __restrict__ x, const float* __restrict__ g,
                          const float* __restrict__ b, float* __restrict__ y,
                          const float* __restrict__ pos, float* __restrict__ y2) {
    const int row = blockIdx.x;
    const int c = threadIdx.x;
    const size_t idx = (size_t)row * 256 + c;
    float v = x[idx];

    __shared__ float red[8];
    float s = v;
#pragma unroll
    for (int o = 16; o; o >>= 1) s += __shfl_xor_sync(~0u, s, o);
    if ((c & 31) == 0) red[c >> 5] = s;
    __syncthreads();
    float tot = red[0] + red[1] + red[2] + red[3] + red[4] + red[5] + red[6] + red[7];
    float mean = tot * (1.f / 256.f);
    float d = v - mean;
    float s2 = d * d;
#pragma unroll
    for (int o = 16; o; o >>= 1) s2 += __shfl_xor_sync(~0u, s2, o);
    __syncthreads();
    if ((c & 31) == 0) red[c >> 5] = s2;
    __syncthreads();
    float var = (red[0] + red[1] + red[2] + red[3] + red[4] + red[5] + red[6] + red[7]) * (1.f / 256.f);
    float out = d * rsqrtf(var + 1e-5f) * g[c] + b[c];
    y[idx] = out;
    if (y2) y2[idx] = out + pos[idx];
}

// ---------------- attention-weight softmax over 16 per (token, head) ----------
__global__ void aw_softmax_kernel(float* __restrict__ aw) {
    const int token = blockIdx.x;
    const int t = threadIdx.x;  // 0..127 : head = t/16, idx = t%16
    const size_t idx = (size_t)token * 128 + t;
    float v = aw[idx];
    float m = v;
#pragma unroll
    for (int o = 8; o; o >>= 1) m = fmaxf(m, __shfl_xor_sync(~0u, m, o, 16));
    float e = expf(v - m);
    float s = e;
#pragma unroll
    for (int o = 8; o; o >>= 1) s += __shfl_xor_sync(~0u, s, o, 16);
    aw[idx] = e / s;
}

// ---------------- deformable sampling: one warp per (token, head) -------------
__global__ void deform_kernel(const float* __restrict__ ref,
                              const int* __restrict__ shapes,
                              const int* __restrict__ lstart,
                              float* __restrict__ out) {
    const int token = blockIdx.x;        // 0..14999
    const int h = threadIdx.x >> 5;      // head
    const int lane = threadIdx.x & 31;   // head-dim
    const int b = token / LQTOT;
    const int lq = token - b * LQTOT;

    const float* offp = g_off + (size_t)token * 256 + h * 32;
    const float* awp  = g_aw + (size_t)token * 128 + h * 16;
    const float* refp = ref + ((size_t)(b * LQTOT + lq) * NL) * 2;
    const size_t vbase = ((size_t)b * SVAL) * 256;

    float acc = 0.f;
#pragma unroll
    for (int l = 0; l < NL; l++) {
        const int Hl = shapes[l * 2];
        const int Wl = shapes[l * 2 + 1];
        const int st = lstart[l];
        const float rx = refp[l * 2];
        const float ry = refp[l * 2 + 1];
        const float fW = (float)Wl, fH = (float)Hl;
#pragma unroll
        for (int p = 0; p < 4; p++) {
            float ox = offp[l * 8 + p * 2];
            float oy = offp[l * 8 + p * 2 + 1];
            float aww = awp[l * 4 + p];
            float lx = rx + ox / fW;
            float ly = ry + oy / fH;
            float x = lx * fW - 0.5f;
            float y = ly * fH - 0.5f;
            float fx0 = floorf(x), fy0 = floorf(y);
            float wx = x - fx0, wy = y - fy0;
            int x0 = (int)fx0, y0 = (int)fy0;
            float tw[4] = {(1.f - wx) * (1.f - wy), wx * (1.f - wy),
                           (1.f - wx) * wy, wx * wy};
            int xs[4] = {x0, x0 + 1, x0, x0 + 1};
            int ys[4] = {y0, y0, y0 + 1, y0 + 1};
#pragma unroll
            for (int tgt = 0; tgt < 4; tgt++) {
                int xi = xs[tgt], yi = ys[tgt];
                if (xi >= 0 && xi < Wl && yi >= 0 && yi < Hl) {
                    size_t vi = vbase + ((size_t)(st + yi * Wl + xi)) * 256 + h * 32 + lane;
                    acc = fmaf(g_value[vi], tw[tgt] * aww, acc);
                }
            }
        }
    }
    out[(size_t)token * 256 + h * 32 + lane] = acc;
}

// ---------------- launch ----------------
static float* sym(const void* s) {
    void* p = nullptr;
    cudaGetSymbolAddress(&p, s);
    return (float*)p;
}

extern "C" void kernel_launch(void* const* d_in, const int* in_sizes, int n_in,
                              void* d_out, int out_size) {
    const float* tgt  = (const float*)d_in[0];
    const float* pos  = (const float*)d_in[1];
    const float* ref  = (const float*)d_in[2];
    const float* src  = (const float*)d_in[3];
    const int* shapes = (const int*)d_in[4];
    const int* lstart = (const int*)d_in[5];
    const float* in_proj_w  = (const float*)d_in[6];
    const float* in_proj_b  = (const float*)d_in[7];
    const float* out_proj_w = (const float*)d_in[8];
    const float* out_proj_b = (const float*)d_in[9];
    const float* ln1_g = (const float*)d_in[10];
    const float* ln1_b = (const float*)d_in[11];
    const float* samp_off_w = (const float*)d_in[12];
    const float* samp_off_b = (const float*)d_in[13];
    const float* aw_w = (const float*)d_in[14];
    const float* aw_b = (const float*)d_in[15];
    const float* vp_w = (const float*)d_in[16];
    const float* vp_b = (const float*)d_in[17];
    const float* op_w = (const float*)d_in[18];
    const float* op_b = (const float*)d_in[19];
    const float* ln2_g = (const float*)d_in[20];
    const float* ln2_b = (const float*)d_in[21];
    const float* ffn1_w = (const float*)d_in[22];
    const float* ffn1_b = (const float*)d_in[23];
    const float* ffn2_w = (const float*)d_in[24];
    const float* ffn2_b = (const float*)d_in[25];
    const float* ln3_g = (const float*)d_in[26];
    const float* ln3_b = (const float*)d_in[27];

    float* p_qksum = sym(g_qksum);
    float* p_qk    = sym(g_qk);
    float* p_v     = sym(g_v);
    float* p_attn  = sym(g_attn);
    float* p_res1  = sym(g_res1);
    float* p_ln1   = sym(g_ln1);
    float* p_query = sym(g_query);
    float* p_off   = sym(g_off);
    float* p_aw    = sym(g_aw);
    float* p_value = sym(g_value);
    float* p_accum = sym(g_accum);
    float* p_res2  = sym(g_res2);
    float* p_ln2   = sym(g_ln2);
    float* p_ffn1  = sym(g_ffn1);
    float* p_res3  = sym(g_res3);

    const int n_elem = NTOK * CDIM;

    // qk-sum = tgt + pos
    add_kernel<<<(n_elem + 255) / 256, 256>>>(tgt, pos, p_qksum, n_elem);

    // QKV projections
    {
        dim3 grid(512 / 64, (NTOK + 63) / 64);
        sgemm_kernel<0><<<grid, 256>>>(p_qksum, in_proj_w, in_proj_b, nullptr, p_qk, NTOK, 512, CDIM);
    }
    {
        dim3 grid(256 / 64, (NTOK + 63) / 64);
        sgemm_kernel<0><<<grid, 256>>>(tgt, in_proj_w + 512 * CDIM, in_proj_b + 512, nullptr, p_v, NTOK, 256, CDIM);
    }

    // self attention
    attn_kernel<<<NSEQ * 2, 128>>>(p_qk, p_v, p_attn);

    // out-proj + residual(tgt)
    {
        dim3 grid(256 / 64, (NTOK + 63) / 64);
        sgemm_kernel<2><<<grid, 256>>>(p_attn, out_proj_w, out_proj_b, tgt, p_res1, NTOK, 256, CDIM);
    }
    // LN1 (+ emit query = ln1 + pos)
    ln_kernel<<<NTOK, 256>>>(p_res1, ln1_g, ln1_b, p_ln1, pos, p_query);

    // sampling offsets + attention weights
    {
        dim3 grid(256 / 64, (NTOK + 63) / 64);
        sgemm_kernel<0><<<grid, 256>>>(p_query, samp_off_w, samp_off_b, nullptr, p_off, NTOK, 256, CDIM);
    }
    {
        dim3 grid(128 / 64, (NTOK + 63) / 64);
        sgemm_kernel<0><<<grid, 256>>>(p_query, aw_w, aw_b, nullptr, p_aw, NTOK, 128, CDIM);
    }
    aw_softmax_kernel<<<NTOK, 128>>>(p_aw);

    // value projection [B*S, 256]
    {
        dim3 grid(256 / 64, (BB * SVAL + 63) / 64);
        sgemm_kernel<0><<<grid, 256>>>(src, vp_w, vp_b, nullptr, p_value, BB * SVAL, 256, CDIM);
    }

    // deformable sampling
    deform_kernel<<<NTOK, 256>>>(ref, shapes, lstart, p_accum);

    // output proj + residual(ln1) -> LN2
    {
        dim3 grid(256 / 64, (NTOK + 63) / 64);
        sgemm_kernel<2><<<grid, 256>>>(p_accum, op_w, op_b, p_ln1, p_res2, NTOK, 256, CDIM);
    }
    ln_kernel<<<NTOK, 256>>>(p_res2, ln2_g, ln2_b, p_ln2, nullptr, nullptr);

    // FFN
    {
        dim3 grid(DFF / 64, (NTOK + 63) / 64);
        sgemm_kernel<1><<<grid, 256>>>(p_ln2, ffn1_w, ffn1_b, nullptr, p_ffn1, NTOK, DFF, CDIM);
    }
    {
        dim3 grid(256 / 64, (NTOK + 63) / 64);
        sgemm_kernel<2><<<grid, 256>>>(p_ffn1, ffn2_w, ffn2_b, p_ln2, p_res3, NTOK, 256, DFF);
    }
    ln_kernel<<<NTOK, 256>>>(p_res3, ln3_g, ln3_b, (float*)d_out, nullptr, nullptr);
}

// round 2
// speedup vs baseline: 1.4099x; 1.4099x over previous
#include <cuda_runtime.h>
#include <math.h>

// ---------------- problem constants ----------------
#define BB    2
#define QQ    300
#define TSEQ  25
#define CDIM  256
#define NHEADS 8
#define HDIM  32
#define NL    4
#define NP    4
#define DFF   1024
#define LQTOT 7500            // Q*T
#define NTOK  15000           // B*LQ
#define NSEQ  600             // B*Q
#define SVAL  21760           // sum of level sizes

// ---------------- scratch (device globals; no allocation at run time) ----------
__device__ __align__(16) float g_qksum[NTOK * CDIM];
__device__ __align__(16) float g_qk[NTOK * 512];
__device__ __align__(16) float g_v[NTOK * CDIM];
__device__ __align__(16) float g_attn[NTOK * CDIM];
__device__ __align__(16) float g_res1[NTOK * CDIM];
__device__ __align__(16) float g_ln1[NTOK * CDIM];
__device__ __align__(16) float g_query[NTOK * CDIM];
__device__ __align__(16) float g_off[NTOK * CDIM];
__device__ __align__(16) float g_aw[NTOK * 128];
__device__ __align__(16) float g_value[(size_t)BB * SVAL * CDIM];
__device__ __align__(16) float g_accum[NTOK * CDIM];
__device__ __align__(16) float g_res2[NTOK * CDIM];
__device__ __align__(16) float g_ln2[NTOK * CDIM];
__device__ __align__(16) float g_ffn1[NTOK * DFF];
__device__ __align__(16) float g_res3[NTOK * CDIM];

// ---------------- elementwise add ----------------
__global__ void add_kernel(const float* __restrict__ a, const float* __restrict__ b,
                           float* __restrict__ out, int n) {
    int i = blockIdx.x * blockDim.x + threadIdx.x;
    if (i < n) out[i] = a[i] + b[i];
}

// ---------------- tiled SGEMM: C[M,N] = A[M,K] @ B[N,K]^T + bias (+epilogue) ---
// 128x64 tile, 256 threads, 8x4 microtile.
// EPI: 0 = bias only, 1 = bias + relu, 2 = bias + residual
template <int EPI>
__global__ __launch_bounds__(256) void sgemm_kernel(
        const float* __restrict__ A, const float* __restrict__ B,
        const float* __restrict__ bias, const float* __restrict__ res,
        float* __restrict__ Cm, int M, int N, int K) {
    __shared__ float As[16][128];
    __shared__ float Bs[16][64];
    const int bm = blockIdx.y * 128;
    const int bn = blockIdx.x * 64;
    const int tx = threadIdx.x & 15;   // N dir: 4 cols each
    const int ty = threadIdx.x >> 4;   // M dir: 8 rows each

    float acc[8][4];
#pragma unroll
    for (int i = 0; i < 8; i++)
#pragma unroll
        for (int j = 0; j < 4; j++) acc[i][j] = 0.f;

    // A-load mapping: 128 rows x 16 k, 2 float4 per thread
    const int arow = threadIdx.x >> 1;           // 0..127
    const int ak   = (threadIdx.x & 1) * 8;      // 0 or 8
    // B-load mapping: 64 rows x 16 k, 1 float4 per thread
    const int brow = threadIdx.x >> 2;           // 0..63
    const int bk   = (threadIdx.x & 3) * 4;      // 0,4,8,12

    for (int k0 = 0; k0 < K; k0 += 16) {
        int ar = bm + arow;
        float4 a0 = make_float4(0.f, 0.f, 0.f, 0.f);
        float4 a1 = a0;
        if (ar < M) {
            const float* ap = A + (size_t)ar * K + k0 + ak;
            a0 = *(const float4*)(ap);
            a1 = *(const float4*)(ap + 4);
        }
        As[ak + 0][arow] = a0.x; As[ak + 1][arow] = a0.y;
        As[ak + 2][arow] = a0.z; As[ak + 3][arow] = a0.w;
        As[ak + 4][arow] = a1.x; As[ak + 5][arow] = a1.y;
        As[ak + 6][arow] = a1.z; As[ak + 7][arow] = a1.w;

        float4 bv = *(const float4*)(B + (size_t)(bn + brow) * K + k0 + bk);
        Bs[bk + 0][brow] = bv.x; Bs[bk + 1][brow] = bv.y;
        Bs[bk + 2][brow] = bv.z; Bs[bk + 3][brow] = bv.w;
        __syncthreads();

#pragma unroll
        for (int k = 0; k < 16; k++) {
            float4 av0 = *(const float4*)&As[k][ty * 8];
            float4 av1 = *(const float4*)&As[k][ty * 8 + 4];
            float4 b4  = *(const float4*)&Bs[k][tx * 4];
            float a[8] = {av0.x, av0.y, av0.z, av0.w, av1.x, av1.y, av1.z, av1.w};
            float b[4] = {b4.x, b4.y, b4.z, b4.w};
#pragma unroll
            for (int i = 0; i < 8; i++)
#pragma unroll
                for (int j = 0; j < 4; j++) acc[i][j] = fmaf(a[i], b[j], acc[i][j]);
        }
        __syncthreads();
    }

    const int cbase = bn + tx * 4;
    float4 bia = *(const float4*)(bias + cbase);
#pragma unroll
    for (int i = 0; i < 8; i++) {
        int r = bm + ty * 8 + i;
        if (r >= M) continue;
        float4 v = make_float4(acc[i][0] + bia.x, acc[i][1] + bia.y,
                               acc[i][2] + bia.z, acc[i][3] + bia.w);
        if (EPI == 1) {
            v.x = fmaxf(v.x, 0.f); v.y = fmaxf(v.y, 0.f);
            v.z = fmaxf(v.z, 0.f); v.w = fmaxf(v.w, 0.f);
        }
        if (EPI == 2) {
            float4 rr = *(const float4*)(res + (size_t)r * N + cbase);
            v.x += rr.x; v.y += rr.y; v.z += rr.z; v.w += rr.w;
        }
        *(float4*)(Cm + (size_t)r * N + cbase) = v;
    }
}

// ---------------- self-attention: lane = query, warp = (seq, head) ----------
// qk: [NTOK,512] (Q 0..255, K 256..511), v: [NTOK,256] -> out [NTOK,256]
__global__ __launch_bounds__(128) void attn_kernel(
        const float* __restrict__ qk, const float* __restrict__ v,
        float* __restrict__ out) {
    const int seq  = blockIdx.x >> 1;               // 0..599
    const int w    = threadIdx.x >> 5;              // warp-in-block 0..3
    const int h    = ((blockIdx.x & 1) << 2) + w;   // head 0..7
    const int lane = threadIdx.x & 31;

    __shared__ float Ks[4][25][32];
    __shared__ float Vs[4][25][32];
    __shared__ float Os[4][25][36];   // padded rows for store bank spread

    const size_t tokbase = (size_t)seq * TSEQ;
    // coalesced K/V stage
    for (int i = lane; i < TSEQ * 32; i += 32) {
        int r = i >> 5;
        Ks[w][r][lane] = qk[(tokbase + r) * 512 + 256 + h * 32 + lane];
        Vs[w][r][lane] = v[(tokbase + r) * 256 + h * 32 + lane];
    }
    __syncwarp();

    if (lane < TSEQ) {
        // q for this lane's query, in registers
        float4 q[8];
        const float4* qp = (const float4*)(qk + (tokbase + lane) * 512 + h * 32);
#pragma unroll
        for (int i = 0; i < 8; i++) q[i] = qp[i];

        const float scale = 0.1767766952966369f;  // 1/sqrt(32)
        float p[25];
        float m = -1e30f;
#pragma unroll
        for (int j = 0; j < TSEQ; j++) {
            const float4* kp = (const float4*)Ks[w][j];  // broadcast reads
            float a = 0.f;
#pragma unroll
            for (int i = 0; i < 8; i++) {
                float4 k4 = kp[i];
                a = fmaf(q[i].x, k4.x, a);
                a = fmaf(q[i].y, k4.y, a);
                a = fmaf(q[i].z, k4.z, a);
                a = fmaf(q[i].w, k4.w, a);
            }
            p[j] = a * scale;
            m = fmaxf(m, p[j]);
        }
        float sum = 0.f;
#pragma unroll
        for (int j = 0; j < TSEQ; j++) { p[j] = __expf(p[j] - m); sum += p[j]; }
        const float inv = 1.f / sum;

#pragma unroll
        for (int d4 = 0; d4 < 8; d4++) {
            float4 o = make_float4(0.f, 0.f, 0.f, 0.f);
#pragma unroll
            for (int j = 0; j < TSEQ; j++) {
                float4 v4 = ((const float4*)Vs[w][j])[d4];  // broadcast
                o.x = fmaf(p[j], v4.x, o.x);
                o.y = fmaf(p[j], v4.y, o.y);
                o.z = fmaf(p[j], v4.z, o.z);
                o.w = fmaf(p[j], v4.w, o.w);
            }
            float* orow = &Os[w][lane][d4 * 4];
            orow[0] = o.x * inv; orow[1] = o.y * inv;
            orow[2] = o.z * inv; orow[3] = o.w * inv;
        }
    }
    __syncwarp();
    // coalesced writeback
    for (int i = lane; i < TSEQ * 32; i += 32) {
        int r = i >> 5;
        out[(tokbase + r) * 256 + h * 32 + lane] = Os[w][r][lane];
    }
}

// ---------------- layernorm over C=256 (block per row) ----------------
// optionally emits y2 = y + pos
__global__ void ln_kernel(const float* __restrict__ x, const float* __restrict__ g,
                          const float* __restrict__ b, float* __restrict__ y,
                          const float* __restrict__ pos, float* __restrict__ y2) {
    const int row = blockIdx.x;
    const int c = threadIdx.x;
    const size_t idx = (size_t)row * 256 + c;
    float v = x[idx];

    __shared__ float red[8];
    float s = v;
#pragma unroll
    for (int o = 16; o; o >>= 1) s += __shfl_xor_sync(~0u, s, o);
    if ((c & 31) == 0) red[c >> 5] = s;
    __syncthreads();
    float tot = red[0] + red[1] + red[2] + red[3] + red[4] + red[5] + red[6] + red[7];
    float mean = tot * (1.f / 256.f);
    float d = v - mean;
    float s2 = d * d;
#pragma unroll
    for (int o = 16; o; o >>= 1) s2 += __shfl_xor_sync(~0u, s2, o);
    __syncthreads();
    if ((c & 31) == 0) red[c >> 5] = s2;
    __syncthreads();
    float var = (red[0] + red[1] + red[2] + red[3] + red[4] + red[5] + red[6] + red[7]) * (1.f / 256.f);
    float out = d * rsqrtf(var + 1e-5f) * g[c] + b[c];
    y[idx] = out;
    if (y2) y2[idx] = out + pos[idx];
}

// ---------------- attention-weight softmax over 16 per (token, head) ----------
__global__ void aw_softmax_kernel(float* __restrict__ aw) {
    const int token = blockIdx.x;
    const int t = threadIdx.x;  // 0..127 : head = t/16, idx = t%16
    const size_t idx = (size_t)token * 128 + t;
    float v = aw[idx];
    float m = v;
#pragma unroll
    for (int o = 8; o; o >>= 1) m = fmaxf(m, __shfl_xor_sync(~0u, m, o, 16));
    float e = __expf(v - m);
    float s = e;
#pragma unroll
    for (int o = 8; o; o >>= 1) s += __shfl_xor_sync(~0u, s, o, 16);
    aw[idx] = e / s;
}

// ---------------- deformable sampling: one warp per (token, head) -------------
__global__ void deform_kernel(const float* __restrict__ ref,
                              const int* __restrict__ shapes,
                              const int* __restrict__ lstart,
                              float* __restrict__ out) {
    const int token = blockIdx.x;        // 0..14999
    const int h = threadIdx.x >> 5;      // head
    const int lane = threadIdx.x & 31;   // head-dim
    const int b = token / LQTOT;
    const int lq = token - b * LQTOT;

    const float* offp = g_off + (size_t)token * 256 + h * 32;
    const float* awp  = g_aw + (size_t)token * 128 + h * 16;
    const float* refp = ref + ((size_t)(b * LQTOT + lq) * NL) * 2;
    const size_t vbase = ((size_t)b * SVAL) * 256;

    float acc = 0.f;
#pragma unroll
    for (int l = 0; l < NL; l++) {
        const int Hl = shapes[l * 2];
        const int Wl = shapes[l * 2 + 1];
        const int st = lstart[l];
        const float rx = refp[l * 2];
        const float ry = refp[l * 2 + 1];
        const float fW = (float)Wl, fH = (float)Hl;
#pragma unroll
        for (int p = 0; p < 4; p++) {
            float ox = offp[l * 8 + p * 2];
            float oy = offp[l * 8 + p * 2 + 1];
            float aww = awp[l * 4 + p];
            float lx = rx + ox / fW;
            float ly = ry + oy / fH;
            float x = lx * fW - 0.5f;
            float y = ly * fH - 0.5f;
            float fx0 = floorf(x), fy0 = floorf(y);
            float wx = x - fx0, wy = y - fy0;
            int x0 = (int)fx0, y0 = (int)fy0;
            float tw[4] = {(1.f - wx) * (1.f - wy), wx * (1.f - wy),
                           (1.f - wx) * wy, wx * wy};
            int xs[4] = {x0, x0 + 1, x0, x0 + 1};
            int ys[4] = {y0, y0, y0 + 1, y0 + 1};
#pragma unroll
            for (int tgt = 0; tgt < 4; tgt++) {
                int xi = xs[tgt], yi = ys[tgt];
                if (xi >= 0 && xi < Wl && yi >= 0 && yi < Hl) {
                    size_t vi = vbase + ((size_t)(st + yi * Wl + xi)) * 256 + h * 32 + lane;
                    acc = fmaf(g_value[vi], tw[tgt] * aww, acc);
                }
            }
        }
    }
    out[(size_t)token * 256 + h * 32 + lane] = acc;
}

// ---------------- launch ----------------
static float* sym(const void* s) {
    void* p = nullptr;
    cudaGetSymbolAddress(&p, s);
    return (float*)p;
}

extern "C" void kernel_launch(void* const* d_in, const int* in_sizes, int n_in,
                              void* d_out, int out_size) {
    const float* tgt  = (const float*)d_in[0];
    const float* pos  = (const float*)d_in[1];
    const float* ref  = (const float*)d_in[2];
    const float* src  = (const float*)d_in[3];
    const int* shapes = (const int*)d_in[4];
    const int* lstart = (const int*)d_in[5];
    const float* in_proj_w  = (const float*)d_in[6];
    const float* in_proj_b  = (const float*)d_in[7];
    const float* out_proj_w = (const float*)d_in[8];
    const float* out_proj_b = (const float*)d_in[9];
    const float* ln1_g = (const float*)d_in[10];
    const float* ln1_b = (const float*)d_in[11];
    const float* samp_off_w = (const float*)d_in[12];
    const float* samp_off_b = (const float*)d_in[13];
    const float* aw_w = (const float*)d_in[14];
    const float* aw_b = (const float*)d_in[15];
    const float* vp_w = (const float*)d_in[16];
    const float* vp_b = (const float*)d_in[17];
    const float* op_w = (const float*)d_in[18];
    const float* op_b = (const float*)d_in[19];
    const float* ln2_g = (const float*)d_in[20];
    const float* ln2_b = (const float*)d_in[21];
    const float* ffn1_w = (const float*)d_in[22];
    const float* ffn1_b = (const float*)d_in[23];
    const float* ffn2_w = (const float*)d_in[24];
    const float* ffn2_b = (const float*)d_in[25];
    const float* ln3_g = (const float*)d_in[26];
    const float* ln3_b = (const float*)d_in[27];

    float* p_qksum = sym(g_qksum);
    float* p_qk    = sym(g_qk);
    float* p_v     = sym(g_v);
    float* p_attn  = sym(g_attn);
    float* p_res1  = sym(g_res1);
    float* p_ln1   = sym(g_ln1);
    float* p_query = sym(g_query);
    float* p_off   = sym(g_off);
    float* p_aw    = sym(g_aw);
    float* p_value = sym(g_value);
    float* p_accum = sym(g_accum);
    float* p_res2  = sym(g_res2);
    float* p_ln2   = sym(g_ln2);
    float* p_ffn1  = sym(g_ffn1);
    float* p_res3  = sym(g_res3);

    const int n_elem = NTOK * CDIM;

    // qk-sum = tgt + pos
    add_kernel<<<(n_elem + 255) / 256, 256>>>(tgt, pos, p_qksum, n_elem);

    // QKV projections
    {
        dim3 grid(512 / 64, (NTOK + 127) / 128);
        sgemm_kernel<0><<<grid, 256>>>(p_qksum, in_proj_w, in_proj_b, nullptr, p_qk, NTOK, 512, CDIM);
    }
    {
        dim3 grid(256 / 64, (NTOK + 127) / 128);
        sgemm_kernel<0><<<grid, 256>>>(tgt, in_proj_w + 512 * CDIM, in_proj_b + 512, nullptr, p_v, NTOK, 256, CDIM);
    }

    // self attention
    attn_kernel<<<NSEQ * 2, 128>>>(p_qk, p_v, p_attn);

    // out-proj + residual(tgt)
    {
        dim3 grid(256 / 64, (NTOK + 127) / 128);
        sgemm_kernel<2><<<grid, 256>>>(p_attn, out_proj_w, out_proj_b, tgt, p_res1, NTOK, 256, CDIM);
    }
    // LN1 (+ emit query = ln1 + pos)
    ln_kernel<<<NTOK, 256>>>(p_res1, ln1_g, ln1_b, p_ln1, pos, p_query);

    // sampling offsets + attention weights
    {
        dim3 grid(256 / 64, (NTOK + 127) / 128);
        sgemm_kernel<0><<<grid, 256>>>(p_query, samp_off_w, samp_off_b, nullptr, p_off, NTOK, 256, CDIM);
    }
    {
        dim3 grid(128 / 64, (NTOK + 127) / 128);
        sgemm_kernel<0><<<grid, 256>>>(p_query, aw_w, aw_b, nullptr, p_aw, NTOK, 128, CDIM);
    }
    aw_softmax_kernel<<<NTOK, 128>>>(p_aw);

    // value projection [B*S, 256]
    {
        dim3 grid(256 / 64, (BB * SVAL + 127) / 128);
        sgemm_kernel<0><<<grid, 256>>>(src, vp_w, vp_b, nullptr, p_value, BB * SVAL, 256, CDIM);
    }

    // deformable sampling
    deform_kernel<<<NTOK, 256>>>(ref, shapes, lstart, p_accum);

    // output proj + residual(ln1) -> LN2
    {
        dim3 grid(256 / 64, (NTOK + 127) / 128);
        sgemm_kernel<2><<<grid, 256>>>(p_accum, op_w, op_b, p_ln1, p_res2, NTOK, 256, CDIM);
    }
    ln_kernel<<<NTOK, 256>>>(p_res2, ln2_g, ln2_b, p_ln2, nullptr, nullptr);

    // FFN
    {
        dim3 grid(DFF / 64, (NTOK + 127) / 128);
        sgemm_kernel<1><<<grid, 256>>>(p_ln2, ffn1_w, ffn1_b, nullptr, p_ffn1, NTOK, DFF, CDIM);
    }
    {
        dim3 grid(256 / 64, (NTOK + 127) / 128);
        sgemm_kernel<2><<<grid, 256>>>(p_ffn1, ffn2_w, ffn2_b, p_ln2, p_res3, NTOK, 256, DFF);
    }
    ln_kernel<<<NTOK, 256>>>(p_res3, ln3_g, ln3_b, (float*)d_out, nullptr, nullptr);
}

// round 4
// speedup vs baseline: 2.4529x; 1.7397x over previous
#include <cuda_runtime.h>
#include <math.h>
#include <stdint.h>

// ---------------- problem constants ----------------
#define BB    2
#define QQ    300
#define TSEQ  25
#define CDIM  256
#define NHEADS 8
#define HDIM  32
#define NL    4
#define NP    4
#define DFF   1024
#define LQTOT 7500
#define NTOK  15000
#define NSEQ  600
#define SVAL  21760

// ---------------- scratch ----------------
__device__ __align__(16) float g_qksum[NTOK * CDIM];
__device__ __align__(16) float g_qk[NTOK * 512];
__device__ __align__(16) float g_v[NTOK * CDIM];
__device__ __align__(16) float g_attn[NTOK * CDIM];
__device__ __align__(16) float g_res1[NTOK * CDIM];
__device__ __align__(16) float g_ln1[NTOK * CDIM];
__device__ __align__(16) float g_query[NTOK * CDIM];
__device__ __align__(16) float g_off[NTOK * CDIM];
__device__ __align__(16) float g_aw[NTOK * 128];
__device__ __align__(16) float g_value[(size_t)BB * SVAL * CDIM];
__device__ __align__(16) float g_accum[NTOK * CDIM];
__device__ __align__(16) float g_res2[NTOK * CDIM];
__device__ __align__(16) float g_ln2[NTOK * CDIM];
__device__ __align__(16) float g_ffn1[NTOK * DFF];
__device__ __align__(16) float g_res3[NTOK * CDIM];

// ================= helpers =================
__device__ __forceinline__ uint32_t smem_to_u32(const void* p) {
    uint32_t a;
    asm("{ .reg .u64 t; cvta.to.shared.u64 t, %1; cvt.u32.u64 %0, t; }" : "=r"(a) : "l"(p));
    return a;
}
__device__ __forceinline__ void cpasync16(uint32_t dst, const void* src) {
    asm volatile("cp.async.ca.shared.global [%0], [%1], 16;" :: "r"(dst), "l"(src) : "memory");
}
#define CP_COMMIT() asm volatile("cp.async.commit_group;" ::: "memory")

// load fp32 from shared + round to tf32 bits
__device__ __forceinline__ uint32_t lds_tf32(uint32_t a) {
    float f;
    asm volatile("ld.shared.f32 %0, [%1];" : "=f"(f) : "r"(a));
    uint32_t r;
    asm volatile("cvt.rn.tf32.f32 %0, %1;" : "=r"(r) : "f"(f));
    return r;
}

__device__ __forceinline__ void mma_tf32(float* d, const uint32_t* a, const uint32_t* b) {
    asm volatile(
        "mma.sync.aligned.m16n8k8.row.col.f32.tf32.tf32.f32 "
        "{%0,%1,%2,%3}, {%4,%5,%6,%7}, {%8,%9}, {%0,%1,%2,%3};"
        : "+f"(d[0]), "+f"(d[1]), "+f"(d[2]), "+f"(d[3])
        : "r"(a[0]), "r"(a[1]), "r"(a[2]), "r"(a[3]), "r"(b[0]), "r"(b[1]));
}

// ================= tf32 mma.sync GEMM =================
// C[M,N] = A[M,K] @ B[N,K]^T + bias;  EPI: 0 none, 1 relu, 2 +res
// grid = (N/128, ceil(M/128)), 256 threads, 64 KB dyn smem (2 x (A16K + B16K)).
// SMEM chunk layout: 128 rows x 32 fp32 (128B/row), 16B granule g stored at g^(row&7).
#define GEMM_SMEM 65536

__device__ __forceinline__ void fill_chunk(uint32_t sa, uint32_t sb,
                                           const float* __restrict__ A,
                                           const float* __restrict__ B,
                                           int bm, int bn, int M, int K, int k0, int tid) {
    const int r = tid >> 1;
    const int h = tid & 1;
    int ar = bm + r; if (ar >= M) ar = M - 1;
    const float* ap = A + (size_t)ar * K + k0 + h * 16;
    const float* bp = B + (size_t)(bn + r) * K + k0 + h * 16;
    const uint32_t da = sa + r * 128;
    const uint32_t db = sb + r * 128;
    const int x = r & 7;
#pragma unroll
    for (int j = 0; j < 4; j++) {
        const int g = h * 4 + j;
        const uint32_t doff = (uint32_t)((g ^ x) << 4);
        cpasync16(da + doff, ap + j * 4);
        cpasync16(db + doff, bp + j * 4);
    }
}

template <int EPI>
__global__ __launch_bounds__(256, 2) void gemm_mma(
        const float* __restrict__ A, const float* __restrict__ B,
        const float* __restrict__ bias, const float* __restrict__ res,
        float* __restrict__ Cm, int M, int N, int K) {
    extern __shared__ char smem[];
    const uint32_t smem_u = smem_to_u32(smem);
    const int tid = threadIdx.x;
    const int wid = tid >> 5;
    const int lane = tid & 31;
    const int wm = wid & 3;          // 4 warps in M: 32 rows each
    const int wn = wid >> 2;         // 2 warps in N: 64 cols each
    const int q = lane >> 2;         // 0..7
    const int t4 = (lane & 3) << 2;  // byte offset of word in granule
    const int bm = blockIdx.y * 128;
    const int bn = blockIdx.x * 128;

    float acc[2][8][4];
#pragma unroll
    for (int mt = 0; mt < 2; mt++)
#pragma unroll
        for (int nt = 0; nt < 8; nt++)
#pragma unroll
            for (int e = 0; e < 4; e++) acc[mt][nt][e] = 0.f;

    const int nc = K >> 5;  // chunks of 32

    // prologue: fill chunk 0 and 1
    fill_chunk(smem_u, smem_u + 16384, A, B, bm, bn, M, K, 0, tid);
    CP_COMMIT();
    fill_chunk(smem_u + 32768, smem_u + 49152, A, B, bm, bn, M, K, 32, tid);
    CP_COMMIT();

    const uint32_t aRow = (uint32_t)((wm * 32 + q) * 128);
    const uint32_t bRow = (uint32_t)((wn * 64 + q) * 128);

    for (int i = 0; i < nc; i++) {
        if (i + 1 < nc) { asm volatile("cp.async.wait_group 1;" ::: "memory"); }
        else            { asm volatile("cp.async.wait_group 0;" ::: "memory"); }
        __syncthreads();

        const uint32_t abuf = smem_u + (uint32_t)((i & 1) * 32768);
        const uint32_t bbuf = abuf + 16384;

#pragma unroll
        for (int ks = 0; ks < 4; ks++) {
            const uint32_t g0 = (uint32_t)(((ks * 2) ^ q) << 4);
            const uint32_t g1 = (uint32_t)(((ks * 2 + 1) ^ q) << 4);
            uint32_t Af[2][4];
#pragma unroll
            for (int mt = 0; mt < 2; mt++) {
                const uint32_t ro = abuf + aRow + (uint32_t)(mt * 2048);
                Af[mt][0] = lds_tf32(ro + g0 + t4);
                Af[mt][1] = lds_tf32(ro + 1024 + g0 + t4);
                Af[mt][2] = lds_tf32(ro + g1 + t4);
                Af[mt][3] = lds_tf32(ro + 1024 + g1 + t4);
            }
            uint32_t Bf[8][2];
#pragma unroll
            for (int nt = 0; nt < 8; nt++) {
                const uint32_t ro = bbuf + bRow + (uint32_t)(nt * 1024);
                Bf[nt][0] = lds_tf32(ro + g0 + t4);
                Bf[nt][1] = lds_tf32(ro + g1 + t4);
            }
#pragma unroll
            for (int mt = 0; mt < 2; mt++)
#pragma unroll
                for (int nt = 0; nt < 8; nt++)
                    mma_tf32(acc[mt][nt], Af[mt], Bf[nt]);
        }
        __syncthreads();

        if (i + 2 < nc) {
            const uint32_t fa = smem_u + (uint32_t)((i & 1) * 32768);
            fill_chunk(fa, fa + 16384, A, B, bm, bn, M, K, (i + 2) * 32, tid);
        }
        CP_COMMIT();  // keep group count in lockstep even when nothing filled
    }

    // ---- epilogue ----
    const int ccol = bn + wn * 64;
    const float* biasp = bias + ccol;
    const int t2 = (lane & 3) * 2;
#pragma unroll
    for (int mt = 0; mt < 2; mt++) {
#pragma unroll
        for (int rs = 0; rs < 2; rs++) {
            const int r = bm + wm * 32 + mt * 16 + q + rs * 8;
            if (r >= M) continue;
            float* cp = Cm + (size_t)r * N + ccol;
            const float* rp = (EPI == 2) ? res + (size_t)r * N + ccol : nullptr;
#pragma unroll
            for (int nt = 0; nt < 8; nt++) {
                const int c = nt * 8 + t2;
                float vx = acc[mt][nt][rs * 2 + 0] + biasp[c];
                float vy = acc[mt][nt][rs * 2 + 1] + biasp[c + 1];
                if (EPI == 1) { vx = fmaxf(vx, 0.f); vy = fmaxf(vy, 0.f); }
                if (EPI == 2) { vx += rp[c]; vy += rp[c + 1]; }
                *(float2*)(cp + c) = make_float2(vx, vy);
            }
        }
    }
}

// ---------------- elementwise add ----------------
__global__ void add_kernel(const float* __restrict__ a, const float* __restrict__ b,
                           float* __restrict__ out, int n) {
    int i = blockIdx.x * blockDim.x + threadIdx.x;
    if (i < n) out[i] = a[i] + b[i];
}

// ---------------- self-attention (lane = query) ----------
__global__ __launch_bounds__(128) void attn_kernel(
        const float* __restrict__ qk, const float* __restrict__ v,
        float* __restrict__ out) {
    const int seq  = blockIdx.x >> 1;
    const int w    = threadIdx.x >> 5;
    const int h    = ((blockIdx.x & 1) << 2) + w;
    const int lane = threadIdx.x & 31;

    __shared__ float Ks[4][25][32];
    __shared__ float Vs[4][25][32];
    __shared__ float Os[4][25][36];

    const size_t tokbase = (size_t)seq * TSEQ;
    for (int i = lane; i < TSEQ * 32; i += 32) {
        int r = i >> 5;
        Ks[w][r][lane] = qk[(tokbase + r) * 512 + 256 + h * 32 + lane];
        Vs[w][r][lane] = v[(tokbase + r) * 256 + h * 32 + lane];
    }
    __syncwarp();

    if (lane < TSEQ) {
        float4 qv[8];
        const float4* qp = (const float4*)(qk + (tokbase + lane) * 512 + h * 32);
#pragma unroll
        for (int i = 0; i < 8; i++) qv[i] = qp[i];

        const float scale = 0.1767766952966369f;
        float p[25];
        float m = -1e30f;
#pragma unroll
        for (int j = 0; j < TSEQ; j++) {
            const float4* kp = (const float4*)Ks[w][j];
            float a = 0.f;
#pragma unroll
            for (int i = 0; i < 8; i++) {
                float4 k4 = kp[i];
                a = fmaf(qv[i].x, k4.x, a); a = fmaf(qv[i].y, k4.y, a);
                a = fmaf(qv[i].z, k4.z, a); a = fmaf(qv[i].w, k4.w, a);
            }
            p[j] = a * scale;
            m = fmaxf(m, p[j]);
        }
        float sum = 0.f;
#pragma unroll
        for (int j = 0; j < TSEQ; j++) { p[j] = __expf(p[j] - m); sum += p[j]; }
        const float inv = 1.f / sum;
#pragma unroll
        for (int d4 = 0; d4 < 8; d4++) {
            float4 o = make_float4(0.f, 0.f, 0.f, 0.f);
#pragma unroll
            for (int j = 0; j < TSEQ; j++) {
                float4 v4 = ((const float4*)Vs[w][j])[d4];
                o.x = fmaf(p[j], v4.x, o.x); o.y = fmaf(p[j], v4.y, o.y);
                o.z = fmaf(p[j], v4.z, o.z); o.w = fmaf(p[j], v4.w, o.w);
            }
            float* orow = &Os[w][lane][d4 * 4];
            orow[0] = o.x * inv; orow[1] = o.y * inv;
            orow[2] = o.z * inv; orow[3] = o.w * inv;
        }
    }
    __syncwarp();
    for (int i = lane; i < TSEQ * 32; i += 32) {
        int r = i >> 5;
        out[(tokbase + r) * 256 + h * 32 + lane] = Os[w][r][lane];
    }
}

// ---------------- layernorm ----------------
__global__ void ln_kernel(const float* __restrict__ x, const float* __restrict__ g,
                          const float* __restrict__ b, float* __restrict__ y,
                          const float* __restrict__ pos, float* __restrict__ y2) {
    const int row = blockIdx.x;
    const int c = threadIdx.x;
    const size_t idx = (size_t)row * 256 + c;
    float v = x[idx];

    __shared__ float red[8];
    float s = v;
#pragma unroll
    for (int o = 16; o; o >>= 1) s += __shfl_xor_sync(~0u, s, o);
    if ((c & 31) == 0) red[c >> 5] = s;
    __syncthreads();
    float tot = red[0] + red[1] + red[2] + red[3] + red[4] + red[5] + red[6] + red[7];
    float mean = tot * (1.f / 256.f);
    float d = v - mean;
    float s2 = d * d;
#pragma unroll
    for (int o = 16; o; o >>= 1) s2 += __shfl_xor_sync(~0u, s2, o);
    __syncthreads();
    if ((c & 31) == 0) red[c >> 5] = s2;
    __syncthreads();
    float var = (red[0] + red[1] + red[2] + red[3] + red[4] + red[5] + red[6] + red[7]) * (1.f / 256.f);
    float out = d * rsqrtf(var + 1e-5f) * g[c] + b[c];
    y[idx] = out;
    if (y2) y2[idx] = out + pos[idx];
}

// ---------------- aw softmax ----------------
__global__ void aw_softmax_kernel(float* __restrict__ aw) {
    const int token = blockIdx.x;
    const int t = threadIdx.x;
    const size_t idx = (size_t)token * 128 + t;
    float v = aw[idx];
    float m = v;
#pragma unroll
    for (int o = 8; o; o >>= 1) m = fmaxf(m, __shfl_xor_sync(~0u, m, o, 16));
    float e = __expf(v - m);
    float s = e;
#pragma unroll
    for (int o = 8; o; o >>= 1) s += __shfl_xor_sync(~0u, s, o, 16);
    aw[idx] = e / s;
}

// ---------------- deformable sampling ----------------
__global__ void deform_kernel(const float* __restrict__ ref,
                              const int* __restrict__ shapes,
                              const int* __restrict__ lstart,
                              float* __restrict__ out) {
    const int token = blockIdx.x;
    const int h = threadIdx.x >> 5;
    const int lane = threadIdx.x & 31;
    const int b = token / LQTOT;
    const int lq = token - b * LQTOT;

    const float* offp = g_off + (size_t)token * 256 + h * 32;
    const float* awp  = g_aw + (size_t)token * 128 + h * 16;
    const float* refp = ref + ((size_t)(b * LQTOT + lq) * NL) * 2;
    const size_t vbase = ((size_t)b * SVAL) * 256;

    float acc = 0.f;
#pragma unroll
    for (int l = 0; l < NL; l++) {
        const int Hl = shapes[l * 2];
        const int Wl = shapes[l * 2 + 1];
        const int st = lstart[l];
        const float rx = refp[l * 2];
        const float ry = refp[l * 2 + 1];
        const float fW = (float)Wl, fH = (float)Hl;
#pragma unroll
        for (int p = 0; p < 4; p++) {
            float ox = offp[l * 8 + p * 2];
            float oy = offp[l * 8 + p * 2 + 1];
            float aww = awp[l * 4 + p];
            float x = (rx + ox / fW) * fW - 0.5f;
            float y = (ry + oy / fH) * fH - 0.5f;
            float fx0 = floorf(x), fy0 = floorf(y);
            float wx = x - fx0, wy = y - fy0;
            int x0 = (int)fx0, y0 = (int)fy0;
            float tw[4] = {(1.f - wx) * (1.f - wy), wx * (1.f - wy),
                           (1.f - wx) * wy, wx * wy};
            int xs[4] = {x0, x0 + 1, x0, x0 + 1};
            int ys[4] = {y0, y0, y0 + 1, y0 + 1};
#pragma unroll
            for (int tgt = 0; tgt < 4; tgt++) {
                int xi = xs[tgt], yi = ys[tgt];
                if (xi >= 0 && xi < Wl && yi >= 0 && yi < Hl) {
                    size_t vi = vbase + ((size_t)(st + yi * Wl + xi)) * 256 + h * 32 + lane;
                    acc = fmaf(g_value[vi], tw[tgt] * aww, acc);
                }
            }
        }
    }
    out[(size_t)token * 256 + h * 32 + lane] = acc;
}

// ---------------- launch ----------------
static float* sym(const void* s) {
    void* p = nullptr;
    cudaGetSymbolAddress(&p, s);
    return (float*)p;
}

template <int EPI>
static void launch_gemm(const float* A, const float* B, const float* bias,
                        const float* res, float* C, int M, int N, int K) {
    cudaFuncSetAttribute(gemm_mma<EPI>, cudaFuncAttributeMaxDynamicSharedMemorySize, GEMM_SMEM);
    dim3 grid(N / 128, (M + 127) / 128);
    gemm_mma<EPI><<<grid, 256, GEMM_SMEM>>>(A, B, bias, res, C, M, N, K);
}

extern "C" void kernel_launch(void* const* d_in, const int* in_sizes, int n_in,
                              void* d_out, int out_size) {
    const float* tgt  = (const float*)d_in[0];
    const float* pos  = (const float*)d_in[1];
    const float* ref  = (const float*)d_in[2];
    const float* src  = (const float*)d_in[3];
    const int* shapes = (const int*)d_in[4];
    const int* lstart = (const int*)d_in[5];
    const float* in_proj_w  = (const float*)d_in[6];
    const float* in_proj_b  = (const float*)d_in[7];
    const float* out_proj_w = (const float*)d_in[8];
    const float* out_proj_b = (const float*)d_in[9];
    const float* ln1_g = (const float*)d_in[10];
    const float* ln1_b = (const float*)d_in[11];
    const float* samp_off_w = (const float*)d_in[12];
    const float* samp_off_b = (const float*)d_in[13];
    const float* aw_w = (const float*)d_in[14];
    const float* aw_b = (const float*)d_in[15];
    const float* vp_w = (const float*)d_in[16];
    const float* vp_b = (const float*)d_in[17];
    const float* op_w = (const float*)d_in[18];
    const float* op_b = (const float*)d_in[19];
    const float* ln2_g = (const float*)d_in[20];
    const float* ln2_b = (const float*)d_in[21];
    const float* ffn1_w = (const float*)d_in[22];
    const float* ffn1_b = (const float*)d_in[23];
    const float* ffn2_w = (const float*)d_in[24];
    const float* ffn2_b = (const float*)d_in[25];
    const float* ln3_g = (const float*)d_in[26];
    const float* ln3_b = (const float*)d_in[27];

    float* p_qksum = sym(g_qksum);
    float* p_qk    = sym(g_qk);
    float* p_v     = sym(g_v);
    float* p_attn  = sym(g_attn);
    float* p_res1  = sym(g_res1);
    float* p_ln1   = sym(g_ln1);
    float* p_query = sym(g_query);
    float* p_off   = sym(g_off);
    float* p_aw    = sym(g_aw);
    float* p_value = sym(g_value);
    float* p_accum = sym(g_accum);
    float* p_res2  = sym(g_res2);
    float* p_ln2   = sym(g_ln2);
    float* p_ffn1  = sym(g_ffn1);
    float* p_res3  = sym(g_res3);

    const int n_elem = NTOK * CDIM;

    // qk-sum = tgt + pos
    add_kernel<<<(n_elem + 255) / 256, 256>>>(tgt, pos, p_qksum, n_elem);

    // QKV projections
    launch_gemm<0>(p_qksum, in_proj_w, in_proj_b, nullptr, p_qk, NTOK, 512, CDIM);
    launch_gemm<0>(tgt, in_proj_w + 512 * CDIM, in_proj_b + 512, nullptr, p_v, NTOK, 256, CDIM);

    attn_kernel<<<NSEQ * 2, 128>>>(p_qk, p_v, p_attn);

    launch_gemm<2>(p_attn, out_proj_w, out_proj_b, tgt, p_res1, NTOK, 256, CDIM);
    ln_kernel<<<NTOK, 256>>>(p_res1, ln1_g, ln1_b, p_ln1, pos, p_query);

    launch_gemm<0>(p_query, samp_off_w, samp_off_b, nullptr, p_off, NTOK, 256, CDIM);
    launch_gemm<0>(p_query, aw_w, aw_b, nullptr, p_aw, NTOK, 128, CDIM);
    aw_softmax_kernel<<<NTOK, 128>>>(p_aw);

    launch_gemm<0>(src, vp_w, vp_b, nullptr, p_value, BB * SVAL, 256, CDIM);

    deform_kernel<<<NTOK, 256>>>(ref, shapes, lstart, p_accum);

    launch_gemm<2>(p_accum, op_w, op_b, p_ln1, p_res2, NTOK, 256, CDIM);
    ln_kernel<<<NTOK, 256>>>(p_res2, ln2_g, ln2_b, p_ln2, nullptr, nullptr);

    launch_gemm<1>(p_ln2, ffn1_w, ffn1_b, nullptr, p_ffn1, NTOK, DFF, CDIM);
    launch_gemm<2>(p_ffn1, ffn2_w, ffn2_b, p_ln2, p_res3, NTOK, 256, DFF);
    ln_kernel<<<NTOK, 256>>>(p_res3, ln3_g, ln3_b, (float*)d_out, nullptr, nullptr);
}

// round 5
// speedup vs baseline: 2.8641x; 1.1677x over previous
#include <cuda_runtime.h>
#include <cuda_bf16.h>
#include <math.h>
#include <stdint.h>

// ---------------- problem constants ----------------
#define BB    2
#define QQ    300
#define TSEQ  25
#define CDIM  256
#define NHEADS 8
#define HDIM  32
#define NL    4
#define NP    4
#define DFF   1024
#define LQTOT 7500
#define NTOK  15000
#define NSEQ  600
#define SVAL  21760

// ---------------- fp32 scratch ----------------
__device__ __align__(16) float g_qk[NTOK * 512];
__device__ __align__(16) float g_v[NTOK * CDIM];
__device__ __align__(16) float g_res1[NTOK * CDIM];
__device__ __align__(16) float g_ln1[NTOK * CDIM];
__device__ __align__(16) float g_off[NTOK * CDIM];
__device__ __align__(16) float g_aw[NTOK * 128];
__device__ __align__(16) float g_value[(size_t)BB * SVAL * CDIM];
__device__ __align__(16) float g_res2[NTOK * CDIM];
__device__ __align__(16) float g_ln2[NTOK * CDIM];
__device__ __align__(16) float g_res3[NTOK * CDIM];

// ---------------- bf16 scratch (GEMM operands) ----------------
__device__ __align__(16) __nv_bfloat16 gb_tgt[NTOK * CDIM];
__device__ __align__(16) __nv_bfloat16 gb_qksum[NTOK * CDIM];
__device__ __align__(16) __nv_bfloat16 gb_attn[NTOK * CDIM];
__device__ __align__(16) __nv_bfloat16 gb_query[NTOK * CDIM];
__device__ __align__(16) __nv_bfloat16 gb_src[(size_t)BB * SVAL * CDIM];
__device__ __align__(16) __nv_bfloat16 gb_accum[NTOK * CDIM];
__device__ __align__(16) __nv_bfloat16 gb_ln2[NTOK * CDIM];
__device__ __align__(16) __nv_bfloat16 gb_ffn1[NTOK * DFF];
// weights
__device__ __align__(16) __nv_bfloat16 gb_inproj[768 * 256];
__device__ __align__(16) __nv_bfloat16 gb_outproj[256 * 256];
__device__ __align__(16) __nv_bfloat16 gb_soff[256 * 256];
__device__ __align__(16) __nv_bfloat16 gb_aww[128 * 256];
__device__ __align__(16) __nv_bfloat16 gb_vp[256 * 256];
__device__ __align__(16) __nv_bfloat16 gb_op[256 * 256];
__device__ __align__(16) __nv_bfloat16 gb_f1w[1024 * 256];
__device__ __align__(16) __nv_bfloat16 gb_f2w[256 * 1024];

// ================= helpers =================
__device__ __forceinline__ uint32_t smem_to_u32(const void* p) {
    uint32_t a;
    asm("{ .reg .u64 t; cvta.to.shared.u64 t, %1; cvt.u32.u64 %0, t; }" : "=r"(a) : "l"(p));
    return a;
}
__device__ __forceinline__ void cpasync16(uint32_t dst, const void* src) {
    asm volatile("cp.async.ca.shared.global [%0], [%1], 16;" :: "r"(dst), "l"(src) : "memory");
}
#define CP_COMMIT() asm volatile("cp.async.commit_group;" ::: "memory")

__device__ __forceinline__ uint32_t lds_u32(uint32_t a) {
    uint32_t r;
    asm volatile("ld.shared.b32 %0, [%1];" : "=r"(r) : "r"(a));
    return r;
}
__device__ __forceinline__ void mma_bf16(float* d, const uint32_t* a, const uint32_t* b) {
    asm volatile(
        "mma.sync.aligned.m16n8k16.row.col.f32.bf16.bf16.f32 "
        "{%0,%1,%2,%3}, {%4,%5,%6,%7}, {%8,%9}, {%0,%1,%2,%3};"
        : "+f"(d[0]), "+f"(d[1]), "+f"(d[2]), "+f"(d[3])
        : "r"(a[0]), "r"(a[1]), "r"(a[2]), "r"(a[3]), "r"(b[0]), "r"(b[1]));
}
__device__ __forceinline__ uint32_t pack_bf16(float x, float y) {
    uint32_t r;
    asm("cvt.rn.bf16x2.f32 %0, %1, %2;" : "=r"(r) : "f"(y), "f"(x));
    return r;
}

// ================= bf16 mma.sync GEMM =================
// C[M,N] = A[M,K] @ B[N,K]^T + bias;  EPI: 0 none, 1 relu, 2 +res
// OUTBF: 1 -> write bf16 output, 0 -> fp32
// grid = (N/128, ceil(M/128)), 256 threads, 64 KB dyn smem.
// chunk: K=64 bf16 (128B/row), 128 rows per tile, granule-16B XOR swizzle.
#define GEMM_SMEM 65536

__device__ __forceinline__ void fill_chunk_b(uint32_t sa, uint32_t sb,
                                             const __nv_bfloat16* __restrict__ A,
                                             const __nv_bfloat16* __restrict__ B,
                                             int bm, int bn, int M, int K, int k0, int tid) {
    const int r = tid & 127;
    const int which = tid >> 7;
    int ar = bm + r; if (ar >= M) ar = M - 1;
    const __nv_bfloat16* gp = which ? (B + (size_t)(bn + r) * K + k0)
                                    : (A + (size_t)ar * K + k0);
    const uint32_t d = (which ? sb : sa) + (uint32_t)(r * 128);
    const int x = r & 7;
#pragma unroll
    for (int j = 0; j < 8; j++)
        cpasync16(d + (uint32_t)((j ^ x) << 4), gp + j * 8);
}

template <int EPI, int OUTBF>
__global__ __launch_bounds__(256, 2) void gemm_mma(
        const __nv_bfloat16* __restrict__ A, const __nv_bfloat16* __restrict__ B,
        const float* __restrict__ bias, const float* __restrict__ res,
        void* __restrict__ Cout, int M, int N, int K) {
    extern __shared__ char smem[];
    const uint32_t smem_u = smem_to_u32(smem);
    const int tid = threadIdx.x;
    const int wid = tid >> 5;
    const int lane = tid & 31;
    const int wm = wid & 3;          // 4 warps in M: 32 rows each
    const int wn = wid >> 2;         // 2 warps in N: 64 cols each
    const int q = lane >> 2;         // 0..7
    const int t4 = (lane & 3) << 2;  // byte offset within granule
    const int bm = blockIdx.y * 128;
    const int bn = blockIdx.x * 128;

    float acc[2][8][4];
#pragma unroll
    for (int mt = 0; mt < 2; mt++)
#pragma unroll
        for (int nt = 0; nt < 8; nt++)
#pragma unroll
            for (int e = 0; e < 4; e++) acc[mt][nt][e] = 0.f;

    const int nc = K >> 6;  // chunks of 64

    fill_chunk_b(smem_u, smem_u + 16384, A, B, bm, bn, M, K, 0, tid);
    CP_COMMIT();
    fill_chunk_b(smem_u + 32768, smem_u + 49152, A, B, bm, bn, M, K, 64, tid);
    CP_COMMIT();

    const uint32_t aRow = (uint32_t)((wm * 32 + q) * 128);
    const uint32_t bRow = (uint32_t)((wn * 64 + q) * 128);

    for (int i = 0; i < nc; i++) {
        if (i + 1 < nc) { asm volatile("cp.async.wait_group 1;" ::: "memory"); }
        else            { asm volatile("cp.async.wait_group 0;" ::: "memory"); }
        __syncthreads();

        const uint32_t abuf = smem_u + (uint32_t)((i & 1) * 32768);
        const uint32_t bbuf = abuf + 16384;

#pragma unroll
        for (int ks = 0; ks < 4; ks++) {
            const uint32_t g0 = (uint32_t)((((ks << 1)    ) ^ q) << 4);
            const uint32_t g1 = (uint32_t)((((ks << 1) | 1) ^ q) << 4);
            uint32_t Af[2][4];
#pragma unroll
            for (int mt = 0; mt < 2; mt++) {
                const uint32_t ro = abuf + aRow + (uint32_t)(mt * 2048);
                Af[mt][0] = lds_u32(ro + g0 + t4);
                Af[mt][1] = lds_u32(ro + 1024 + g0 + t4);
                Af[mt][2] = lds_u32(ro + g1 + t4);
                Af[mt][3] = lds_u32(ro + 1024 + g1 + t4);
            }
            uint32_t Bf[8][2];
#pragma unroll
            for (int nt = 0; nt < 8; nt++) {
                const uint32_t ro = bbuf + bRow + (uint32_t)(nt * 1024);
                Bf[nt][0] = lds_u32(ro + g0 + t4);
                Bf[nt][1] = lds_u32(ro + g1 + t4);
            }
#pragma unroll
            for (int mt = 0; mt < 2; mt++)
#pragma unroll
                for (int nt = 0; nt < 8; nt++)
                    mma_bf16(acc[mt][nt], Af[mt], Bf[nt]);
        }
        __syncthreads();

        if (i + 2 < nc) {
            const uint32_t fa = smem_u + (uint32_t)((i & 1) * 32768);
            fill_chunk_b(fa, fa + 16384, A, B, bm, bn, M, K, (i + 2) * 64, tid);
        }
        CP_COMMIT();
    }

    // ---- epilogue ----
    const int ccol = bn + wn * 64;
    const float* biasp = bias + ccol;
    const int t2 = (lane & 3) * 2;
#pragma unroll
    for (int mt = 0; mt < 2; mt++) {
#pragma unroll
        for (int rs = 0; rs < 2; rs++) {
            const int r = bm + wm * 32 + mt * 16 + q + rs * 8;
            if (r >= M) continue;
            const float* rp = (EPI == 2) ? res + (size_t)r * N + ccol : nullptr;
#pragma unroll
            for (int nt = 0; nt < 8; nt++) {
                const int c = nt * 8 + t2;
                float vx = acc[mt][nt][rs * 2 + 0] + biasp[c];
                float vy = acc[mt][nt][rs * 2 + 1] + biasp[c + 1];
                if (EPI == 1) { vx = fmaxf(vx, 0.f); vy = fmaxf(vy, 0.f); }
                if (EPI == 2) { vx += rp[c]; vy += rp[c + 1]; }
                if (OUTBF) {
                    uint32_t* cp = (uint32_t*)((__nv_bfloat16*)Cout + (size_t)r * N + ccol + c);
                    *cp = pack_bf16(vx, vy);
                } else {
                    float* cp = (float*)Cout + (size_t)r * N + ccol + c;
                    *(float2*)cp = make_float2(vx, vy);
                }
            }
        }
    }
}

// ---------------- fp32 -> bf16 convert ----------------
__global__ void f2b_kernel(const float* __restrict__ in, __nv_bfloat16* __restrict__ out, int n4) {
    int i = blockIdx.x * blockDim.x + threadIdx.x;
    if (i < n4) {
        float4 v = ((const float4*)in)[i];
        uint2 o;
        o.x = pack_bf16(v.x, v.y);
        o.y = pack_bf16(v.z, v.w);
        ((uint2*)out)[i] = o;
    }
}

// ---------------- add (tgt+pos) -> bf16 ----------------
__global__ void addb_kernel(const float* __restrict__ a, const float* __restrict__ b,
                            __nv_bfloat16* __restrict__ out, int n4) {
    int i = blockIdx.x * blockDim.x + threadIdx.x;
    if (i < n4) {
        float4 x = ((const float4*)a)[i];
        float4 y = ((const float4*)b)[i];
        uint2 o;
        o.x = pack_bf16(x.x + y.x, x.y + y.y);
        o.y = pack_bf16(x.z + y.z, x.w + y.w);
        ((uint2*)out)[i] = o;
    }
}

// ---------------- self-attention (lane = query), bf16 out ----------
__global__ __launch_bounds__(128) void attn_kernel(
        const float* __restrict__ qk, const float* __restrict__ v,
        __nv_bfloat16* __restrict__ out) {
    const int seq  = blockIdx.x >> 1;
    const int w    = threadIdx.x >> 5;
    const int h    = ((blockIdx.x & 1) << 2) + w;
    const int lane = threadIdx.x & 31;

    __shared__ float Ks[4][25][32];
    __shared__ float Vs[4][25][32];
    __shared__ float Os[4][25][36];

    const size_t tokbase = (size_t)seq * TSEQ;
    for (int i = lane; i < TSEQ * 32; i += 32) {
        int r = i >> 5;
        Ks[w][r][lane] = qk[(tokbase + r) * 512 + 256 + h * 32 + lane];
        Vs[w][r][lane] = v[(tokbase + r) * 256 + h * 32 + lane];
    }
    __syncwarp();

    if (lane < TSEQ) {
        float4 qv[8];
        const float4* qp = (const float4*)(qk + (tokbase + lane) * 512 + h * 32);
#pragma unroll
        for (int i = 0; i < 8; i++) qv[i] = qp[i];

        const float scale = 0.1767766952966369f;
        float p[25];
        float m = -1e30f;
#pragma unroll
        for (int j = 0; j < TSEQ; j++) {
            const float4* kp = (const float4*)Ks[w][j];
            float a = 0.f;
#pragma unroll
            for (int i = 0; i < 8; i++) {
                float4 k4 = kp[i];
                a = fmaf(qv[i].x, k4.x, a); a = fmaf(qv[i].y, k4.y, a);
                a = fmaf(qv[i].z, k4.z, a); a = fmaf(qv[i].w, k4.w, a);
            }
            p[j] = a * scale;
            m = fmaxf(m, p[j]);
        }
        float sum = 0.f;
#pragma unroll
        for (int j = 0; j < TSEQ; j++) { p[j] = __expf(p[j] - m); sum += p[j]; }
        const float inv = 1.f / sum;
#pragma unroll
        for (int d4 = 0; d4 < 8; d4++) {
            float4 o = make_float4(0.f, 0.f, 0.f, 0.f);
#pragma unroll
            for (int j = 0; j < TSEQ; j++) {
                float4 v4 = ((const float4*)Vs[w][j])[d4];
                o.x = fmaf(p[j], v4.x, o.x); o.y = fmaf(p[j], v4.y, o.y);
                o.z = fmaf(p[j], v4.z, o.z); o.w = fmaf(p[j], v4.w, o.w);
            }
            float* orow = &Os[w][lane][d4 * 4];
            orow[0] = o.x * inv; orow[1] = o.y * inv;
            orow[2] = o.z * inv; orow[3] = o.w * inv;
        }
    }
    __syncwarp();
    for (int i = lane; i < TSEQ * 32; i += 32) {
        int r = i >> 5;
        out[(tokbase + r) * 256 + h * 32 + lane] = __float2bfloat16(Os[w][r][lane]);
    }
}

// ---------------- layernorm ----------------
// y fp32; y2b = bf16(y + pos) if pos != null; yb = bf16(y) if yb != null
__global__ void ln_kernel(const float* __restrict__ x, const float* __restrict__ g,
                          const float* __restrict__ b, float* __restrict__ y,
                          const float* __restrict__ pos, __nv_bfloat16* __restrict__ y2b,
                          __nv_bfloat16* __restrict__ yb) {
    const int row = blockIdx.x;
    const int c = threadIdx.x;
    const size_t idx = (size_t)row * 256 + c;
    float v = x[idx];

    __shared__ float red[8];
    float s = v;
#pragma unroll
    for (int o = 16; o; o >>= 1) s += __shfl_xor_sync(~0u, s, o);
    if ((c & 31) == 0) red[c >> 5] = s;
    __syncthreads();
    float tot = red[0] + red[1] + red[2] + red[3] + red[4] + red[5] + red[6] + red[7];
    float mean = tot * (1.f / 256.f);
    float d = v - mean;
    float s2 = d * d;
#pragma unroll
    for (int o = 16; o; o >>= 1) s2 += __shfl_xor_sync(~0u, s2, o);
    __syncthreads();
    if ((c & 31) == 0) red[c >> 5] = s2;
    __syncthreads();
    float var = (red[0] + red[1] + red[2] + red[3] + red[4] + red[5] + red[6] + red[7]) * (1.f / 256.f);
    float out = d * rsqrtf(var + 1e-5f) * g[c] + b[c];
    y[idx] = out;
    if (y2b) y2b[idx] = __float2bfloat16(out + pos[idx]);
    if (yb) yb[idx] = __float2bfloat16(out);
}

// ---------------- aw softmax ----------------
__global__ void aw_softmax_kernel(float* __restrict__ aw) {
    const int token = blockIdx.x;
    const int t = threadIdx.x;
    const size_t idx = (size_t)token * 128 + t;
    float v = aw[idx];
    float m = v;
#pragma unroll
    for (int o = 8; o; o >>= 1) m = fmaxf(m, __shfl_xor_sync(~0u, m, o, 16));
    float e = __expf(v - m);
    float s = e;
#pragma unroll
    for (int o = 8; o; o >>= 1) s += __shfl_xor_sync(~0u, s, o, 16);
    aw[idx] = e / s;
}

// ---------------- deformable sampling, bf16 out ----------------
__global__ void deform_kernel(const float* __restrict__ ref,
                              const int* __restrict__ shapes,
                              const int* __restrict__ lstart,
                              __nv_bfloat16* __restrict__ out) {
    const int token = blockIdx.x;
    const int h = threadIdx.x >> 5;
    const int lane = threadIdx.x & 31;
    const int b = token / LQTOT;
    const int lq = token - b * LQTOT;

    const float* offp = g_off + (size_t)token * 256 + h * 32;
    const float* awp  = g_aw + (size_t)token * 128 + h * 16;
    const float* refp = ref + ((size_t)(b * LQTOT + lq) * NL) * 2;
    const size_t vbase = ((size_t)b * SVAL) * 256;

    float acc = 0.f;
#pragma unroll
    for (int l = 0; l < NL; l++) {
        const int Hl = shapes[l * 2];
        const int Wl = shapes[l * 2 + 1];
        const int st = lstart[l];
        const float rx = refp[l * 2];
        const float ry = refp[l * 2 + 1];
        const float fW = (float)Wl, fH = (float)Hl;
#pragma unroll
        for (int p = 0; p < 4; p++) {
            float ox = offp[l * 8 + p * 2];
            float oy = offp[l * 8 + p * 2 + 1];
            float aww = awp[l * 4 + p];
            float x = (rx + ox / fW) * fW - 0.5f;
            float y = (ry + oy / fH) * fH - 0.5f;
            float fx0 = floorf(x), fy0 = floorf(y);
            float wx = x - fx0, wy = y - fy0;
            int x0 = (int)fx0, y0 = (int)fy0;
            float tw[4] = {(1.f - wx) * (1.f - wy), wx * (1.f - wy),
                           (1.f - wx) * wy, wx * wy};
            int xs[4] = {x0, x0 + 1, x0, x0 + 1};
            int ys[4] = {y0, y0, y0 + 1, y0 + 1};
#pragma unroll
            for (int tgt = 0; tgt < 4; tgt++) {
                int xi = xs[tgt], yi = ys[tgt];
                if (xi >= 0 && xi < Wl && yi >= 0 && yi < Hl) {
                    size_t vi = vbase + ((size_t)(st + yi * Wl + xi)) * 256 + h * 32 + lane;
                    acc = fmaf(g_value[vi], tw[tgt] * aww, acc);
                }
            }
        }
    }
    out[(size_t)token * 256 + h * 32 + lane] = __float2bfloat16(acc);
}

// ---------------- launch ----------------
static void* sym(const void* s) {
    void* p = nullptr;
    cudaGetSymbolAddress(&p, s);
    return p;
}

template <int EPI, int OUTBF>
static void launch_gemm(const __nv_bfloat16* A, const __nv_bfloat16* B, const float* bias,
                        const float* res, void* C, int M, int N, int K) {
    cudaFuncSetAttribute(gemm_mma<EPI, OUTBF>, cudaFuncAttributeMaxDynamicSharedMemorySize, GEMM_SMEM);
    dim3 grid(N / 128, (M + 127) / 128);
    gemm_mma<EPI, OUTBF><<<grid, 256, GEMM_SMEM>>>(A, B, bias, res, C, M, N, K);
}

static void convert(const float* in, __nv_bfloat16* out, int n) {
    int n4 = n / 4;
    f2b_kernel<<<(n4 + 255) / 256, 256>>>(in, out, n4);
}

extern "C" void kernel_launch(void* const* d_in, const int* in_sizes, int n_in,
                              void* d_out, int out_size) {
    const float* tgt  = (const float*)d_in[0];
    const float* pos  = (const float*)d_in[1];
    const float* ref  = (const float*)d_in[2];
    const float* src  = (const float*)d_in[3];
    const int* shapes = (const int*)d_in[4];
    const int* lstart = (const int*)d_in[5];
    const float* in_proj_w  = (const float*)d_in[6];
    const float* in_proj_b  = (const float*)d_in[7];
    const float* out_proj_w = (const float*)d_in[8];
    const float* out_proj_b = (const float*)d_in[9];
    const float* ln1_g = (const float*)d_in[10];
    const float* ln1_b = (const float*)d_in[11];
    const float* samp_off_w = (const float*)d_in[12];
    const float* samp_off_b = (const float*)d_in[13];
    const float* aw_w = (const float*)d_in[14];
    const float* aw_b = (const float*)d_in[15];
    const float* vp_w = (const float*)d_in[16];
    const float* vp_b = (const float*)d_in[17];
    const float* op_w = (const float*)d_in[18];
    const float* op_b = (const float*)d_in[19];
    const float* ln2_g = (const float*)d_in[20];
    const float* ln2_b = (const float*)d_in[21];
    const float* ffn1_w = (const float*)d_in[22];
    const float* ffn1_b = (const float*)d_in[23];
    const float* ffn2_w = (const float*)d_in[24];
    const float* ffn2_b = (const float*)d_in[25];
    const float* ln3_g = (const float*)d_in[26];
    const float* ln3_b = (const float*)d_in[27];

    float* p_qk    = (float*)sym(g_qk);
    float* p_v     = (float*)sym(g_v);
    float* p_res1  = (float*)sym(g_res1);
    float* p_ln1   = (float*)sym(g_ln1);
    float* p_off   = (float*)sym(g_off);
    float* p_aw    = (float*)sym(g_aw);
    float* p_value = (float*)sym(g_value);
    float* p_res2  = (float*)sym(g_res2);
    float* p_ln2   = (float*)sym(g_ln2);
    float* p_res3  = (float*)sym(g_res3);

    __nv_bfloat16* b_tgt   = (__nv_bfloat16*)sym(gb_tgt);
    __nv_bfloat16* b_qksum = (__nv_bfloat16*)sym(gb_qksum);
    __nv_bfloat16* b_attn  = (__nv_bfloat16*)sym(gb_attn);
    __nv_bfloat16* b_query = (__nv_bfloat16*)sym(gb_query);
    __nv_bfloat16* b_src   = (__nv_bfloat16*)sym(gb_src);
    __nv_bfloat16* b_accum = (__nv_bfloat16*)sym(gb_accum);
    __nv_bfloat16* b_ln2   = (__nv_bfloat16*)sym(gb_ln2);
    __nv_bfloat16* b_ffn1  = (__nv_bfloat16*)sym(gb_ffn1);
    __nv_bfloat16* b_inproj = (__nv_bfloat16*)sym(gb_inproj);
    __nv_bfloat16* b_outproj = (__nv_bfloat16*)sym(gb_outproj);
    __nv_bfloat16* b_soff  = (__nv_bfloat16*)sym(gb_soff);
    __nv_bfloat16* b_aww   = (__nv_bfloat16*)sym(gb_aww);
    __nv_bfloat16* b_vp    = (__nv_bfloat16*)sym(gb_vp);
    __nv_bfloat16* b_op    = (__nv_bfloat16*)sym(gb_op);
    __nv_bfloat16* b_f1w   = (__nv_bfloat16*)sym(gb_f1w);
    __nv_bfloat16* b_f2w   = (__nv_bfloat16*)sym(gb_f2w);

    // ---- converts (weights + input activations) ----
    convert(in_proj_w, b_inproj, 768 * 256);
    convert(out_proj_w, b_outproj, 256 * 256);
    convert(samp_off_w, b_soff, 256 * 256);
    convert(aw_w, b_aww, 128 * 256);
    convert(vp_w, b_vp, 256 * 256);
    convert(op_w, b_op, 256 * 256);
    convert(ffn1_w, b_f1w, 1024 * 256);
    convert(ffn2_w, b_f2w, 256 * 1024);
    convert(tgt, b_tgt, NTOK * CDIM);
    convert(src, b_src, BB * SVAL * CDIM);

    const int n4 = NTOK * CDIM / 4;
    addb_kernel<<<(n4 + 255) / 256, 256>>>(tgt, pos, b_qksum, n4);

    // QKV projections
    launch_gemm<0, 0>(b_qksum, b_inproj, in_proj_b, nullptr, p_qk, NTOK, 512, CDIM);
    launch_gemm<0, 0>(b_tgt, b_inproj + 512 * 256, in_proj_b + 512, nullptr, p_v, NTOK, 256, CDIM);

    attn_kernel<<<NSEQ * 2, 128>>>(p_qk, p_v, b_attn);

    launch_gemm<2, 0>(b_attn, b_outproj, out_proj_b, tgt, p_res1, NTOK, 256, CDIM);
    ln_kernel<<<NTOK, 256>>>(p_res1, ln1_g, ln1_b, p_ln1, pos, b_query, nullptr);

    launch_gemm<0, 0>(b_query, b_soff, samp_off_b, nullptr, p_off, NTOK, 256, CDIM);
    launch_gemm<0, 0>(b_query, b_aww, aw_b, nullptr, p_aw, NTOK, 128, CDIM);
    aw_softmax_kernel<<<NTOK, 128>>>(p_aw);

    launch_gemm<0, 0>(b_src, b_vp, vp_b, nullptr, p_value, BB * SVAL, 256, CDIM);

    deform_kernel<<<NTOK, 256>>>(ref, shapes, lstart, b_accum);

    launch_gemm<2, 0>(b_accum, b_op, op_b, p_ln1, p_res2, NTOK, 256, CDIM);
    ln_kernel<<<NTOK, 256>>>(p_res2, ln2_g, ln2_b, p_ln2, nullptr, nullptr, b_ln2);

    launch_gemm<1, 1>(b_ln2, b_f1w, ffn1_b, nullptr, b_ffn1, NTOK, DFF, CDIM);
    launch_gemm<2, 0>(b_ffn1, b_f2w, ffn2_b, p_ln2, p_res3, NTOK, 256, DFF);
    ln_kernel<<<NTOK, 256>>>(p_res3, ln3_g, ln3_b, (float*)d_out, nullptr, nullptr, nullptr);
}

// round 6
// speedup vs baseline: 2.9313x; 1.0235x over previous
#include <cuda_runtime.h>
#include <cuda_bf16.h>
#include <math.h>
#include <stdint.h>

// ---------------- problem constants ----------------
#define BB    2
#define QQ    300
#define TSEQ  25
#define CDIM  256
#define NHEADS 8
#define HDIM  32
#define NL    4
#define NP    4
#define DFF   1024
#define LQTOT 7500
#define NTOK  15000
#define NSEQ  600
#define SVAL  21760

// ---------------- fp32 scratch ----------------
__device__ __align__(16) float g_qk[NTOK * 512];
__device__ __align__(16) float g_v[NTOK * CDIM];
__device__ __align__(16) float g_res1[NTOK * CDIM];
__device__ __align__(16) float g_ln1[NTOK * CDIM];
__device__ __align__(16) float g_off[NTOK * CDIM];
__device__ __align__(16) float g_aw[NTOK * 128];
__device__ __align__(16) float g_value[(size_t)BB * SVAL * CDIM];
__device__ __align__(16) float g_res2[NTOK * CDIM];
__device__ __align__(16) float g_ln2[NTOK * CDIM];
__device__ __align__(16) float g_res3[NTOK * CDIM];

// ---------------- bf16 scratch ----------------
__device__ __align__(16) __nv_bfloat16 gb_tgt[NTOK * CDIM];
__device__ __align__(16) __nv_bfloat16 gb_qksum[NTOK * CDIM];
__device__ __align__(16) __nv_bfloat16 gb_attn[NTOK * CDIM];
__device__ __align__(16) __nv_bfloat16 gb_query[NTOK * CDIM];
__device__ __align__(16) __nv_bfloat16 gb_src[(size_t)BB * SVAL * CDIM];
__device__ __align__(16) __nv_bfloat16 gb_accum[NTOK * CDIM];
__device__ __align__(16) __nv_bfloat16 gb_ln2[NTOK * CDIM];
__device__ __align__(16) __nv_bfloat16 gb_ffn1[NTOK * DFF];
// weights
__device__ __align__(16) __nv_bfloat16 gb_inproj[768 * 256];
__device__ __align__(16) __nv_bfloat16 gb_outproj[256 * 256];
__device__ __align__(16) __nv_bfloat16 gb_soff[256 * 256];
__device__ __align__(16) __nv_bfloat16 gb_aww[128 * 256];
__device__ __align__(16) __nv_bfloat16 gb_vp[256 * 256];
__device__ __align__(16) __nv_bfloat16 gb_op[256 * 256];
__device__ __align__(16) __nv_bfloat16 gb_f1w[1024 * 256];
__device__ __align__(16) __nv_bfloat16 gb_f2w[256 * 1024];

// ================= helpers =================
__device__ __forceinline__ uint32_t smem_to_u32(const void* p) {
    uint32_t a;
    asm("{ .reg .u64 t; cvta.to.shared.u64 t, %1; cvt.u32.u64 %0, t; }" : "=r"(a) : "l"(p));
    return a;
}
__device__ __forceinline__ void cpasync16(uint32_t dst, const void* src) {
    asm volatile("cp.async.ca.shared.global [%0], [%1], 16;" :: "r"(dst), "l"(src) : "memory");
}
#define CP_COMMIT() asm volatile("cp.async.commit_group;" ::: "memory")

__device__ __forceinline__ uint32_t lds_u32(uint32_t a) {
    uint32_t r;
    asm volatile("ld.shared.b32 %0, [%1];" : "=r"(r) : "r"(a));
    return r;
}
__device__ __forceinline__ void mma_bf16(float* d, const uint32_t* a, const uint32_t* b) {
    asm volatile(
        "mma.sync.aligned.m16n8k16.row.col.f32.bf16.bf16.f32 "
        "{%0,%1,%2,%3}, {%4,%5,%6,%7}, {%8,%9}, {%0,%1,%2,%3};"
        : "+f"(d[0]), "+f"(d[1]), "+f"(d[2]), "+f"(d[3])
        : "r"(a[0]), "r"(a[1]), "r"(a[2]), "r"(a[3]), "r"(b[0]), "r"(b[1]));
}
__device__ __forceinline__ uint32_t pack_bf16(float x, float y) {
    uint32_t r;
    asm("cvt.rn.bf16x2.f32 %0, %1, %2;" : "=r"(r) : "f"(y), "f"(x));
    return r;
}

// ================= bf16 mma.sync GEMM, 3-stage pipeline =================
// C[M,N] = A[M,K] @ B[N,K]^T + bias;  EPI: 0 none, 1 relu, 2 +res
// OUTBF: 1 -> bf16 out, 0 -> fp32 out
// grid = (N/128, ceil(M/128)), 256 threads, 96 KB dyn smem.
// chunk: K=64 bf16 (128B/row), 128 rows per tile, 16B-granule XOR swizzle.
#define GEMM_SMEM (3 * 32768)

__device__ __forceinline__ void fill_chunk_b(uint32_t sbuf,
                                             const __nv_bfloat16* __restrict__ A,
                                             const __nv_bfloat16* __restrict__ B,
                                             int bm, int bn, int M, int K, int k0, int tid) {
    const int r = tid & 127;
    const int which = tid >> 7;
    int ar = bm + r; if (ar >= M) ar = M - 1;
    const __nv_bfloat16* gp = which ? (B + (size_t)(bn + r) * K + k0)
                                    : (A + (size_t)ar * K + k0);
    const uint32_t d = sbuf + (uint32_t)(which * 16384) + (uint32_t)(r * 128);
    const int x = r & 7;
#pragma unroll
    for (int j = 0; j < 8; j++)
        cpasync16(d + (uint32_t)((j ^ x) << 4), gp + j * 8);
}

template <int EPI, int OUTBF>
__global__ __launch_bounds__(256, 2) void gemm_mma(
        const __nv_bfloat16* __restrict__ A, const __nv_bfloat16* __restrict__ B,
        const float* __restrict__ bias, const float* __restrict__ res,
        void* __restrict__ Cout, int M, int N, int K) {
    extern __shared__ char smem[];
    const uint32_t smem_u = smem_to_u32(smem);
    const int tid = threadIdx.x;
    const int wid = tid >> 5;
    const int lane = tid & 31;
    const int wm = wid & 3;          // 4 warps in M: 32 rows each
    const int wn = wid >> 2;         // 2 warps in N: 64 cols each
    const int q = lane >> 2;         // 0..7
    const int t4 = (lane & 3) << 2;  // byte offset within granule
    const int bm = blockIdx.y * 128;
    const int bn = blockIdx.x * 128;

    float acc[2][8][4];
#pragma unroll
    for (int mt = 0; mt < 2; mt++)
#pragma unroll
        for (int nt = 0; nt < 8; nt++)
#pragma unroll
            for (int e = 0; e < 4; e++) acc[mt][nt][e] = 0.f;

    const int nc = K >> 6;  // chunks of 64 (always >= 4 here)

    fill_chunk_b(smem_u, A, B, bm, bn, M, K, 0, tid);
    CP_COMMIT();
    fill_chunk_b(smem_u + 32768, A, B, bm, bn, M, K, 64, tid);
    CP_COMMIT();

    const uint32_t aRow = (uint32_t)((wm * 32 + q) * 128);
    const uint32_t bRow = (uint32_t)((wn * 64 + q) * 128) + 16384;

    int stage = 0;  // stage of chunk i
    for (int i = 0; i < nc; i++) {
        // issue fill for chunk i+2 into stage (i+2)%3
        if (i + 2 < nc) {
            int fs = stage + 2; if (fs >= 3) fs -= 3;
            fill_chunk_b(smem_u + (uint32_t)(fs * 32768), A, B, bm, bn, M, K, (i + 2) * 64, tid);
        }
        CP_COMMIT();
        asm volatile("cp.async.wait_group 2;" ::: "memory");
        __syncthreads();

        const uint32_t buf = smem_u + (uint32_t)(stage * 32768);

#pragma unroll
        for (int ks = 0; ks < 4; ks++) {
            const uint32_t g0 = (uint32_t)((((ks << 1)    ) ^ q) << 4);
            const uint32_t g1 = (uint32_t)((((ks << 1) | 1) ^ q) << 4);
            uint32_t Af[2][4];
#pragma unroll
            for (int mt = 0; mt < 2; mt++) {
                const uint32_t ro = buf + aRow + (uint32_t)(mt * 2048);
                Af[mt][0] = lds_u32(ro + g0 + t4);
                Af[mt][1] = lds_u32(ro + 1024 + g0 + t4);
                Af[mt][2] = lds_u32(ro + g1 + t4);
                Af[mt][3] = lds_u32(ro + 1024 + g1 + t4);
            }
            uint32_t Bf[8][2];
#pragma unroll
            for (int nt = 0; nt < 8; nt++) {
                const uint32_t ro = buf + bRow + (uint32_t)(nt * 1024);
                Bf[nt][0] = lds_u32(ro + g0 + t4);
                Bf[nt][1] = lds_u32(ro + g1 + t4);
            }
#pragma unroll
            for (int mt = 0; mt < 2; mt++)
#pragma unroll
                for (int nt = 0; nt < 8; nt++)
                    mma_bf16(acc[mt][nt], Af[mt], Bf[nt]);
        }
        __syncthreads();
        stage++; if (stage == 3) stage = 0;
    }

    // ---- epilogue ----
    const int ccol = bn + wn * 64;
    const float* biasp = bias + ccol;
    const int t2 = (lane & 3) * 2;
#pragma unroll
    for (int mt = 0; mt < 2; mt++) {
#pragma unroll
        for (int rs = 0; rs < 2; rs++) {
            const int r = bm + wm * 32 + mt * 16 + q + rs * 8;
            if (r >= M) continue;
            const float* rp = (EPI == 2) ? res + (size_t)r * N + ccol : nullptr;
#pragma unroll
            for (int nt = 0; nt < 8; nt++) {
                const int c = nt * 8 + t2;
                float vx = acc[mt][nt][rs * 2 + 0] + biasp[c];
                float vy = acc[mt][nt][rs * 2 + 1] + biasp[c + 1];
                if (EPI == 1) { vx = fmaxf(vx, 0.f); vy = fmaxf(vy, 0.f); }
                if (EPI == 2) { vx += rp[c]; vy += rp[c + 1]; }
                if (OUTBF) {
                    uint32_t* cp = (uint32_t*)((__nv_bfloat16*)Cout + (size_t)r * N + ccol + c);
                    *cp = pack_bf16(vx, vy);
                } else {
                    float* cp = (float*)Cout + (size_t)r * N + ccol + c;
                    *(float2*)cp = make_float2(vx, vy);
                }
            }
        }
    }
}

// ---------------- fused weight convert (8 segments, one launch) ------------
struct WConvArgs {
    const float4* in[8];
    uint2* out[8];
    int off4[9];
};
__global__ void wconv_kernel(WConvArgs a) {
    int i = blockIdx.x * blockDim.x + threadIdx.x;
    if (i >= a.off4[8]) return;
    int s = 0;
#pragma unroll
    for (int k = 1; k < 8; k++) s += (i >= a.off4[k]);
    int j = i - a.off4[s];
    float4 v = a.in[s][j];
    uint2 o;
    o.x = pack_bf16(v.x, v.y);
    o.y = pack_bf16(v.z, v.w);
    a.out[s][j] = o;
}

// ---------------- fp32 -> bf16 convert ----------------
__global__ void f2b_kernel(const float* __restrict__ in, __nv_bfloat16* __restrict__ out, int n4) {
    int i = blockIdx.x * blockDim.x + threadIdx.x;
    if (i < n4) {
        float4 v = ((const float4*)in)[i];
        uint2 o;
        o.x = pack_bf16(v.x, v.y);
        o.y = pack_bf16(v.z, v.w);
        ((uint2*)out)[i] = o;
    }
}

// ---------------- add (tgt+pos) -> bf16 ----------------
__global__ void addb_kernel(const float* __restrict__ a, const float* __restrict__ b,
                            __nv_bfloat16* __restrict__ out, int n4) {
    int i = blockIdx.x * blockDim.x + threadIdx.x;
    if (i < n4) {
        float4 x = ((const float4*)a)[i];
        float4 y = ((const float4*)b)[i];
        uint2 o;
        o.x = pack_bf16(x.x + y.x, x.y + y.y);
        o.y = pack_bf16(x.z + y.z, x.w + y.w);
        ((uint2*)out)[i] = o;
    }
}

// ---------------- self-attention (lane = query), bf16 out ----------
__global__ __launch_bounds__(128) void attn_kernel(
        const float* __restrict__ qk, const float* __restrict__ v,
        __nv_bfloat16* __restrict__ out) {
    const int seq  = blockIdx.x >> 1;
    const int w    = threadIdx.x >> 5;
    const int h    = ((blockIdx.x & 1) << 2) + w;
    const int lane = threadIdx.x & 31;

    __shared__ float Ks[4][25][32];
    __shared__ float Vs[4][25][32];
    __shared__ float Os[4][25][36];

    const size_t tokbase = (size_t)seq * TSEQ;
    for (int i = lane; i < TSEQ * 32; i += 32) {
        int r = i >> 5;
        Ks[w][r][lane] = qk[(tokbase + r) * 512 + 256 + h * 32 + lane];
        Vs[w][r][lane] = v[(tokbase + r) * 256 + h * 32 + lane];
    }
    __syncwarp();

    if (lane < TSEQ) {
        float4 qv[8];
        const float4* qp = (const float4*)(qk + (tokbase + lane) * 512 + h * 32);
#pragma unroll
        for (int i = 0; i < 8; i++) qv[i] = qp[i];

        const float scale = 0.1767766952966369f;
        float p[25];
        float m = -1e30f;
#pragma unroll
        for (int j = 0; j < TSEQ; j++) {
            const float4* kp = (const float4*)Ks[w][j];
            float a = 0.f;
#pragma unroll
            for (int i = 0; i < 8; i++) {
                float4 k4 = kp[i];
                a = fmaf(qv[i].x, k4.x, a); a = fmaf(qv[i].y, k4.y, a);
                a = fmaf(qv[i].z, k4.z, a); a = fmaf(qv[i].w, k4.w, a);
            }
            p[j] = a * scale;
            m = fmaxf(m, p[j]);
        }
        float sum = 0.f;
#pragma unroll
        for (int j = 0; j < TSEQ; j++) { p[j] = __expf(p[j] - m); sum += p[j]; }
        const float inv = 1.f / sum;
#pragma unroll
        for (int d4 = 0; d4 < 8; d4++) {
            float4 o = make_float4(0.f, 0.f, 0.f, 0.f);
#pragma unroll
            for (int j = 0; j < TSEQ; j++) {
                float4 v4 = ((const float4*)Vs[w][j])[d4];
                o.x = fmaf(p[j], v4.x, o.x); o.y = fmaf(p[j], v4.y, o.y);
                o.z = fmaf(p[j], v4.z, o.z); o.w = fmaf(p[j], v4.w, o.w);
            }
            float* orow = &Os[w][lane][d4 * 4];
            orow[0] = o.x * inv; orow[1] = o.y * inv;
            orow[2] = o.z * inv; orow[3] = o.w * inv;
        }
    }
    __syncwarp();
    for (int i = lane; i < TSEQ * 32; i += 32) {
        int r = i >> 5;
        out[(tokbase + r) * 256 + h * 32 + lane] = __float2bfloat16(Os[w][r][lane]);
    }
}

// ---------------- layernorm ----------------
__global__ void ln_kernel(const float* __restrict__ x, const float* __restrict__ g,
                          const float* __restrict__ b, float* __restrict__ y,
                          const float* __restrict__ pos, __nv_bfloat16* __restrict__ y2b,
                          __nv_bfloat16* __restrict__ yb) {
    const int row = blockIdx.x;
    const int c = threadIdx.x;
    const size_t idx = (size_t)row * 256 + c;
    float v = x[idx];

    __shared__ float red[8];
    float s = v;
#pragma unroll
    for (int o = 16; o; o >>= 1) s += __shfl_xor_sync(~0u, s, o);
    if ((c & 31) == 0) red[c >> 5] = s;
    __syncthreads();
    float tot = red[0] + red[1] + red[2] + red[3] + red[4] + red[5] + red[6] + red[7];
    float mean = tot * (1.f / 256.f);
    float d = v - mean;
    float s2 = d * d;
#pragma unroll
    for (int o = 16; o; o >>= 1) s2 += __shfl_xor_sync(~0u, s2, o);
    __syncthreads();
    if ((c & 31) == 0) red[c >> 5] = s2;
    __syncthreads();
    float var = (red[0] + red[1] + red[2] + red[3] + red[4] + red[5] + red[6] + red[7]) * (1.f / 256.f);
    float out = d * rsqrtf(var + 1e-5f) * g[c] + b[c];
    y[idx] = out;
    if (y2b) y2b[idx] = __float2bfloat16(out + pos[idx]);
    if (yb) yb[idx] = __float2bfloat16(out);
}

// ---------------- aw softmax ----------------
__global__ void aw_softmax_kernel(float* __restrict__ aw) {
    const int token = blockIdx.x;
    const int t = threadIdx.x;
    const size_t idx = (size_t)token * 128 + t;
    float v = aw[idx];
    float m = v;
#pragma unroll
    for (int o = 8; o; o >>= 1) m = fmaxf(m, __shfl_xor_sync(~0u, m, o, 16));
    float e = __expf(v - m);
    float s = e;
#pragma unroll
    for (int o = 8; o; o >>= 1) s += __shfl_xor_sync(~0u, s, o, 16);
    aw[idx] = e / s;
}

// ---------------- deformable sampling, bf16 out ----------------
__global__ void deform_kernel(const float* __restrict__ ref,
                              const int* __restrict__ shapes,
                              const int* __restrict__ lstart,
                              __nv_bfloat16* __restrict__ out) {
    const int token = blockIdx.x;
    const int h = threadIdx.x >> 5;
    const int lane = threadIdx.x & 31;
    const int b = token / LQTOT;
    const int lq = token - b * LQTOT;

    const float* offp = g_off + (size_t)token * 256 + h * 32;
    const float* awp  = g_aw + (size_t)token * 128 + h * 16;
    const float* refp = ref + ((size_t)(b * LQTOT + lq) * NL) * 2;
    const size_t vbase = ((size_t)b * SVAL) * 256;

    float acc = 0.f;
#pragma unroll
    for (int l = 0; l < NL; l++) {
        const int Hl = shapes[l * 2];
        const int Wl = shapes[l * 2 + 1];
        const int st = lstart[l];
        const float rx = refp[l * 2];
        const float ry = refp[l * 2 + 1];
        const float fW = (float)Wl, fH = (float)Hl;
#pragma unroll
        for (int p = 0; p < 4; p++) {
            float ox = offp[l * 8 + p * 2];
            float oy = offp[l * 8 + p * 2 + 1];
            float aww = awp[l * 4 + p];
            float x = (rx + ox / fW) * fW - 0.5f;
            float y = (ry + oy / fH) * fH - 0.5f;
            float fx0 = floorf(x), fy0 = floorf(y);
            float wx = x - fx0, wy = y - fy0;
            int x0 = (int)fx0, y0 = (int)fy0;
            float tw[4] = {(1.f - wx) * (1.f - wy), wx * (1.f - wy),
                           (1.f - wx) * wy, wx * wy};
            int xs[4] = {x0, x0 + 1, x0, x0 + 1};
            int ys[4] = {y0, y0, y0 + 1, y0 + 1};
#pragma unroll
            for (int tgt = 0; tgt < 4; tgt++) {
                int xi = xs[tgt], yi = ys[tgt];
                if (xi >= 0 && xi < Wl && yi >= 0 && yi < Hl) {
                    size_t vi = vbase + ((size_t)(st + yi * Wl + xi)) * 256 + h * 32 + lane;
                    acc = fmaf(g_value[vi], tw[tgt] * aww, acc);
                }
            }
        }
    }
    out[(size_t)token * 256 + h * 32 + lane] = __float2bfloat16(acc);
}

// ---------------- launch ----------------
static void* sym(const void* s) {
    void* p = nullptr;
    cudaGetSymbolAddress(&p, s);
    return p;
}

template <int EPI, int OUTBF>
static void launch_gemm(const __nv_bfloat16* A, const __nv_bfloat16* B, const float* bias,
                        const float* res, void* C, int M, int N, int K) {
    static bool done = false;
    if (!done) {
        cudaFuncSetAttribute(gemm_mma<EPI, OUTBF>, cudaFuncAttributeMaxDynamicSharedMemorySize, GEMM_SMEM);
        done = true;
    }
    dim3 grid(N / 128, (M + 127) / 128);
    gemm_mma<EPI, OUTBF><<<grid, 256, GEMM_SMEM>>>(A, B, bias, res, C, M, N, K);
}

extern "C" void kernel_launch(void* const* d_in, const int* in_sizes, int n_in,
                              void* d_out, int out_size) {
    const float* tgt  = (const float*)d_in[0];
    const float* pos  = (const float*)d_in[1];
    const float* ref  = (const float*)d_in[2];
    const float* src  = (const float*)d_in[3];
    const int* shapes = (const int*)d_in[4];
    const int* lstart = (const int*)d_in[5];
    const float* in_proj_w  = (const float*)d_in[6];
    const float* in_proj_b  = (const float*)d_in[7];
    const float* out_proj_w = (const float*)d_in[8];
    const float* out_proj_b = (const float*)d_in[9];
    const float* ln1_g = (const float*)d_in[10];
    const float* ln1_b = (const float*)d_in[11];
    const float* samp_off_w = (const float*)d_in[12];
    const float* samp_off_b = (const float*)d_in[13];
    const float* aw_w = (const float*)d_in[14];
    const float* aw_b = (const float*)d_in[15];
    const float* vp_w = (const float*)d_in[16];
    const float* vp_b = (const float*)d_in[17];
    const float* op_w = (const float*)d_in[18];
    const float* op_b = (const float*)d_in[19];
    const float* ln2_g = (const float*)d_in[20];
    const float* ln2_b = (const float*)d_in[21];
    const float* ffn1_w = (const float*)d_in[22];
    const float* ffn1_b = (const float*)d_in[23];
    const float* ffn2_w = (const float*)d_in[24];
    const float* ffn2_b = (const float*)d_in[25];
    const float* ln3_g = (const float*)d_in[26];
    const float* ln3_b = (const float*)d_in[27];

    float* p_qk    = (float*)sym(g_qk);
    float* p_v     = (float*)sym(g_v);
    float* p_res1  = (float*)sym(g_res1);
    float* p_ln1   = (float*)sym(g_ln1);
    float* p_off   = (float*)sym(g_off);
    float* p_aw    = (float*)sym(g_aw);
    float* p_value = (float*)sym(g_value);
    float* p_res2  = (float*)sym(g_res2);
    float* p_ln2   = (float*)sym(g_ln2);
    float* p_res3  = (float*)sym(g_res3);

    __nv_bfloat16* b_tgt   = (__nv_bfloat16*)sym(gb_tgt);
    __nv_bfloat16* b_qksum = (__nv_bfloat16*)sym(gb_qksum);
    __nv_bfloat16* b_attn  = (__nv_bfloat16*)sym(gb_attn);
    __nv_bfloat16* b_query = (__nv_bfloat16*)sym(gb_query);
    __nv_bfloat16* b_src   = (__nv_bfloat16*)sym(gb_src);
    __nv_bfloat16* b_accum = (__nv_bfloat16*)sym(gb_accum);
    __nv_bfloat16* b_ln2   = (__nv_bfloat16*)sym(gb_ln2);
    __nv_bfloat16* b_ffn1  = (__nv_bfloat16*)sym(gb_ffn1);
    __nv_bfloat16* b_inproj = (__nv_bfloat16*)sym(gb_inproj);
    __nv_bfloat16* b_outproj = (__nv_bfloat16*)sym(gb_outproj);
    __nv_bfloat16* b_soff  = (__nv_bfloat16*)sym(gb_soff);
    __nv_bfloat16* b_aww   = (__nv_bfloat16*)sym(gb_aww);
    __nv_bfloat16* b_vp    = (__nv_bfloat16*)sym(gb_vp);
    __nv_bfloat16* b_op    = (__nv_bfloat16*)sym(gb_op);
    __nv_bfloat16* b_f1w   = (__nv_bfloat16*)sym(gb_f1w);
    __nv_bfloat16* b_f2w   = (__nv_bfloat16*)sym(gb_f2w);

    // ---- launch 1: all weight converts fused ----
    {
        WConvArgs a;
        const float* ins[8] = {in_proj_w, out_proj_w, samp_off_w, aw_w, vp_w, op_w, ffn1_w, ffn2_w};
        __nv_bfloat16* outs[8] = {b_inproj, b_outproj, b_soff, b_aww, b_vp, b_op, b_f1w, b_f2w};
        int ns[8] = {768 * 256, 256 * 256, 256 * 256, 128 * 256, 256 * 256, 256 * 256, 1024 * 256, 256 * 1024};
        int acc4 = 0;
        for (int i = 0; i < 8; i++) {
            a.in[i] = (const float4*)ins[i];
            a.out[i] = (uint2*)outs[i];
            a.off4[i] = acc4;
            acc4 += ns[i] / 4;
        }
        a.off4[8] = acc4;
        wconv_kernel<<<(acc4 + 255) / 256, 256>>>(a);
    }

    const int n4 = NTOK * CDIM / 4;
    // launch 2
    addb_kernel<<<(n4 + 255) / 256, 256>>>(tgt, pos, b_qksum, n4);
    // launch 3
    f2b_kernel<<<(n4 + 255) / 256, 256>>>(tgt, b_tgt, n4);
    // launches 4, 5 (src split in half so launch 6 is the qk GEMM for ncu)
    const int s4 = BB * SVAL * CDIM / 4;
    const int s4h = s4 / 2;
    f2b_kernel<<<(s4h + 255) / 256, 256>>>(src, b_src, s4h);
    f2b_kernel<<<(s4 - s4h + 255) / 256, 256>>>(src + (size_t)s4h * 4,
                                                b_src + (size_t)s4h * 4, s4 - s4h);

    // launch 6: qk GEMM (profiled by ncu -s 5 -c 1)
    launch_gemm<0, 0>(b_qksum, b_inproj, in_proj_b, nullptr, p_qk, NTOK, 512, CDIM);
    launch_gemm<0, 0>(b_tgt, b_inproj + 512 * 256, in_proj_b + 512, nullptr, p_v, NTOK, 256, CDIM);

    attn_kernel<<<NSEQ * 2, 128>>>(p_qk, p_v, b_attn);

    launch_gemm<2, 0>(b_attn, b_outproj, out_proj_b, tgt, p_res1, NTOK, 256, CDIM);
    ln_kernel<<<NTOK, 256>>>(p_res1, ln1_g, ln1_b, p_ln1, pos, b_query, nullptr);

    launch_gemm<0, 0>(b_query, b_soff, samp_off_b, nullptr, p_off, NTOK, 256, CDIM);
    launch_gemm<0, 0>(b_query, b_aww, aw_b, nullptr, p_aw, NTOK, 128, CDIM);
    aw_softmax_kernel<<<NTOK, 128>>>(p_aw);

    launch_gemm<0, 0>(b_src, b_vp, vp_b, nullptr, p_value, BB * SVAL, 256, CDIM);

    deform_kernel<<<NTOK, 256>>>(ref, shapes, lstart, b_accum);

    launch_gemm<2, 0>(b_accum, b_op, op_b, p_ln1, p_res2, NTOK, 256, CDIM);
    ln_kernel<<<NTOK, 256>>>(p_res2, ln2_g, ln2_b, p_ln2, nullptr, nullptr, b_ln2);

    launch_gemm<1, 1>(b_ln2, b_f1w, ffn1_b, nullptr, b_ffn1, NTOK, DFF, CDIM);
    launch_gemm<2, 0>(b_ffn1, b_f2w, ffn2_b, p_ln2, p_res3, NTOK, 256, DFF);
    ln_kernel<<<NTOK, 256>>>(p_res3, ln3_g, ln3_b, (float*)d_out, nullptr, nullptr, nullptr);
}

// round 7
// speedup vs baseline: 3.0199x; 1.0302x over previous
#include <cuda_runtime.h>
#include <cuda_bf16.h>
#include <math.h>
#include <stdint.h>

// ---------------- problem constants ----------------
#define BB    2
#define QQ    300
#define TSEQ  25
#define CDIM  256
#define NHEADS 8
#define HDIM  32
#define NL    4
#define NP    4
#define DFF   1024
#define LQTOT 7500
#define NTOK  15000
#define NSEQ  600
#define SVAL  21760

// ---------------- fp32 scratch ----------------
__device__ __align__(16) float g_qk[NTOK * 512];
__device__ __align__(16) float g_v[NTOK * CDIM];
__device__ __align__(16) float g_res1[NTOK * CDIM];
__device__ __align__(16) float g_ln1[NTOK * CDIM];
__device__ __align__(16) float g_offaw[NTOK * 384];
__device__ __align__(16) float g_value[(size_t)BB * SVAL * CDIM];
__device__ __align__(16) float g_res2[NTOK * CDIM];
__device__ __align__(16) float g_ln2[NTOK * CDIM];
__device__ __align__(16) float g_res3[NTOK * CDIM];
__device__ __align__(16) float g_bias384[384];

// ---------------- bf16 scratch ----------------
__device__ __align__(16) __nv_bfloat16 gb_tgt[NTOK * CDIM];
__device__ __align__(16) __nv_bfloat16 gb_qksum[NTOK * CDIM];
__device__ __align__(16) __nv_bfloat16 gb_attn[NTOK * CDIM];
__device__ __align__(16) __nv_bfloat16 gb_query[NTOK * CDIM];
__device__ __align__(16) __nv_bfloat16 gb_src[(size_t)BB * SVAL * CDIM];
__device__ __align__(16) __nv_bfloat16 gb_accum[NTOK * CDIM];
__device__ __align__(16) __nv_bfloat16 gb_ln2[NTOK * CDIM];
__device__ __align__(16) __nv_bfloat16 gb_ffn1[NTOK * DFF];
// weights
__device__ __align__(16) __nv_bfloat16 gb_inproj[768 * 256];
__device__ __align__(16) __nv_bfloat16 gb_outproj[256 * 256];
__device__ __align__(16) __nv_bfloat16 gb_soffaw[384 * 256];
__device__ __align__(16) __nv_bfloat16 gb_vp[256 * 256];
__device__ __align__(16) __nv_bfloat16 gb_op[256 * 256];
__device__ __align__(16) __nv_bfloat16 gb_f1w[1024 * 256];
__device__ __align__(16) __nv_bfloat16 gb_f2w[256 * 1024];

// ================= helpers =================
__device__ __forceinline__ uint32_t smem_to_u32(const void* p) {
    uint32_t a;
    asm("{ .reg .u64 t; cvta.to.shared.u64 t, %1; cvt.u32.u64 %0, t; }" : "=r"(a) : "l"(p));
    return a;
}
__device__ __forceinline__ void cpasync16(uint32_t dst, const void* src) {
    asm volatile("cp.async.ca.shared.global [%0], [%1], 16;" :: "r"(dst), "l"(src) : "memory");
}
#define CP_COMMIT() asm volatile("cp.async.commit_group;" ::: "memory")

__device__ __forceinline__ uint32_t lds_u32(uint32_t a) {
    uint32_t r;
    asm volatile("ld.shared.b32 %0, [%1];" : "=r"(r) : "r"(a));
    return r;
}
__device__ __forceinline__ void mma_bf16(float* d, const uint32_t* a, const uint32_t* b) {
    asm volatile(
        "mma.sync.aligned.m16n8k16.row.col.f32.bf16.bf16.f32 "
        "{%0,%1,%2,%3}, {%4,%5,%6,%7}, {%8,%9}, {%0,%1,%2,%3};"
        : "+f"(d[0]), "+f"(d[1]), "+f"(d[2]), "+f"(d[3])
        : "r"(a[0]), "r"(a[1]), "r"(a[2]), "r"(a[3]), "r"(b[0]), "r"(b[1]));
}
__device__ __forceinline__ uint32_t pack_bf16(float x, float y) {
    uint32_t r;
    asm("cvt.rn.bf16x2.f32 %0, %1, %2;" : "=r"(r) : "f"(y), "f"(x));
    return r;
}

// ================= bf16 mma.sync GEMM, 3-stage pipeline, compile-time K ======
#define GEMM_SMEM (3 * 32768)

template <int K>
__device__ __forceinline__ void fill_chunk_b(uint32_t sbuf,
                                             const __nv_bfloat16* __restrict__ A,
                                             const __nv_bfloat16* __restrict__ B,
                                             int bm, int bn, int M, int k0, int tid) {
    const int r = tid & 127;
    const int which = tid >> 7;
    int ar = bm + r; if (ar >= M) ar = M - 1;
    const __nv_bfloat16* gp = which ? (B + (size_t)(bn + r) * K + k0)
                                    : (A + (size_t)ar * K + k0);
    const uint32_t d = sbuf + (uint32_t)(which * 16384) + (uint32_t)(r * 128);
    const int x = r & 7;
#pragma unroll
    for (int j = 0; j < 8; j++)
        cpasync16(d + (uint32_t)((j ^ x) << 4), gp + j * 8);
}

template <int EPI, int OUTBF, int NC>
__global__ __launch_bounds__(256, 2) void gemm_mma(
        const __nv_bfloat16* __restrict__ A, const __nv_bfloat16* __restrict__ B,
        const float* __restrict__ bias, const float* __restrict__ res,
        void* __restrict__ Cout, int M, int N) {
    constexpr int K = NC * 64;
    extern __shared__ char smem[];
    const uint32_t smem_u = smem_to_u32(smem);
    const int tid = threadIdx.x;
    const int wid = tid >> 5;
    const int lane = tid & 31;
    const int wm = wid & 3;
    const int wn = wid >> 2;
    const int q = lane >> 2;
    const int t4 = (lane & 3) << 2;
    const int bm = blockIdx.y * 128;
    const int bn = blockIdx.x * 128;

    float acc[2][8][4];
#pragma unroll
    for (int mt = 0; mt < 2; mt++)
#pragma unroll
        for (int nt = 0; nt < 8; nt++)
#pragma unroll
            for (int e = 0; e < 4; e++) acc[mt][nt][e] = 0.f;

    fill_chunk_b<K>(smem_u, A, B, bm, bn, M, 0, tid);
    CP_COMMIT();
    fill_chunk_b<K>(smem_u + 32768, A, B, bm, bn, M, 64, tid);
    CP_COMMIT();

    const uint32_t aRow = (uint32_t)((wm * 32 + q) * 128);
    const uint32_t bRow = (uint32_t)((wn * 64 + q) * 128) + 16384;

#pragma unroll
    for (int i = 0; i < NC; i++) {
        const int stage = i % 3;
        if (i + 2 < NC) {
            const int fs = (i + 2) % 3;
            fill_chunk_b<K>(smem_u + (uint32_t)(fs * 32768), A, B, bm, bn, M, (i + 2) * 64, tid);
        }
        CP_COMMIT();
        asm volatile("cp.async.wait_group 2;" ::: "memory");
        __syncthreads();

        const uint32_t buf = smem_u + (uint32_t)(stage * 32768);

#pragma unroll
        for (int ks = 0; ks < 4; ks++) {
            const uint32_t g0 = (uint32_t)((((ks << 1)    ) ^ q) << 4);
            const uint32_t g1 = (uint32_t)((((ks << 1) | 1) ^ q) << 4);
            uint32_t Af[2][4];
#pragma unroll
            for (int mt = 0; mt < 2; mt++) {
                const uint32_t ro = buf + aRow + (uint32_t)(mt * 2048);
                Af[mt][0] = lds_u32(ro + g0 + t4);
                Af[mt][1] = lds_u32(ro + 1024 + g0 + t4);
                Af[mt][2] = lds_u32(ro + g1 + t4);
                Af[mt][3] = lds_u32(ro + 1024 + g1 + t4);
            }
            uint32_t Bf[8][2];
#pragma unroll
            for (int nt = 0; nt < 8; nt++) {
                const uint32_t ro = buf + bRow + (uint32_t)(nt * 1024);
                Bf[nt][0] = lds_u32(ro + g0 + t4);
                Bf[nt][1] = lds_u32(ro + g1 + t4);
            }
#pragma unroll
            for (int mt = 0; mt < 2; mt++)
#pragma unroll
                for (int nt = 0; nt < 8; nt++)
                    mma_bf16(acc[mt][nt], Af[mt], Bf[nt]);
        }
        __syncthreads();
    }

    // ---- epilogue ----
    const int ccol = bn + wn * 64;
    const float* biasp = bias + ccol;
    const int t2 = (lane & 3) * 2;
#pragma unroll
    for (int mt = 0; mt < 2; mt++) {
#pragma unroll
        for (int rs = 0; rs < 2; rs++) {
            const int r = bm + wm * 32 + mt * 16 + q + rs * 8;
            if (r >= M) continue;
            const float* rp = (EPI == 2) ? res + (size_t)r * N + ccol : nullptr;
#pragma unroll
            for (int nt = 0; nt < 8; nt++) {
                const int c = nt * 8 + t2;
                float vx = acc[mt][nt][rs * 2 + 0] + biasp[c];
                float vy = acc[mt][nt][rs * 2 + 1] + biasp[c + 1];
                if (EPI == 1) { vx = fmaxf(vx, 0.f); vy = fmaxf(vy, 0.f); }
                if (EPI == 2) { vx += rp[c]; vy += rp[c + 1]; }
                if (OUTBF) {
                    uint32_t* cp = (uint32_t*)((__nv_bfloat16*)Cout + (size_t)r * N + ccol + c);
                    *cp = pack_bf16(vx, vy);
                } else {
                    float* cp = (float*)Cout + (size_t)r * N + ccol + c;
                    *(float2*)cp = make_float2(vx, vy);
                }
            }
        }
    }
}

// ---------------- fused weight convert + bias concat ------------
struct WConvArgs {
    const float4* in[8];
    uint2* out[8];
    int off4[9];
    const float4* sob4;   // samp_off_b (64 float4)
    const float4* awb4;   // aw_b (32 float4)
    float4* bias384;
};
__global__ void wconv_kernel(WConvArgs a) {
    int i = blockIdx.x * blockDim.x + threadIdx.x;
    if (i < 96) {
        a.bias384[i] = (i < 64) ? a.sob4[i] : a.awb4[i - 64];
    }
    if (i >= a.off4[8]) return;
    int s = 0;
#pragma unroll
    for (int k = 1; k < 8; k++) s += (i >= a.off4[k]);
    int j = i - a.off4[s];
    float4 v = a.in[s][j];
    uint2 o;
    o.x = pack_bf16(v.x, v.y);
    o.y = pack_bf16(v.z, v.w);
    a.out[s][j] = o;
}

// ---------------- fp32 -> bf16 convert ----------------
__global__ void f2b_kernel(const float* __restrict__ in, __nv_bfloat16* __restrict__ out, int n4) {
    int i = blockIdx.x * blockDim.x + threadIdx.x;
    if (i < n4) {
        float4 v = ((const float4*)in)[i];
        uint2 o;
        o.x = pack_bf16(v.x, v.y);
        o.y = pack_bf16(v.z, v.w);
        ((uint2*)out)[i] = o;
    }
}

// ---------------- add (tgt+pos) -> bf16 ----------------
__global__ void addb_kernel(const float* __restrict__ a, const float* __restrict__ b,
                            __nv_bfloat16* __restrict__ out, int n4) {
    int i = blockIdx.x * blockDim.x + threadIdx.x;
    if (i < n4) {
        float4 x = ((const float4*)a)[i];
        float4 y = ((const float4*)b)[i];
        uint2 o;
        o.x = pack_bf16(x.x + y.x, x.y + y.y);
        o.y = pack_bf16(x.z + y.z, x.w + y.w);
        ((uint2*)out)[i] = o;
    }
}

// ---------------- self-attention (lane = query), bf16 out ----------
__global__ __launch_bounds__(128) void attn_kernel(
        const float* __restrict__ qk, const float* __restrict__ v,
        __nv_bfloat16* __restrict__ out) {
    const int seq  = blockIdx.x >> 1;
    const int w    = threadIdx.x >> 5;
    const int h    = ((blockIdx.x & 1) << 2) + w;
    const int lane = threadIdx.x & 31;

    __shared__ float Ks[4][25][32];
    __shared__ float Vs[4][25][32];
    __shared__ float Os[4][25][36];

    const size_t tokbase = (size_t)seq * TSEQ;
    for (int i = lane; i < TSEQ * 32; i += 32) {
        int r = i >> 5;
        Ks[w][r][lane] = qk[(tokbase + r) * 512 + 256 + h * 32 + lane];
        Vs[w][r][lane] = v[(tokbase + r) * 256 + h * 32 + lane];
    }
    __syncwarp();

    if (lane < TSEQ) {
        float4 qv[8];
        const float4* qp = (const float4*)(qk + (tokbase + lane) * 512 + h * 32);
#pragma unroll
        for (int i = 0; i < 8; i++) qv[i] = qp[i];

        const float scale = 0.1767766952966369f;
        float p[25];
        float m = -1e30f;
#pragma unroll
        for (int j = 0; j < TSEQ; j++) {
            const float4* kp = (const float4*)Ks[w][j];
            float a = 0.f;
#pragma unroll
            for (int i = 0; i < 8; i++) {
                float4 k4 = kp[i];
                a = fmaf(qv[i].x, k4.x, a); a = fmaf(qv[i].y, k4.y, a);
                a = fmaf(qv[i].z, k4.z, a); a = fmaf(qv[i].w, k4.w, a);
            }
            p[j] = a * scale;
            m = fmaxf(m, p[j]);
        }
        float sum = 0.f;
#pragma unroll
        for (int j = 0; j < TSEQ; j++) { p[j] = __expf(p[j] - m); sum += p[j]; }
        const float inv = 1.f / sum;
#pragma unroll
        for (int d4 = 0; d4 < 8; d4++) {
            float4 o = make_float4(0.f, 0.f, 0.f, 0.f);
#pragma unroll
            for (int j = 0; j < TSEQ; j++) {
                float4 v4 = ((const float4*)Vs[w][j])[d4];
                o.x = fmaf(p[j], v4.x, o.x); o.y = fmaf(p[j], v4.y, o.y);
                o.z = fmaf(p[j], v4.z, o.z); o.w = fmaf(p[j], v4.w, o.w);
            }
            float* orow = &Os[w][lane][d4 * 4];
            orow[0] = o.x * inv; orow[1] = o.y * inv;
            orow[2] = o.z * inv; orow[3] = o.w * inv;
        }
    }
    __syncwarp();
    for (int i = lane; i < TSEQ * 32; i += 32) {
        int r = i >> 5;
        out[(tokbase + r) * 256 + h * 32 + lane] = __float2bfloat16(Os[w][r][lane]);
    }
}

// ---------------- layernorm ----------------
__global__ void ln_kernel(const float* __restrict__ x, const float* __restrict__ g,
                          const float* __restrict__ b, float* __restrict__ y,
                          const float* __restrict__ pos, __nv_bfloat16* __restrict__ y2b,
                          __nv_bfloat16* __restrict__ yb) {
    const int row = blockIdx.x;
    const int c = threadIdx.x;
    const size_t idx = (size_t)row * 256 + c;
    float v = x[idx];

    __shared__ float red[8];
    float s = v;
#pragma unroll
    for (int o = 16; o; o >>= 1) s += __shfl_xor_sync(~0u, s, o);
    if ((c & 31) == 0) red[c >> 5] = s;
    __syncthreads();
    float tot = red[0] + red[1] + red[2] + red[3] + red[4] + red[5] + red[6] + red[7];
    float mean = tot * (1.f / 256.f);
    float d = v - mean;
    float s2 = d * d;
#pragma unroll
    for (int o = 16; o; o >>= 1) s2 += __shfl_xor_sync(~0u, s2, o);
    __syncthreads();
    if ((c & 31) == 0) red[c >> 5] = s2;
    __syncthreads();
    float var = (red[0] + red[1] + red[2] + red[3] + red[4] + red[5] + red[6] + red[7]) * (1.f / 256.f);
    float out = d * rsqrtf(var + 1e-5f) * g[c] + b[c];
    y[idx] = out;
    if (y2b) y2b[idx] = __float2bfloat16(out + pos[idx]);
    if (yb) yb[idx] = __float2bfloat16(out);
}

// ---------------- aw softmax (over g_offaw cols 256..383, stride 384) -------
__global__ void aw_softmax_kernel(float* __restrict__ offaw) {
    const int token = blockIdx.x;
    const int t = threadIdx.x;
    const size_t idx = (size_t)token * 384 + 256 + t;
    float v = offaw[idx];
    float m = v;
#pragma unroll
    for (int o = 8; o; o >>= 1) m = fmaxf(m, __shfl_xor_sync(~0u, m, o, 16));
    float e = __expf(v - m);
    float s = e;
#pragma unroll
    for (int o = 8; o; o >>= 1) s += __shfl_xor_sync(~0u, s, o, 16);
    offaw[idx] = e / s;
}

// ---------------- deformable sampling, bf16 out ----------------
__global__ void deform_kernel(const float* __restrict__ ref,
                              const int* __restrict__ shapes,
                              const int* __restrict__ lstart,
                              __nv_bfloat16* __restrict__ out) {
    const int token = blockIdx.x;
    const int h = threadIdx.x >> 5;
    const int lane = threadIdx.x & 31;
    const int b = token / LQTOT;
    const int lq = token - b * LQTOT;

    const float* offp = g_offaw + (size_t)token * 384 + h * 32;
    const float* awp  = g_offaw + (size_t)token * 384 + 256 + h * 16;
    const float* refp = ref + ((size_t)(b * LQTOT + lq) * NL) * 2;
    const size_t vbase = ((size_t)b * SVAL) * 256;

    float acc = 0.f;
#pragma unroll
    for (int l = 0; l < NL; l++) {
        const int Hl = shapes[l * 2];
        const int Wl = shapes[l * 2 + 1];
        const int st = lstart[l];
        const float rx = refp[l * 2];
        const float ry = refp[l * 2 + 1];
        const float fW = (float)Wl, fH = (float)Hl;
#pragma unroll
        for (int p = 0; p < 4; p++) {
            float ox = offp[l * 8 + p * 2];
            float oy = offp[l * 8 + p * 2 + 1];
            float aww = awp[l * 4 + p];
            float x = (rx + ox / fW) * fW - 0.5f;
            float y = (ry + oy / fH) * fH - 0.5f;
            float fx0 = floorf(x), fy0 = floorf(y);
            float wx = x - fx0, wy = y - fy0;
            int x0 = (int)fx0, y0 = (int)fy0;
            float tw[4] = {(1.f - wx) * (1.f - wy), wx * (1.f - wy),
                           (1.f - wx) * wy, wx * wy};
            int xs[4] = {x0, x0 + 1, x0, x0 + 1};
            int ys[4] = {y0, y0, y0 + 1, y0 + 1};
#pragma unroll
            for (int tgt = 0; tgt < 4; tgt++) {
                int xi = xs[tgt], yi = ys[tgt];
                if (xi >= 0 && xi < Wl && yi >= 0 && yi < Hl) {
                    size_t vi = vbase + ((size_t)(st + yi * Wl + xi)) * 256 + h * 32 + lane;
                    acc = fmaf(g_value[vi], tw[tgt] * aww, acc);
                }
            }
        }
    }
    out[(size_t)token * 256 + h * 32 + lane] = __float2bfloat16(acc);
}

// ---------------- launch ----------------
static void* sym(const void* s) {
    void* p = nullptr;
    cudaGetSymbolAddress(&p, s);
    return p;
}

template <int EPI, int OUTBF, int NC>
static void launch_gemm(const __nv_bfloat16* A, const __nv_bfloat16* B, const float* bias,
                        const float* res, void* C, int M, int N, cudaStream_t st) {
    static bool done = false;
    if (!done) {
        cudaFuncSetAttribute(gemm_mma<EPI, OUTBF, NC>, cudaFuncAttributeMaxDynamicSharedMemorySize, GEMM_SMEM);
        done = true;
    }
    dim3 grid(N / 128, (M + 127) / 128);
    gemm_mma<EPI, OUTBF, NC><<<grid, 256, GEMM_SMEM, st>>>(A, B, bias, res, C, M, N);
}

extern "C" void kernel_launch(void* const* d_in, const int* in_sizes, int n_in,
                              void* d_out, int out_size) {
    const float* tgt  = (const float*)d_in[0];
    const float* pos  = (const float*)d_in[1];
    const float* ref  = (const float*)d_in[2];
    const float* src  = (const float*)d_in[3];
    const int* shapes = (const int*)d_in[4];
    const int* lstart = (const int*)d_in[5];
    const float* in_proj_w  = (const float*)d_in[6];
    const float* in_proj_b  = (const float*)d_in[7];
    const float* out_proj_w = (const float*)d_in[8];
    const float* out_proj_b = (const float*)d_in[9];
    const float* ln1_g = (const float*)d_in[10];
    const float* ln1_b = (const float*)d_in[11];
    const float* samp_off_w = (const float*)d_in[12];
    const float* samp_off_b = (const float*)d_in[13];
    const float* aw_w = (const float*)d_in[14];
    const float* aw_b = (const float*)d_in[15];
    const float* vp_w = (const float*)d_in[16];
    const float* vp_b = (const float*)d_in[17];
    const float* op_w = (const float*)d_in[18];
    const float* op_b = (const float*)d_in[19];
    const float* ln2_g = (const float*)d_in[20];
    const float* ln2_b = (const float*)d_in[21];
    const float* ffn1_w = (const float*)d_in[22];
    const float* ffn1_b = (const float*)d_in[23];
    const float* ffn2_w = (const float*)d_in[24];
    const float* ffn2_b = (const float*)d_in[25];
    const float* ln3_g = (const float*)d_in[26];
    const float* ln3_b = (const float*)d_in[27];

    float* p_qk    = (float*)sym(g_qk);
    float* p_v     = (float*)sym(g_v);
    float* p_res1  = (float*)sym(g_res1);
    float* p_ln1   = (float*)sym(g_ln1);
    float* p_offaw = (float*)sym(g_offaw);
    float* p_value = (float*)sym(g_value);
    float* p_res2  = (float*)sym(g_res2);
    float* p_ln2   = (float*)sym(g_ln2);
    float* p_res3  = (float*)sym(g_res3);
    float* p_b384  = (float*)sym(g_bias384);

    __nv_bfloat16* b_tgt   = (__nv_bfloat16*)sym(gb_tgt);
    __nv_bfloat16* b_qksum = (__nv_bfloat16*)sym(gb_qksum);
    __nv_bfloat16* b_attn  = (__nv_bfloat16*)sym(gb_attn);
    __nv_bfloat16* b_query = (__nv_bfloat16*)sym(gb_query);
    __nv_bfloat16* b_src   = (__nv_bfloat16*)sym(gb_src);
    __nv_bfloat16* b_accum = (__nv_bfloat16*)sym(gb_accum);
    __nv_bfloat16* b_ln2   = (__nv_bfloat16*)sym(gb_ln2);
    __nv_bfloat16* b_ffn1  = (__nv_bfloat16*)sym(gb_ffn1);
    __nv_bfloat16* b_inproj = (__nv_bfloat16*)sym(gb_inproj);
    __nv_bfloat16* b_outproj = (__nv_bfloat16*)sym(gb_outproj);
    __nv_bfloat16* b_soffaw = (__nv_bfloat16*)sym(gb_soffaw);
    __nv_bfloat16* b_vp    = (__nv_bfloat16*)sym(gb_vp);
    __nv_bfloat16* b_op    = (__nv_bfloat16*)sym(gb_op);
    __nv_bfloat16* b_f1w   = (__nv_bfloat16*)sym(gb_f1w);
    __nv_bfloat16* b_f2w   = (__nv_bfloat16*)sym(gb_f2w);

    // side streams + events (created once; host resources only)
    static cudaStream_t s2 = nullptr, s3 = nullptr;
    static cudaEvent_t evPre = nullptr, evV = nullptr, evVp = nullptr;
    if (!s2) {
        cudaStreamCreateWithFlags(&s2, cudaStreamNonBlocking);
        cudaStreamCreateWithFlags(&s3, cudaStreamNonBlocking);
        cudaEventCreateWithFlags(&evPre, cudaEventDisableTiming);
        cudaEventCreateWithFlags(&evV, cudaEventDisableTiming);
        cudaEventCreateWithFlags(&evVp, cudaEventDisableTiming);
    }

    // ---- launch 1: weight converts + bias concat ----
    {
        WConvArgs a;
        const float* ins[8] = {in_proj_w, out_proj_w, samp_off_w, aw_w, vp_w, op_w, ffn1_w, ffn2_w};
        __nv_bfloat16* outs[8] = {b_inproj, b_outproj, b_soffaw, b_soffaw + 256 * 256,
                                  b_vp, b_op, b_f1w, b_f2w};
        int ns[8] = {768 * 256, 256 * 256, 256 * 256, 128 * 256, 256 * 256, 256 * 256, 1024 * 256, 256 * 1024};
        int acc4 = 0;
        for (int i = 0; i < 8; i++) {
            a.in[i] = (const float4*)ins[i];
            a.out[i] = (uint2*)outs[i];
            a.off4[i] = acc4;
            acc4 += ns[i] / 4;
        }
        a.off4[8] = acc4;
        a.sob4 = (const float4*)samp_off_b;
        a.awb4 = (const float4*)aw_b;
        a.bias384 = (float4*)p_b384;
        wconv_kernel<<<(acc4 + 255) / 256, 256>>>(a);
    }

    const int n4 = NTOK * CDIM / 4;
    // launch 2
    addb_kernel<<<(n4 + 255) / 256, 256>>>(tgt, pos, b_qksum, n4);
    // launch 3
    f2b_kernel<<<(n4 + 255) / 256, 256>>>(tgt, b_tgt, n4);
    // launch 4
    const int s4 = BB * SVAL * CDIM / 4;
    f2b_kernel<<<(s4 + 255) / 256, 256>>>(src, b_src, s4);

    // fork point: weights + activations converted
    cudaEventRecord(evPre, 0);

    // launch 5 (ncu-profiled slot): qk GEMM on main stream
    launch_gemm<0, 0, 4>(b_qksum, b_inproj, in_proj_b, nullptr, p_qk, NTOK, 512, 0);

    // v GEMM on s3 (parallel with qk)
    cudaStreamWaitEvent(s3, evPre, 0);
    launch_gemm<0, 0, 4>(b_tgt, b_inproj + 512 * 256, in_proj_b + 512, nullptr, p_v, NTOK, 256, s3);
    cudaEventRecord(evV, s3);

    // vp GEMM on s2 (parallel with the whole attn chain)
    cudaStreamWaitEvent(s2, evPre, 0);
    launch_gemm<0, 0, 4>(b_src, b_vp, vp_b, nullptr, p_value, BB * SVAL, 256, s2);
    cudaEventRecord(evVp, s2);

    // main: join v, run attention chain
    cudaStreamWaitEvent(0, evV, 0);
    attn_kernel<<<NSEQ * 2, 128>>>(p_qk, p_v, b_attn);

    launch_gemm<2, 0, 4>(b_attn, b_outproj, out_proj_b, tgt, p_res1, NTOK, 256, 0);
    ln_kernel<<<NTOK, 256>>>(p_res1, ln1_g, ln1_b, p_ln1, pos, b_query, nullptr);

    // fused samp_off + aw GEMM: [M, 384]
    launch_gemm<0, 0, 4>(b_query, b_soffaw, p_b384, nullptr, p_offaw, NTOK, 384, 0);
    aw_softmax_kernel<<<NTOK, 128>>>(p_offaw);

    // join vp, sample
    cudaStreamWaitEvent(0, evVp, 0);
    deform_kernel<<<NTOK, 256>>>(ref, shapes, lstart, b_accum);

    launch_gemm<2, 0, 4>(b_accum, b_op, op_b, p_ln1, p_res2, NTOK, 256, 0);
    ln_kernel<<<NTOK, 256>>>(p_res2, ln2_g, ln2_b, p_ln2, nullptr, nullptr, b_ln2);

    launch_gemm<1, 1, 4>(b_ln2, b_f1w, ffn1_b, nullptr, b_ffn1, NTOK, DFF, 0);
    launch_gemm<2, 0, 16>(b_ffn1, b_f2w, ffn2_b, p_ln2, p_res3, NTOK, 256, 0);
    ln_kernel<<<NTOK, 256>>>(p_res3, ln3_g, ln3_b, (float*)d_out, nullptr, nullptr, nullptr);
}

// round 8
// speedup vs baseline: 3.0514x; 1.0104x over previous
#include <cuda_runtime.h>
#include <cuda_bf16.h>
#include <math.h>
#include <stdint.h>

// ---------------- problem constants ----------------
#define BB    2
#define QQ    300
#define TSEQ  25
#define CDIM  256
#define NHEADS 8
#define HDIM  32
#define NL    4
#define NP    4
#define DFF   1024
#define LQTOT 7500
#define NTOK  15000
#define NSEQ  600
#define SVAL  21760

// ---------------- fp32 scratch ----------------
__device__ __align__(16) float g_res1[NTOK * CDIM];
__device__ __align__(16) float g_ln1[NTOK * CDIM];
__device__ __align__(16) float g_offaw[NTOK * 384];
__device__ __align__(16) float g_res2[NTOK * CDIM];
__device__ __align__(16) float g_ln2[NTOK * CDIM];
__device__ __align__(16) float g_res3[NTOK * CDIM];
__device__ __align__(16) float g_bias384[384];

// ---------------- bf16 scratch ----------------
__device__ __align__(16) __nv_bfloat16 gb_qk[NTOK * 512];
__device__ __align__(16) __nv_bfloat16 gb_v[NTOK * CDIM];
__device__ __align__(16) __nv_bfloat16 gb_value[(size_t)BB * SVAL * CDIM];
__device__ __align__(16) __nv_bfloat16 gb_tgt[NTOK * CDIM];
__device__ __align__(16) __nv_bfloat16 gb_qksum[NTOK * CDIM];
__device__ __align__(16) __nv_bfloat16 gb_attn[NTOK * CDIM];
__device__ __align__(16) __nv_bfloat16 gb_query[NTOK * CDIM];
__device__ __align__(16) __nv_bfloat16 gb_src[(size_t)BB * SVAL * CDIM];
__device__ __align__(16) __nv_bfloat16 gb_accum[NTOK * CDIM];
__device__ __align__(16) __nv_bfloat16 gb_ln2[NTOK * CDIM];
__device__ __align__(16) __nv_bfloat16 gb_ffn1[NTOK * DFF];
// weights
__device__ __align__(16) __nv_bfloat16 gb_inproj[768 * 256];
__device__ __align__(16) __nv_bfloat16 gb_outproj[256 * 256];
__device__ __align__(16) __nv_bfloat16 gb_soffaw[384 * 256];
__device__ __align__(16) __nv_bfloat16 gb_vp[256 * 256];
__device__ __align__(16) __nv_bfloat16 gb_op[256 * 256];
__device__ __align__(16) __nv_bfloat16 gb_f1w[1024 * 256];
__device__ __align__(16) __nv_bfloat16 gb_f2w[256 * 1024];

// ================= helpers =================
__device__ __forceinline__ uint32_t smem_to_u32(const void* p) {
    uint32_t a;
    asm("{ .reg .u64 t; cvta.to.shared.u64 t, %1; cvt.u32.u64 %0, t; }" : "=r"(a) : "l"(p));
    return a;
}
__device__ __forceinline__ void cpasync16(uint32_t dst, const void* src) {
    asm volatile("cp.async.ca.shared.global [%0], [%1], 16;" :: "r"(dst), "l"(src) : "memory");
}
#define CP_COMMIT() asm volatile("cp.async.commit_group;" ::: "memory")

__device__ __forceinline__ uint32_t lds_u32(uint32_t a) {
    uint32_t r;
    asm volatile("ld.shared.b32 %0, [%1];" : "=r"(r) : "r"(a));
    return r;
}
__device__ __forceinline__ void mma_bf16(float* d, const uint32_t* a, const uint32_t* b) {
    asm volatile(
        "mma.sync.aligned.m16n8k16.row.col.f32.bf16.bf16.f32 "
        "{%0,%1,%2,%3}, {%4,%5,%6,%7}, {%8,%9}, {%0,%1,%2,%3};"
        : "+f"(d[0]), "+f"(d[1]), "+f"(d[2]), "+f"(d[3])
        : "r"(a[0]), "r"(a[1]), "r"(a[2]), "r"(a[3]), "r"(b[0]), "r"(b[1]));
}
__device__ __forceinline__ uint32_t pack_bf16(float x, float y) {
    uint32_t r;
    asm("cvt.rn.bf16x2.f32 %0, %1, %2;" : "=r"(r) : "f"(y), "f"(x));
    return r;
}
__device__ __forceinline__ float bf_lo(uint32_t u) {
    return __uint_as_float(u << 16);
}
__device__ __forceinline__ float bf_hi(uint32_t u) {
    return __uint_as_float(u & 0xFFFF0000u);
}

// ================= bf16 mma.sync GEMM, 3-stage pipeline, compile-time K ======
#define GEMM_SMEM (3 * 32768)

template <int K>
__device__ __forceinline__ void fill_chunk_b(uint32_t sbuf,
                                             const __nv_bfloat16* __restrict__ A,
                                             const __nv_bfloat16* __restrict__ B,
                                             int bm, int bn, int M, int k0, int tid) {
    const int r = tid & 127;
    const int which = tid >> 7;
    int ar = bm + r; if (ar >= M) ar = M - 1;
    const __nv_bfloat16* gp = which ? (B + (size_t)(bn + r) * K + k0)
                                    : (A + (size_t)ar * K + k0);
    const uint32_t d = sbuf + (uint32_t)(which * 16384) + (uint32_t)(r * 128);
    const int x = r & 7;
#pragma unroll
    for (int j = 0; j < 8; j++)
        cpasync16(d + (uint32_t)((j ^ x) << 4), gp + j * 8);
}

template <int EPI, int OUTBF, int NC>
__global__ __launch_bounds__(256, 2) void gemm_mma(
        const __nv_bfloat16* __restrict__ A, const __nv_bfloat16* __restrict__ B,
        const float* __restrict__ bias, const float* __restrict__ res,
        void* __restrict__ Cout, int M, int N) {
    constexpr int K = NC * 64;
    extern __shared__ char smem[];
    const uint32_t smem_u = smem_to_u32(smem);
    const int tid = threadIdx.x;
    const int wid = tid >> 5;
    const int lane = tid & 31;
    const int wm = wid & 3;
    const int wn = wid >> 2;
    const int q = lane >> 2;
    const int t4 = (lane & 3) << 2;
    const int bm = blockIdx.y * 128;
    const int bn = blockIdx.x * 128;

    float acc[2][8][4];
#pragma unroll
    for (int mt = 0; mt < 2; mt++)
#pragma unroll
        for (int nt = 0; nt < 8; nt++)
#pragma unroll
            for (int e = 0; e < 4; e++) acc[mt][nt][e] = 0.f;

    fill_chunk_b<K>(smem_u, A, B, bm, bn, M, 0, tid);
    CP_COMMIT();
    fill_chunk_b<K>(smem_u + 32768, A, B, bm, bn, M, 64, tid);
    CP_COMMIT();

    const uint32_t aRow = (uint32_t)((wm * 32 + q) * 128);
    const uint32_t bRow = (uint32_t)((wn * 64 + q) * 128) + 16384;

#pragma unroll
    for (int i = 0; i < NC; i++) {
        const int stage = i % 3;
        if (i + 2 < NC) {
            const int fs = (i + 2) % 3;
            fill_chunk_b<K>(smem_u + (uint32_t)(fs * 32768), A, B, bm, bn, M, (i + 2) * 64, tid);
        }
        CP_COMMIT();
        asm volatile("cp.async.wait_group 2;" ::: "memory");
        __syncthreads();

        const uint32_t buf = smem_u + (uint32_t)(stage * 32768);

#pragma unroll
        for (int ks = 0; ks < 4; ks++) {
            const uint32_t g0 = (uint32_t)((((ks << 1)    ) ^ q) << 4);
            const uint32_t g1 = (uint32_t)((((ks << 1) | 1) ^ q) << 4);
            uint32_t Af[2][4];
#pragma unroll
            for (int mt = 0; mt < 2; mt++) {
                const uint32_t ro = buf + aRow + (uint32_t)(mt * 2048);
                Af[mt][0] = lds_u32(ro + g0 + t4);
                Af[mt][1] = lds_u32(ro + 1024 + g0 + t4);
                Af[mt][2] = lds_u32(ro + g1 + t4);
                Af[mt][3] = lds_u32(ro + 1024 + g1 + t4);
            }
            uint32_t Bf[8][2];
#pragma unroll
            for (int nt = 0; nt < 8; nt++) {
                const uint32_t ro = buf + bRow + (uint32_t)(nt * 1024);
                Bf[nt][0] = lds_u32(ro + g0 + t4);
                Bf[nt][1] = lds_u32(ro + g1 + t4);
            }
#pragma unroll
            for (int mt = 0; mt < 2; mt++)
#pragma unroll
                for (int nt = 0; nt < 8; nt++)
                    mma_bf16(acc[mt][nt], Af[mt], Bf[nt]);
        }
        __syncthreads();
    }

    // ---- epilogue ----
    const int ccol = bn + wn * 64;
    const float* biasp = bias + ccol;
    const int t2 = (lane & 3) * 2;
#pragma unroll
    for (int mt = 0; mt < 2; mt++) {
#pragma unroll
        for (int rs = 0; rs < 2; rs++) {
            const int r = bm + wm * 32 + mt * 16 + q + rs * 8;
            if (r >= M) continue;
            const float* rp = (EPI == 2) ? res + (size_t)r * N + ccol : nullptr;
#pragma unroll
            for (int nt = 0; nt < 8; nt++) {
                const int c = nt * 8 + t2;
                float vx = acc[mt][nt][rs * 2 + 0] + biasp[c];
                float vy = acc[mt][nt][rs * 2 + 1] + biasp[c + 1];
                if (EPI == 1) { vx = fmaxf(vx, 0.f); vy = fmaxf(vy, 0.f); }
                if (EPI == 2) { vx += rp[c]; vy += rp[c + 1]; }
                if (OUTBF) {
                    uint32_t* cp = (uint32_t*)((__nv_bfloat16*)Cout + (size_t)r * N + ccol + c);
                    *cp = pack_bf16(vx, vy);
                } else {
                    float* cp = (float*)Cout + (size_t)r * N + ccol + c;
                    *(float2*)cp = make_float2(vx, vy);
                }
            }
        }
    }
}

// ---------------- fused weight convert + bias concat ------------
struct WConvArgs {
    const float4* in[8];
    uint2* out[8];
    int off4[9];
    const float4* sob4;
    const float4* awb4;
    float4* bias384;
};
__global__ void wconv_kernel(WConvArgs a) {
    int i = blockIdx.x * blockDim.x + threadIdx.x;
    if (i < 96) {
        a.bias384[i] = (i < 64) ? a.sob4[i] : a.awb4[i - 64];
    }
    if (i >= a.off4[8]) return;
    int s = 0;
#pragma unroll
    for (int k = 1; k < 8; k++) s += (i >= a.off4[k]);
    int j = i - a.off4[s];
    float4 v = a.in[s][j];
    uint2 o;
    o.x = pack_bf16(v.x, v.y);
    o.y = pack_bf16(v.z, v.w);
    a.out[s][j] = o;
}

// ---------------- fp32 -> bf16 convert ----------------
__global__ void f2b_kernel(const float* __restrict__ in, __nv_bfloat16* __restrict__ out, int n4) {
    int i = blockIdx.x * blockDim.x + threadIdx.x;
    if (i < n4) {
        float4 v = ((const float4*)in)[i];
        uint2 o;
        o.x = pack_bf16(v.x, v.y);
        o.y = pack_bf16(v.z, v.w);
        ((uint2*)out)[i] = o;
    }
}

// ---------------- fused: qksum = bf16(tgt+pos), tgtb = bf16(tgt) ----------
__global__ void prep_kernel(const float* __restrict__ tgt, const float* __restrict__ pos,
                            __nv_bfloat16* __restrict__ qksum, __nv_bfloat16* __restrict__ tgtb,
                            int n4) {
    int i = blockIdx.x * blockDim.x + threadIdx.x;
    if (i < n4) {
        float4 x = ((const float4*)tgt)[i];
        float4 y = ((const float4*)pos)[i];
        uint2 t;
        t.x = pack_bf16(x.x, x.y);
        t.y = pack_bf16(x.z, x.w);
        ((uint2*)tgtb)[i] = t;
        uint2 o;
        o.x = pack_bf16(x.x + y.x, x.y + y.y);
        o.y = pack_bf16(x.z + y.z, x.w + y.w);
        ((uint2*)qksum)[i] = o;
    }
}

// ---------------- self-attention (lane = query), bf16 in/out ----------
__global__ __launch_bounds__(128) void attn_kernel(
        const __nv_bfloat16* __restrict__ qk, const __nv_bfloat16* __restrict__ v,
        __nv_bfloat16* __restrict__ out) {
    const int seq  = blockIdx.x >> 1;
    const int w    = threadIdx.x >> 5;
    const int h    = ((blockIdx.x & 1) << 2) + w;
    const int lane = threadIdx.x & 31;

    __shared__ float Ks[4][25][32];
    __shared__ float Vs[4][25][32];
    __shared__ float Os[4][25][36];

    const size_t tokbase = (size_t)seq * TSEQ;
    for (int i = lane; i < TSEQ * 32; i += 32) {
        int r = i >> 5;
        Ks[w][r][lane] = __bfloat162float(qk[(tokbase + r) * 512 + 256 + h * 32 + lane]);
        Vs[w][r][lane] = __bfloat162float(v[(tokbase + r) * 256 + h * 32 + lane]);
    }
    __syncwarp();

    if (lane < TSEQ) {
        // load this lane's 32-dim q as 4 x uint4 (16 x bf16x2)
        float qv[32];
        const uint4* qp = (const uint4*)(qk + (tokbase + lane) * 512 + h * 32);
#pragma unroll
        for (int i = 0; i < 4; i++) {
            uint4 u = qp[i];
            uint32_t us[4] = {u.x, u.y, u.z, u.w};
#pragma unroll
            for (int j = 0; j < 4; j++) {
                qv[i * 8 + j * 2 + 0] = bf_lo(us[j]);
                qv[i * 8 + j * 2 + 1] = bf_hi(us[j]);
            }
        }

        const float scale = 0.1767766952966369f;
        float p[25];
        float m = -1e30f;
#pragma unroll
        for (int j = 0; j < TSEQ; j++) {
            const float* kp = Ks[w][j];
            float a = 0.f;
#pragma unroll
            for (int i = 0; i < 32; i++) a = fmaf(qv[i], kp[i], a);
            p[j] = a * scale;
            m = fmaxf(m, p[j]);
        }
        float sum = 0.f;
#pragma unroll
        for (int j = 0; j < TSEQ; j++) { p[j] = __expf(p[j] - m); sum += p[j]; }
        const float inv = 1.f / sum;
#pragma unroll
        for (int d4 = 0; d4 < 8; d4++) {
            float4 o = make_float4(0.f, 0.f, 0.f, 0.f);
#pragma unroll
            for (int j = 0; j < TSEQ; j++) {
                float4 v4 = ((const float4*)Vs[w][j])[d4];
                o.x = fmaf(p[j], v4.x, o.x); o.y = fmaf(p[j], v4.y, o.y);
                o.z = fmaf(p[j], v4.z, o.z); o.w = fmaf(p[j], v4.w, o.w);
            }
            float* orow = &Os[w][lane][d4 * 4];
            orow[0] = o.x * inv; orow[1] = o.y * inv;
            orow[2] = o.z * inv; orow[3] = o.w * inv;
        }
    }
    __syncwarp();
    for (int i = lane; i < TSEQ * 32; i += 32) {
        int r = i >> 5;
        out[(tokbase + r) * 256 + h * 32 + lane] = __float2bfloat16(Os[w][r][lane]);
    }
}

// ---------------- layernorm ----------------
__global__ void ln_kernel(const float* __restrict__ x, const float* __restrict__ g,
                          const float* __restrict__ b, float* __restrict__ y,
                          const float* __restrict__ pos, __nv_bfloat16* __restrict__ y2b,
                          __nv_bfloat16* __restrict__ yb) {
    const int row = blockIdx.x;
    const int c = threadIdx.x;
    const size_t idx = (size_t)row * 256 + c;
    float v = x[idx];

    __shared__ float red[8];
    float s = v;
#pragma unroll
    for (int o = 16; o; o >>= 1) s += __shfl_xor_sync(~0u, s, o);
    if ((c & 31) == 0) red[c >> 5] = s;
    __syncthreads();
    float tot = red[0] + red[1] + red[2] + red[3] + red[4] + red[5] + red[6] + red[7];
    float mean = tot * (1.f / 256.f);
    float d = v - mean;
    float s2 = d * d;
#pragma unroll
    for (int o = 16; o; o >>= 1) s2 += __shfl_xor_sync(~0u, s2, o);
    __syncthreads();
    if ((c & 31) == 0) red[c >> 5] = s2;
    __syncthreads();
    float var = (red[0] + red[1] + red[2] + red[3] + red[4] + red[5] + red[6] + red[7]) * (1.f / 256.f);
    float out = d * rsqrtf(var + 1e-5f) * g[c] + b[c];
    y[idx] = out;
    if (y2b) y2b[idx] = __float2bfloat16(out + pos[idx]);
    if (yb) yb[idx] = __float2bfloat16(out);
}

// ---------------- deformable sampling w/ fused aw softmax, bf16 value -------
__global__ __launch_bounds__(256) void deform_kernel(
        const float* __restrict__ ref,
        const int* __restrict__ shapes,
        const int* __restrict__ lstart,
        __nv_bfloat16* __restrict__ out) {
    const int token = blockIdx.x;
    const int h = threadIdx.x >> 5;
    const int lane = threadIdx.x & 31;
    const int b = token / LQTOT;
    const int lq = token - b * LQTOT;

    __shared__ float sAw[8][16];

    // fused softmax over the 16 aw logits of this (token, head)
    {
        float v = -1e30f;
        if (lane < 16) v = g_offaw[(size_t)token * 384 + 256 + h * 16 + lane];
        float m = v;
#pragma unroll
        for (int o = 8; o; o >>= 1) m = fmaxf(m, __shfl_xor_sync(~0u, m, o, 16));
        float e = (lane < 16) ? __expf(v - m) : 0.f;
        float s = e;
#pragma unroll
        for (int o = 8; o; o >>= 1) s += __shfl_xor_sync(~0u, s, o, 16);
        if (lane < 16) sAw[h][lane] = e / s;
    }
    __syncwarp();

    const float* offp = g_offaw + (size_t)token * 384 + h * 32;
    const float* awp  = sAw[h];
    const float* refp = ref + ((size_t)(b * LQTOT + lq) * NL) * 2;
    const size_t vbase = ((size_t)b * SVAL) * 256;

    float acc = 0.f;
#pragma unroll
    for (int l = 0; l < NL; l++) {
        const int Hl = shapes[l * 2];
        const int Wl = shapes[l * 2 + 1];
        const int st = lstart[l];
        const float rx = refp[l * 2];
        const float ry = refp[l * 2 + 1];
        const float fW = (float)Wl, fH = (float)Hl;
#pragma unroll
        for (int p = 0; p < 4; p++) {
            float ox = offp[l * 8 + p * 2];
            float oy = offp[l * 8 + p * 2 + 1];
            float aww = awp[l * 4 + p];
            float x = (rx + ox / fW) * fW - 0.5f;
            float y = (ry + oy / fH) * fH - 0.5f;
            float fx0 = floorf(x), fy0 = floorf(y);
            float wx = x - fx0, wy = y - fy0;
            int x0 = (int)fx0, y0 = (int)fy0;
            float tw[4] = {(1.f - wx) * (1.f - wy), wx * (1.f - wy),
                           (1.f - wx) * wy, wx * wy};
            int xs[4] = {x0, x0 + 1, x0, x0 + 1};
            int ys[4] = {y0, y0, y0 + 1, y0 + 1};
#pragma unroll
            for (int tgt = 0; tgt < 4; tgt++) {
                int xi = xs[tgt], yi = ys[tgt];
                if (xi >= 0 && xi < Wl && yi >= 0 && yi < Hl) {
                    size_t vi = vbase + ((size_t)(st + yi * Wl + xi)) * 256 + h * 32 + lane;
                    acc = fmaf(__bfloat162float(gb_value[vi]), tw[tgt] * aww, acc);
                }
            }
        }
    }
    out[(size_t)token * 256 + h * 32 + lane] = __float2bfloat16(acc);
}

// ---------------- launch ----------------
static void* sym(const void* s) {
    void* p = nullptr;
    cudaGetSymbolAddress(&p, s);
    return p;
}

template <int EPI, int OUTBF, int NC>
static void launch_gemm(const __nv_bfloat16* A, const __nv_bfloat16* B, const float* bias,
                        const float* res, void* C, int M, int N, cudaStream_t st) {
    static bool done = false;
    if (!done) {
        cudaFuncSetAttribute(gemm_mma<EPI, OUTBF, NC>, cudaFuncAttributeMaxDynamicSharedMemorySize, GEMM_SMEM);
        done = true;
    }
    dim3 grid(N / 128, (M + 127) / 128);
    gemm_mma<EPI, OUTBF, NC><<<grid, 256, GEMM_SMEM, st>>>(A, B, bias, res, C, M, N);
}

extern "C" void kernel_launch(void* const* d_in, const int* in_sizes, int n_in,
                              void* d_out, int out_size) {
    const float* tgt  = (const float*)d_in[0];
    const float* pos  = (const float*)d_in[1];
    const float* ref  = (const float*)d_in[2];
    const float* src  = (const float*)d_in[3];
    const int* shapes = (const int*)d_in[4];
    const int* lstart = (const int*)d_in[5];
    const float* in_proj_w  = (const float*)d_in[6];
    const float* in_proj_b  = (const float*)d_in[7];
    const float* out_proj_w = (const float*)d_in[8];
    const float* out_proj_b = (const float*)d_in[9];
    const float* ln1_g = (const float*)d_in[10];
    const float* ln1_b = (const float*)d_in[11];
    const float* samp_off_w = (const float*)d_in[12];
    const float* samp_off_b = (const float*)d_in[13];
    const float* aw_w = (const float*)d_in[14];
    const float* aw_b = (const float*)d_in[15];
    const float* vp_w = (const float*)d_in[16];
    const float* vp_b = (const float*)d_in[17];
    const float* op_w = (const float*)d_in[18];
    const float* op_b = (const float*)d_in[19];
    const float* ln2_g = (const float*)d_in[20];
    const float* ln2_b = (const float*)d_in[21];
    const float* ffn1_w = (const float*)d_in[22];
    const float* ffn1_b = (const float*)d_in[23];
    const float* ffn2_w = (const float*)d_in[24];
    const float* ffn2_b = (const float*)d_in[25];
    const float* ln3_g = (const float*)d_in[26];
    const float* ln3_b = (const float*)d_in[27];

    float* p_res1  = (float*)sym(g_res1);
    float* p_ln1   = (float*)sym(g_ln1);
    float* p_offaw = (float*)sym(g_offaw);
    float* p_res2  = (float*)sym(g_res2);
    float* p_ln2   = (float*)sym(g_ln2);
    float* p_res3  = (float*)sym(g_res3);
    float* p_b384  = (float*)sym(g_bias384);

    __nv_bfloat16* b_qk    = (__nv_bfloat16*)sym(gb_qk);
    __nv_bfloat16* b_v     = (__nv_bfloat16*)sym(gb_v);
    __nv_bfloat16* b_value = (__nv_bfloat16*)sym(gb_value);
    __nv_bfloat16* b_tgt   = (__nv_bfloat16*)sym(gb_tgt);
    __nv_bfloat16* b_qksum = (__nv_bfloat16*)sym(gb_qksum);
    __nv_bfloat16* b_attn  = (__nv_bfloat16*)sym(gb_attn);
    __nv_bfloat16* b_query = (__nv_bfloat16*)sym(gb_query);
    __nv_bfloat16* b_src   = (__nv_bfloat16*)sym(gb_src);
    __nv_bfloat16* b_accum = (__nv_bfloat16*)sym(gb_accum);
    __nv_bfloat16* b_ln2   = (__nv_bfloat16*)sym(gb_ln2);
    __nv_bfloat16* b_ffn1  = (__nv_bfloat16*)sym(gb_ffn1);
    __nv_bfloat16* b_inproj = (__nv_bfloat16*)sym(gb_inproj);
    __nv_bfloat16* b_outproj = (__nv_bfloat16*)sym(gb_outproj);
    __nv_bfloat16* b_soffaw = (__nv_bfloat16*)sym(gb_soffaw);
    __nv_bfloat16* b_vp    = (__nv_bfloat16*)sym(gb_vp);
    __nv_bfloat16* b_op    = (__nv_bfloat16*)sym(gb_op);
    __nv_bfloat16* b_f1w   = (__nv_bfloat16*)sym(gb_f1w);
    __nv_bfloat16* b_f2w   = (__nv_bfloat16*)sym(gb_f2w);

    static cudaStream_t s2 = nullptr, s3 = nullptr;
    static cudaEvent_t evPre = nullptr, evV = nullptr, evVp = nullptr;
    if (!s2) {
        cudaStreamCreateWithFlags(&s2, cudaStreamNonBlocking);
        cudaStreamCreateWithFlags(&s3, cudaStreamNonBlocking);
        cudaEventCreateWithFlags(&evPre, cudaEventDisableTiming);
        cudaEventCreateWithFlags(&evV, cudaEventDisableTiming);
        cudaEventCreateWithFlags(&evVp, cudaEventDisableTiming);
    }

    // ---- weight converts + bias concat ----
    {
        WConvArgs a;
        const float* ins[8] = {in_proj_w, out_proj_w, samp_off_w, aw_w, vp_w, op_w, ffn1_w, ffn2_w};
        __nv_bfloat16* outs[8] = {b_inproj, b_outproj, b_soffaw, b_soffaw + 256 * 256,
                                  b_vp, b_op, b_f1w, b_f2w};
        int ns[8] = {768 * 256, 256 * 256, 256 * 256, 128 * 256, 256 * 256, 256 * 256, 1024 * 256, 256 * 1024};
        int acc4 = 0;
        for (int i = 0; i < 8; i++) {
            a.in[i] = (const float4*)ins[i];
            a.out[i] = (uint2*)outs[i];
            a.off4[i] = acc4;
            acc4 += ns[i] / 4;
        }
        a.off4[8] = acc4;
        a.sob4 = (const float4*)samp_off_b;
        a.awb4 = (const float4*)aw_b;
        a.bias384 = (float4*)p_b384;
        wconv_kernel<<<(acc4 + 255) / 256, 256>>>(a);
    }

    const int n4 = NTOK * CDIM / 4;
    prep_kernel<<<(n4 + 255) / 256, 256>>>(tgt, pos, b_qksum, b_tgt, n4);
    const int s4 = BB * SVAL * CDIM / 4;
    f2b_kernel<<<(s4 + 255) / 256, 256>>>(src, b_src, s4);

    cudaEventRecord(evPre, 0);

    // qk GEMM on main stream (bf16 out)
    launch_gemm<0, 1, 4>(b_qksum, b_inproj, in_proj_b, nullptr, b_qk, NTOK, 512, 0);

    // v GEMM on s3 (bf16 out)
    cudaStreamWaitEvent(s3, evPre, 0);
    launch_gemm<0, 1, 4>(b_tgt, b_inproj + 512 * 256, in_proj_b + 512, nullptr, b_v, NTOK, 256, s3);
    cudaEventRecord(evV, s3);

    // vp GEMM on s2 (bf16 value)
    cudaStreamWaitEvent(s2, evPre, 0);
    launch_gemm<0, 1, 4>(b_src, b_vp, vp_b, nullptr, b_value, BB * SVAL, 256, s2);
    cudaEventRecord(evVp, s2);

    cudaStreamWaitEvent(0, evV, 0);
    attn_kernel<<<NSEQ * 2, 128>>>(b_qk, b_v, b_attn);

    launch_gemm<2, 0, 4>(b_attn, b_outproj, out_proj_b, tgt, p_res1, NTOK, 256, 0);
    ln_kernel<<<NTOK, 256>>>(p_res1, ln1_g, ln1_b, p_ln1, pos, b_query, nullptr);

    launch_gemm<0, 0, 4>(b_query, b_soffaw, p_b384, nullptr, p_offaw, NTOK, 384, 0);

    cudaStreamWaitEvent(0, evVp, 0);
    deform_kernel<<<NTOK, 256>>>(ref, shapes, lstart, b_accum);

    launch_gemm<2, 0, 4>(b_accum, b_op, op_b, p_ln1, p_res2, NTOK, 256, 0);
    ln_kernel<<<NTOK, 256>>>(p_res2, ln2_g, ln2_b, p_ln2, nullptr, nullptr, b_ln2);

    launch_gemm<1, 1, 4>(b_ln2, b_f1w, ffn1_b, nullptr, b_ffn1, NTOK, DFF, 0);
    launch_gemm<2, 0, 16>(b_ffn1, b_f2w, ffn2_b, p_ln2, p_res3, NTOK, 256, 0);
    ln_kernel<<<NTOK, 256>>>(p_res3, ln3_g, ln3_b, (float*)d_out, nullptr, nullptr, nullptr);
}

// round 9
// speedup vs baseline: 3.1415x; 1.0295x over previous
#include <cuda_runtime.h>
#include <cuda_bf16.h>
#include <math.h>
#include <stdint.h>

// ---------------- problem constants ----------------
#define BB    2
#define QQ    300
#define TSEQ  25
#define CDIM  256
#define NHEADS 8
#define HDIM  32
#define NL    4
#define NP    4
#define DFF   1024
#define LQTOT 7500
#define NTOK  15000
#define NSEQ  600
#define SVAL  21760

// ---------------- fp32 scratch ----------------
__device__ __align__(16) float g_res1[NTOK * CDIM];
__device__ __align__(16) float g_ln1[NTOK * CDIM];
__device__ __align__(16) float g_offaw[NTOK * 384];
__device__ __align__(16) float g_res2[NTOK * CDIM];
__device__ __align__(16) float g_ln2[NTOK * CDIM];
__device__ __align__(16) float g_res3[NTOK * CDIM];
__device__ __align__(16) float g_bias384[384];

// ---------------- bf16 scratch ----------------
__device__ __align__(16) __nv_bfloat16 gb_qk[NTOK * 512];
__device__ __align__(16) __nv_bfloat16 gb_v[NTOK * CDIM];
__device__ __align__(16) __nv_bfloat16 gb_value[(size_t)BB * SVAL * CDIM];
__device__ __align__(16) __nv_bfloat16 gb_tgt[NTOK * CDIM];
__device__ __align__(16) __nv_bfloat16 gb_qksum[NTOK * CDIM];
__device__ __align__(16) __nv_bfloat16 gb_attn[NTOK * CDIM];
__device__ __align__(16) __nv_bfloat16 gb_query[NTOK * CDIM];
__device__ __align__(16) __nv_bfloat16 gb_src[(size_t)BB * SVAL * CDIM];
__device__ __align__(16) __nv_bfloat16 gb_accum[NTOK * CDIM];
__device__ __align__(16) __nv_bfloat16 gb_ln2[NTOK * CDIM];
__device__ __align__(16) __nv_bfloat16 gb_ffn1[NTOK * DFF];
// weights
__device__ __align__(16) __nv_bfloat16 gb_inproj[768 * 256];
__device__ __align__(16) __nv_bfloat16 gb_outproj[256 * 256];
__device__ __align__(16) __nv_bfloat16 gb_soffaw[384 * 256];
__device__ __align__(16) __nv_bfloat16 gb_vp[256 * 256];
__device__ __align__(16) __nv_bfloat16 gb_op[256 * 256];
__device__ __align__(16) __nv_bfloat16 gb_f1w[1024 * 256];
__device__ __align__(16) __nv_bfloat16 gb_f2w[256 * 1024];

// ================= helpers =================
__device__ __forceinline__ uint32_t smem_to_u32(const void* p) {
    uint32_t a;
    asm("{ .reg .u64 t; cvta.to.shared.u64 t, %1; cvt.u32.u64 %0, t; }" : "=r"(a) : "l"(p));
    return a;
}
__device__ __forceinline__ void cpasync16(uint32_t dst, const void* src) {
    asm volatile("cp.async.ca.shared.global [%0], [%1], 16;" :: "r"(dst), "l"(src) : "memory");
}
#define CP_COMMIT() asm volatile("cp.async.commit_group;" ::: "memory")

__device__ __forceinline__ void ldmatrix_x4(uint32_t& r0, uint32_t& r1, uint32_t& r2,
                                            uint32_t& r3, uint32_t addr) {
    asm volatile("ldmatrix.sync.aligned.m8n8.x4.shared.b16 {%0,%1,%2,%3}, [%4];"
                 : "=r"(r0), "=r"(r1), "=r"(r2), "=r"(r3) : "r"(addr));
}
__device__ __forceinline__ void mma_bf16(float* d, const uint32_t* a, uint32_t b0, uint32_t b1) {
    asm volatile(
        "mma.sync.aligned.m16n8k16.row.col.f32.bf16.bf16.f32 "
        "{%0,%1,%2,%3}, {%4,%5,%6,%7}, {%8,%9}, {%0,%1,%2,%3};"
        : "+f"(d[0]), "+f"(d[1]), "+f"(d[2]), "+f"(d[3])
        : "r"(a[0]), "r"(a[1]), "r"(a[2]), "r"(a[3]), "r"(b0), "r"(b1));
}
__device__ __forceinline__ uint32_t pack_bf16(float x, float y) {
    uint32_t r;
    asm("cvt.rn.bf16x2.f32 %0, %1, %2;" : "=r"(r) : "f"(y), "f"(x));
    return r;
}

// ================= bf16 mma.sync GEMM, ldmatrix fragments =================
#define GEMM_SMEM (3 * 32768)

template <int K>
__device__ __forceinline__ void fill_chunk_b(uint32_t sbuf,
                                             const __nv_bfloat16* __restrict__ A,
                                             const __nv_bfloat16* __restrict__ B,
                                             int bm, int bn, int M, int k0, int tid) {
    const int r = tid & 127;
    const int which = tid >> 7;
    int ar = bm + r; if (ar >= M) ar = M - 1;
    const __nv_bfloat16* gp = which ? (B + (size_t)(bn + r) * K + k0)
                                    : (A + (size_t)ar * K + k0);
    const uint32_t d = sbuf + (uint32_t)(which * 16384) + (uint32_t)(r * 128);
    const int x = r & 7;
#pragma unroll
    for (int j = 0; j < 8; j++)
        cpasync16(d + (uint32_t)((j ^ x) << 4), gp + j * 8);
}

template <int EPI, int OUTBF, int NC>
__global__ __launch_bounds__(256, 2) void gemm_mma(
        const __nv_bfloat16* __restrict__ A, const __nv_bfloat16* __restrict__ B,
        const float* __restrict__ bias, const float* __restrict__ res,
        void* __restrict__ Cout, int M, int N) {
    constexpr int K = NC * 64;
    extern __shared__ char smem[];
    const uint32_t smem_u = smem_to_u32(smem);
    const int tid = threadIdx.x;
    const int wid = tid >> 5;
    const int lane = tid & 31;
    const int wm = wid & 3;
    const int wn = wid >> 2;
    const int bm = blockIdx.y * 128;
    const int bn = blockIdx.x * 128;

    float acc[2][8][4];
#pragma unroll
    for (int mt = 0; mt < 2; mt++)
#pragma unroll
        for (int nt = 0; nt < 8; nt++)
#pragma unroll
            for (int e = 0; e < 4; e++) acc[mt][nt][e] = 0.f;

    fill_chunk_b<K>(smem_u, A, B, bm, bn, M, 0, tid);
    CP_COMMIT();
    fill_chunk_b<K>(smem_u + 32768, A, B, bm, bn, M, 64, tid);
    CP_COMMIT();

    // ldmatrix lane addressing: 16-row block; lane row = (l&7) + ((l>>3)&1)*8,
    // k-granule = ks*2 + (l>>4), swizzle = (granule ^ (row&7)) * 16
    const uint32_t laneRowOff = (uint32_t)((((lane & 7) + ((lane >> 3) & 1) * 8)) * 128);
    const int xr = lane & 7;
    const int gsel = lane >> 4;
    uint32_t swz[4];
#pragma unroll
    for (int ks = 0; ks < 4; ks++)
        swz[ks] = (uint32_t)(((ks * 2 + gsel) ^ xr) << 4);

    const uint32_t aBase0 = (uint32_t)((wm * 32) * 128) + laneRowOff;
    const uint32_t aBase1 = aBase0 + 16 * 128;
    uint32_t bBase[4];
#pragma unroll
    for (int j = 0; j < 4; j++)
        bBase[j] = 16384u + (uint32_t)((wn * 64 + j * 16) * 128) + laneRowOff;

#pragma unroll
    for (int i = 0; i < NC; i++) {
        const int stage = i % 3;
        if (i + 2 < NC) {
            const int fs = (i + 2) % 3;
            fill_chunk_b<K>(smem_u + (uint32_t)(fs * 32768), A, B, bm, bn, M, (i + 2) * 64, tid);
        }
        CP_COMMIT();
        asm volatile("cp.async.wait_group 2;" ::: "memory");
        __syncthreads();

        const uint32_t buf = smem_u + (uint32_t)(stage * 32768);

#pragma unroll
        for (int ks = 0; ks < 4; ks++) {
            const uint32_t s = swz[ks];
            uint32_t Af[2][4];
            ldmatrix_x4(Af[0][0], Af[0][1], Af[0][2], Af[0][3], buf + aBase0 + s);
            ldmatrix_x4(Af[1][0], Af[1][1], Af[1][2], Af[1][3], buf + aBase1 + s);
            uint32_t Bf[4][4];
#pragma unroll
            for (int j = 0; j < 4; j++)
                ldmatrix_x4(Bf[j][0], Bf[j][1], Bf[j][2], Bf[j][3], buf + bBase[j] + s);
#pragma unroll
            for (int mt = 0; mt < 2; mt++)
#pragma unroll
                for (int j = 0; j < 4; j++) {
                    mma_bf16(acc[mt][j * 2 + 0], Af[mt], Bf[j][0], Bf[j][2]);
                    mma_bf16(acc[mt][j * 2 + 1], Af[mt], Bf[j][1], Bf[j][3]);
                }
        }
        __syncthreads();
    }

    // ---- epilogue ----
    const int q = lane >> 2;
    const int ccol = bn + wn * 64;
    const float* biasp = bias + ccol;
    const int t2 = (lane & 3) * 2;
#pragma unroll
    for (int mt = 0; mt < 2; mt++) {
#pragma unroll
        for (int rs = 0; rs < 2; rs++) {
            const int r = bm + wm * 32 + mt * 16 + q + rs * 8;
            if (r >= M) continue;
            const float* rp = (EPI == 2) ? res + (size_t)r * N + ccol : nullptr;
#pragma unroll
            for (int nt = 0; nt < 8; nt++) {
                const int c = nt * 8 + t2;
                float vx = acc[mt][nt][rs * 2 + 0] + biasp[c];
                float vy = acc[mt][nt][rs * 2 + 1] + biasp[c + 1];
                if (EPI == 1) { vx = fmaxf(vx, 0.f); vy = fmaxf(vy, 0.f); }
                if (EPI == 2) { vx += rp[c]; vy += rp[c + 1]; }
                if (OUTBF) {
                    uint32_t* cp = (uint32_t*)((__nv_bfloat16*)Cout + (size_t)r * N + ccol + c);
                    *cp = pack_bf16(vx, vy);
                } else {
                    float* cp = (float*)Cout + (size_t)r * N + ccol + c;
                    *(float2*)cp = make_float2(vx, vy);
                }
            }
        }
    }
}

// ---------------- fused weight convert + bias concat ------------
struct WConvArgs {
    const float4* in[8];
    uint2* out[8];
    int off4[9];
    const float4* sob4;
    const float4* awb4;
    float4* bias384;
};
__global__ void wconv_kernel(WConvArgs a) {
    int i = blockIdx.x * blockDim.x + threadIdx.x;
    if (i < 96) {
        a.bias384[i] = (i < 64) ? a.sob4[i] : a.awb4[i - 64];
    }
    if (i >= a.off4[8]) return;
    int s = 0;
#pragma unroll
    for (int k = 1; k < 8; k++) s += (i >= a.off4[k]);
    int j = i - a.off4[s];
    float4 v = a.in[s][j];
    uint2 o;
    o.x = pack_bf16(v.x, v.y);
    o.y = pack_bf16(v.z, v.w);
    a.out[s][j] = o;
}

// ---------------- fp32 -> bf16 convert ----------------
__global__ void f2b_kernel(const float* __restrict__ in, __nv_bfloat16* __restrict__ out, int n4) {
    int i = blockIdx.x * blockDim.x + threadIdx.x;
    if (i < n4) {
        float4 v = ((const float4*)in)[i];
        uint2 o;
        o.x = pack_bf16(v.x, v.y);
        o.y = pack_bf16(v.z, v.w);
        ((uint2*)out)[i] = o;
    }
}

// ---------------- fused: qksum = bf16(tgt+pos), tgtb = bf16(tgt) ----------
__global__ void prep_kernel(const float* __restrict__ tgt, const float* __restrict__ pos,
                            __nv_bfloat16* __restrict__ qksum, __nv_bfloat16* __restrict__ tgtb,
                            int n4) {
    int i = blockIdx.x * blockDim.x + threadIdx.x;
    if (i < n4) {
        float4 x = ((const float4*)tgt)[i];
        float4 y = ((const float4*)pos)[i];
        uint2 t;
        t.x = pack_bf16(x.x, x.y);
        t.y = pack_bf16(x.z, x.w);
        ((uint2*)tgtb)[i] = t;
        uint2 o;
        o.x = pack_bf16(x.x + y.x, x.y + y.y);
        o.y = pack_bf16(x.z + y.z, x.w + y.w);
        ((uint2*)qksum)[i] = o;
    }
}

// ---------------- self-attention (lane = query), bf16 in/out ----------
__device__ __forceinline__ float bf_lo(uint32_t u) { return __uint_as_float(u << 16); }
__device__ __forceinline__ float bf_hi(uint32_t u) { return __uint_as_float(u & 0xFFFF0000u); }

__global__ __launch_bounds__(128) void attn_kernel(
        const __nv_bfloat16* __restrict__ qk, const __nv_bfloat16* __restrict__ v,
        __nv_bfloat16* __restrict__ out) {
    const int seq  = blockIdx.x >> 1;
    const int w    = threadIdx.x >> 5;
    const int h    = ((blockIdx.x & 1) << 2) + w;
    const int lane = threadIdx.x & 31;

    __shared__ float Ks[4][25][32];
    __shared__ float Vs[4][25][32];
    __shared__ float Os[4][25][36];

    const size_t tokbase = (size_t)seq * TSEQ;
    for (int i = lane; i < TSEQ * 32; i += 32) {
        int r = i >> 5;
        Ks[w][r][lane] = __bfloat162float(qk[(tokbase + r) * 512 + 256 + h * 32 + lane]);
        Vs[w][r][lane] = __bfloat162float(v[(tokbase + r) * 256 + h * 32 + lane]);
    }
    __syncwarp();

    if (lane < TSEQ) {
        float qv[32];
        const uint4* qp = (const uint4*)(qk + (tokbase + lane) * 512 + h * 32);
#pragma unroll
        for (int i = 0; i < 4; i++) {
            uint4 u = qp[i];
            uint32_t us[4] = {u.x, u.y, u.z, u.w};
#pragma unroll
            for (int j = 0; j < 4; j++) {
                qv[i * 8 + j * 2 + 0] = bf_lo(us[j]);
                qv[i * 8 + j * 2 + 1] = bf_hi(us[j]);
            }
        }

        const float scale = 0.1767766952966369f;
        float p[25];
        float m = -1e30f;
#pragma unroll
        for (int j = 0; j < TSEQ; j++) {
            const float* kp = Ks[w][j];
            float a = 0.f;
#pragma unroll
            for (int i = 0; i < 32; i++) a = fmaf(qv[i], kp[i], a);
            p[j] = a * scale;
            m = fmaxf(m, p[j]);
        }
        float sum = 0.f;
#pragma unroll
        for (int j = 0; j < TSEQ; j++) { p[j] = __expf(p[j] - m); sum += p[j]; }
        const float inv = 1.f / sum;
#pragma unroll
        for (int d4 = 0; d4 < 8; d4++) {
            float4 o = make_float4(0.f, 0.f, 0.f, 0.f);
#pragma unroll
            for (int j = 0; j < TSEQ; j++) {
                float4 v4 = ((const float4*)Vs[w][j])[d4];
                o.x = fmaf(p[j], v4.x, o.x); o.y = fmaf(p[j], v4.y, o.y);
                o.z = fmaf(p[j], v4.z, o.z); o.w = fmaf(p[j], v4.w, o.w);
            }
            float* orow = &Os[w][lane][d4 * 4];
            orow[0] = o.x * inv; orow[1] = o.y * inv;
            orow[2] = o.z * inv; orow[3] = o.w * inv;
        }
    }
    __syncwarp();
    for (int i = lane; i < TSEQ * 32; i += 32) {
        int r = i >> 5;
        out[(tokbase + r) * 256 + h * 32 + lane] = __float2bfloat16(Os[w][r][lane]);
    }
}

// ---------------- layernorm ----------------
__global__ void ln_kernel(const float* __restrict__ x, const float* __restrict__ g,
                          const float* __restrict__ b, float* __restrict__ y,
                          const float* __restrict__ pos, __nv_bfloat16* __restrict__ y2b,
                          __nv_bfloat16* __restrict__ yb) {
    const int row = blockIdx.x;
    const int c = threadIdx.x;
    const size_t idx = (size_t)row * 256 + c;
    float v = x[idx];

    __shared__ float red[8];
    float s = v;
#pragma unroll
    for (int o = 16; o; o >>= 1) s += __shfl_xor_sync(~0u, s, o);
    if ((c & 31) == 0) red[c >> 5] = s;
    __syncthreads();
    float tot = red[0] + red[1] + red[2] + red[3] + red[4] + red[5] + red[6] + red[7];
    float mean = tot * (1.f / 256.f);
    float d = v - mean;
    float s2 = d * d;
#pragma unroll
    for (int o = 16; o; o >>= 1) s2 += __shfl_xor_sync(~0u, s2, o);
    __syncthreads();
    if ((c & 31) == 0) red[c >> 5] = s2;
    __syncthreads();
    float var = (red[0] + red[1] + red[2] + red[3] + red[4] + red[5] + red[6] + red[7]) * (1.f / 256.f);
    float out = d * rsqrtf(var + 1e-5f) * g[c] + b[c];
    y[idx] = out;
    if (y2b) y2b[idx] = __float2bfloat16(out + pos[idx]);
    if (yb) yb[idx] = __float2bfloat16(out);
}

// ---------------- deformable sampling w/ fused aw softmax, bf16 value -------
__global__ __launch_bounds__(256) void deform_kernel(
        const float* __restrict__ ref,
        const int* __restrict__ shapes,
        const int* __restrict__ lstart,
        __nv_bfloat16* __restrict__ out) {
    const int token = blockIdx.x;
    const int h = threadIdx.x >> 5;
    const int lane = threadIdx.x & 31;
    const int b = token / LQTOT;
    const int lq = token - b * LQTOT;

    __shared__ float sAw[8][16];

    {
        float v = -1e30f;
        if (lane < 16) v = g_offaw[(size_t)token * 384 + 256 + h * 16 + lane];
        float m = v;
#pragma unroll
        for (int o = 8; o; o >>= 1) m = fmaxf(m, __shfl_xor_sync(~0u, m, o, 16));
        float e = (lane < 16) ? __expf(v - m) : 0.f;
        float s = e;
#pragma unroll
        for (int o = 8; o; o >>= 1) s += __shfl_xor_sync(~0u, s, o, 16);
        if (lane < 16) sAw[h][lane] = e / s;
    }
    __syncwarp();

    const float* offp = g_offaw + (size_t)token * 384 + h * 32;
    const float* awp  = sAw[h];
    const float* refp = ref + ((size_t)(b * LQTOT + lq) * NL) * 2;
    const size_t vbase = ((size_t)b * SVAL) * 256;

    float acc = 0.f;
#pragma unroll
    for (int l = 0; l < NL; l++) {
        const int Hl = shapes[l * 2];
        const int Wl = shapes[l * 2 + 1];
        const int st = lstart[l];
        const float rx = refp[l * 2];
        const float ry = refp[l * 2 + 1];
        const float fW = (float)Wl, fH = (float)Hl;
#pragma unroll
        for (int p = 0; p < 4; p++) {
            float ox = offp[l * 8 + p * 2];
            float oy = offp[l * 8 + p * 2 + 1];
            float aww = awp[l * 4 + p];
            float x = (rx + ox / fW) * fW - 0.5f;
            float y = (ry + oy / fH) * fH - 0.5f;
            float fx0 = floorf(x), fy0 = floorf(y);
            float wx = x - fx0, wy = y - fy0;
            int x0 = (int)fx0, y0 = (int)fy0;
            float tw[4] = {(1.f - wx) * (1.f - wy), wx * (1.f - wy),
                           (1.f - wx) * wy, wx * wy};
            int xs[4] = {x0, x0 + 1, x0, x0 + 1};
            int ys[4] = {y0, y0, y0 + 1, y0 + 1};
#pragma unroll
            for (int tgt = 0; tgt < 4; tgt++) {
                int xi = xs[tgt], yi = ys[tgt];
                if (xi >= 0 && xi < Wl && yi >= 0 && yi < Hl) {
                    size_t vi = vbase + ((size_t)(st + yi * Wl + xi)) * 256 + h * 32 + lane;
                    acc = fmaf(__bfloat162float(gb_value[vi]), tw[tgt] * aww, acc);
                }
            }
        }
    }
    out[(size_t)token * 256 + h * 32 + lane] = __float2bfloat16(acc);
}

// ---------------- launch ----------------
static void* sym(const void* s) {
    void* p = nullptr;
    cudaGetSymbolAddress(&p, s);
    return p;
}

template <int EPI, int OUTBF, int NC>
static void launch_gemm(const __nv_bfloat16* A, const __nv_bfloat16* B, const float* bias,
                        const float* res, void* C, int M, int N, cudaStream_t st) {
    static bool done = false;
    if (!done) {
        cudaFuncSetAttribute(gemm_mma<EPI, OUTBF, NC>, cudaFuncAttributeMaxDynamicSharedMemorySize, GEMM_SMEM);
        done = true;
    }
    dim3 grid(N / 128, (M + 127) / 128);
    gemm_mma<EPI, OUTBF, NC><<<grid, 256, GEMM_SMEM, st>>>(A, B, bias, res, C, M, N);
}

extern "C" void kernel_launch(void* const* d_in, const int* in_sizes, int n_in,
                              void* d_out, int out_size) {
    const float* tgt  = (const float*)d_in[0];
    const float* pos  = (const float*)d_in[1];
    const float* ref  = (const float*)d_in[2];
    const float* src  = (const float*)d_in[3];
    const int* shapes = (const int*)d_in[4];
    const int* lstart = (const int*)d_in[5];
    const float* in_proj_w  = (const float*)d_in[6];
    const float* in_proj_b  = (const float*)d_in[7];
    const float* out_proj_w = (const float*)d_in[8];
    const float* out_proj_b = (const float*)d_in[9];
    const float* ln1_g = (const float*)d_in[10];
    const float* ln1_b = (const float*)d_in[11];
    const float* samp_off_w = (const float*)d_in[12];
    const float* samp_off_b = (const float*)d_in[13];
    const float* aw_w = (const float*)d_in[14];
    const float* aw_b = (const float*)d_in[15];
    const float* vp_w = (const float*)d_in[16];
    const float* vp_b = (const float*)d_in[17];
    const float* op_w = (const float*)d_in[18];
    const float* op_b = (const float*)d_in[19];
    const float* ln2_g = (const float*)d_in[20];
    const float* ln2_b = (const float*)d_in[21];
    const float* ffn1_w = (const float*)d_in[22];
    const float* ffn1_b = (const float*)d_in[23];
    const float* ffn2_w = (const float*)d_in[24];
    const float* ffn2_b = (const float*)d_in[25];
    const float* ln3_g = (const float*)d_in[26];
    const float* ln3_b = (const float*)d_in[27];

    float* p_res1  = (float*)sym(g_res1);
    float* p_ln1   = (float*)sym(g_ln1);
    float* p_offaw = (float*)sym(g_offaw);
    float* p_res2  = (float*)sym(g_res2);
    float* p_ln2   = (float*)sym(g_ln2);
    float* p_res3  = (float*)sym(g_res3);
    float* p_b384  = (float*)sym(g_bias384);

    __nv_bfloat16* b_qk    = (__nv_bfloat16*)sym(gb_qk);
    __nv_bfloat16* b_v     = (__nv_bfloat16*)sym(gb_v);
    __nv_bfloat16* b_value = (__nv_bfloat16*)sym(gb_value);
    __nv_bfloat16* b_tgt   = (__nv_bfloat16*)sym(gb_tgt);
    __nv_bfloat16* b_qksum = (__nv_bfloat16*)sym(gb_qksum);
    __nv_bfloat16* b_attn  = (__nv_bfloat16*)sym(gb_attn);
    __nv_bfloat16* b_query = (__nv_bfloat16*)sym(gb_query);
    __nv_bfloat16* b_src   = (__nv_bfloat16*)sym(gb_src);
    __nv_bfloat16* b_accum = (__nv_bfloat16*)sym(gb_accum);
    __nv_bfloat16* b_ln2   = (__nv_bfloat16*)sym(gb_ln2);
    __nv_bfloat16* b_ffn1  = (__nv_bfloat16*)sym(gb_ffn1);
    __nv_bfloat16* b_inproj = (__nv_bfloat16*)sym(gb_inproj);
    __nv_bfloat16* b_outproj = (__nv_bfloat16*)sym(gb_outproj);
    __nv_bfloat16* b_soffaw = (__nv_bfloat16*)sym(gb_soffaw);
    __nv_bfloat16* b_vp    = (__nv_bfloat16*)sym(gb_vp);
    __nv_bfloat16* b_op    = (__nv_bfloat16*)sym(gb_op);
    __nv_bfloat16* b_f1w   = (__nv_bfloat16*)sym(gb_f1w);
    __nv_bfloat16* b_f2w   = (__nv_bfloat16*)sym(gb_f2w);

    static cudaStream_t s2 = nullptr, s3 = nullptr;
    static cudaEvent_t evPre = nullptr, evV = nullptr, evVp = nullptr;
    if (!s2) {
        cudaStreamCreateWithFlags(&s2, cudaStreamNonBlocking);
        cudaStreamCreateWithFlags(&s3, cudaStreamNonBlocking);
        cudaEventCreateWithFlags(&evPre, cudaEventDisableTiming);
        cudaEventCreateWithFlags(&evV, cudaEventDisableTiming);
        cudaEventCreateWithFlags(&evVp, cudaEventDisableTiming);
    }

    // ---- weight converts + bias concat ----
    {
        WConvArgs a;
        const float* ins[8] = {in_proj_w, out_proj_w, samp_off_w, aw_w, vp_w, op_w, ffn1_w, ffn2_w};
        __nv_bfloat16* outs[8] = {b_inproj, b_outproj, b_soffaw, b_soffaw + 256 * 256,
                                  b_vp, b_op, b_f1w, b_f2w};
        int ns[8] = {768 * 256, 256 * 256, 256 * 256, 128 * 256, 256 * 256, 256 * 256, 1024 * 256, 256 * 1024};
        int acc4 = 0;
        for (int i = 0; i < 8; i++) {
            a.in[i] = (const float4*)ins[i];
            a.out[i] = (uint2*)outs[i];
            a.off4[i] = acc4;
            acc4 += ns[i] / 4;
        }
        a.off4[8] = acc4;
        a.sob4 = (const float4*)samp_off_b;
        a.awb4 = (const float4*)aw_b;
        a.bias384 = (float4*)p_b384;
        wconv_kernel<<<(acc4 + 255) / 256, 256>>>(a);
    }

    const int n4 = NTOK * CDIM / 4;
    prep_kernel<<<(n4 + 255) / 256, 256>>>(tgt, pos, b_qksum, b_tgt, n4);
    const int s4 = BB * SVAL * CDIM / 4;
    f2b_kernel<<<(s4 + 255) / 256, 256>>>(src, b_src, s4);

    cudaEventRecord(evPre, 0);

    launch_gemm<0, 1, 4>(b_qksum, b_inproj, in_proj_b, nullptr, b_qk, NTOK, 512, 0);

    cudaStreamWaitEvent(s3, evPre, 0);
    launch_gemm<0, 1, 4>(b_tgt, b_inproj + 512 * 256, in_proj_b + 512, nullptr, b_v, NTOK, 256, s3);
    cudaEventRecord(evV, s3);

    cudaStreamWaitEvent(s2, evPre, 0);
    launch_gemm<0, 1, 4>(b_src, b_vp, vp_b, nullptr, b_value, BB * SVAL, 256, s2);
    cudaEventRecord(evVp, s2);

    cudaStreamWaitEvent(0, evV, 0);
    attn_kernel<<<NSEQ * 2, 128>>>(b_qk, b_v, b_attn);

    launch_gemm<2, 0, 4>(b_attn, b_outproj, out_proj_b, tgt, p_res1, NTOK, 256, 0);
    ln_kernel<<<NTOK, 256>>>(p_res1, ln1_g, ln1_b, p_ln1, pos, b_query, nullptr);

    launch_gemm<0, 0, 4>(b_query, b_soffaw, p_b384, nullptr, p_offaw, NTOK, 384, 0);

    cudaStreamWaitEvent(0, evVp, 0);
    deform_kernel<<<NTOK, 256>>>(ref, shapes, lstart, b_accum);

    launch_gemm<2, 0, 4>(b_accum, b_op, op_b, p_ln1, p_res2, NTOK, 256, 0);
    ln_kernel<<<NTOK, 256>>>(p_res2, ln2_g, ln2_b, p_ln2, nullptr, nullptr, b_ln2);

    launch_gemm<1, 1, 4>(b_ln2, b_f1w, ffn1_b, nullptr, b_ffn1, NTOK, DFF, 0);
    launch_gemm<2, 0, 16>(b_ffn1, b_f2w, ffn2_b, p_ln2, p_res3, NTOK, 256, 0);
    ln_kernel<<<NTOK, 256>>>(p_res3, ln3_g, ln3_b, (float*)d_out, nullptr, nullptr, nullptr);
}

// round 10
// speedup vs baseline: 3.8068x; 1.2118x over previous
#include <cuda_runtime.h>
#include <cuda_bf16.h>
#include <math.h>
#include <stdint.h>

// ---------------- problem constants ----------------
#define BB    2
#define QQ    300
#define TSEQ  25
#define CDIM  256
#define NHEADS 8
#define HDIM  32
#define NL    4
#define NP    4
#define DFF   1024
#define LQTOT 7500
#define NTOK  15000
#define NSEQ  600
#define SVAL  21760

// ---------------- fp32 scratch ----------------
__device__ __align__(16) float g_res1[NTOK * CDIM];
__device__ __align__(16) float g_ln1[NTOK * CDIM];
__device__ __align__(16) float g_offaw[NTOK * 384];
__device__ __align__(16) float g_res2[NTOK * CDIM];
__device__ __align__(16) float g_ln2[NTOK * CDIM];
__device__ __align__(16) float g_res3[NTOK * CDIM];
__device__ __align__(16) float g_bias384[384];

// ---------------- bf16 scratch ----------------
__device__ __align__(16) __nv_bfloat16 gb_qk[NTOK * 512];
__device__ __align__(16) __nv_bfloat16 gb_v[NTOK * CDIM];
__device__ __align__(16) __nv_bfloat16 gb_value[(size_t)BB * SVAL * CDIM];
__device__ __align__(16) __nv_bfloat16 gb_tgt[NTOK * CDIM];
__device__ __align__(16) __nv_bfloat16 gb_qksum[NTOK * CDIM];
__device__ __align__(16) __nv_bfloat16 gb_attn[NTOK * CDIM];
__device__ __align__(16) __nv_bfloat16 gb_query[NTOK * CDIM];
__device__ __align__(16) __nv_bfloat16 gb_src[(size_t)BB * SVAL * CDIM];
__device__ __align__(16) __nv_bfloat16 gb_accum[NTOK * CDIM];
__device__ __align__(16) __nv_bfloat16 gb_ln2[NTOK * CDIM];
__device__ __align__(16) __nv_bfloat16 gb_ffn1[NTOK * DFF];
// weights
__device__ __align__(16) __nv_bfloat16 gb_inproj[768 * 256];
__device__ __align__(16) __nv_bfloat16 gb_outproj[256 * 256];
__device__ __align__(16) __nv_bfloat16 gb_soffaw[384 * 256];
__device__ __align__(16) __nv_bfloat16 gb_vp[256 * 256];
__device__ __align__(16) __nv_bfloat16 gb_op[256 * 256];
__device__ __align__(16) __nv_bfloat16 gb_f1w[1024 * 256];
__device__ __align__(16) __nv_bfloat16 gb_f2w[256 * 1024];

// ================= helpers =================
__device__ __forceinline__ uint32_t smem_to_u32(const void* p) {
    uint32_t a;
    asm("{ .reg .u64 t; cvta.to.shared.u64 t, %1; cvt.u32.u64 %0, t; }" : "=r"(a) : "l"(p));
    return a;
}
__device__ __forceinline__ void cpasync16(uint32_t dst, const void* src) {
    asm volatile("cp.async.ca.shared.global [%0], [%1], 16;" :: "r"(dst), "l"(src) : "memory");
}
#define CP_COMMIT() asm volatile("cp.async.commit_group;" ::: "memory")

__device__ __forceinline__ void ldmatrix_x4(uint32_t& r0, uint32_t& r1, uint32_t& r2,
                                            uint32_t& r3, uint32_t addr) {
    asm volatile("ldmatrix.sync.aligned.m8n8.x4.shared.b16 {%0,%1,%2,%3}, [%4];"
                 : "=r"(r0), "=r"(r1), "=r"(r2), "=r"(r3) : "r"(addr));
}
__device__ __forceinline__ void mma_bf16(float* d, const uint32_t* a, uint32_t b0, uint32_t b1) {
    asm volatile(
        "mma.sync.aligned.m16n8k16.row.col.f32.bf16.bf16.f32 "
        "{%0,%1,%2,%3}, {%4,%5,%6,%7}, {%8,%9}, {%0,%1,%2,%3};"
        : "+f"(d[0]), "+f"(d[1]), "+f"(d[2]), "+f"(d[3])
        : "r"(a[0]), "r"(a[1]), "r"(a[2]), "r"(a[3]), "r"(b0), "r"(b1));
}
__device__ __forceinline__ uint32_t pack_bf16(float x, float y) {
    uint32_t r;
    asm("cvt.rn.bf16x2.f32 %0, %1, %2;" : "=r"(r) : "f"(y), "f"(x));
    return r;
}

// ================= bf16 mma.sync GEMM, ldmatrix fragments =================
#define GEMM_SMEM (3 * 32768)

// Coalesced fill: warp covers 4 consecutive rows x 8 granules per step
// -> each cp.async warp-op touches 4 fully-used 128B lines (was 32 partial).
template <int K>
__device__ __forceinline__ void fill_chunk_b(uint32_t sbuf,
                                             const __nv_bfloat16* __restrict__ A,
                                             const __nv_bfloat16* __restrict__ B,
                                             int bm, int bn, int M, int k0, int tid) {
    const int which = tid >> 7;        // 0 = A tile, 1 = B tile
    const int t = tid & 127;
    const int g = t & 7;               // 16B granule within 128B row
    const int r0 = t >> 3;             // 0..15
    const uint32_t dbase = sbuf + (uint32_t)(which * 16384);
#pragma unroll
    for (int j = 0; j < 8; j++) {
        const int r = r0 + j * 16;     // 0..127
        int gr;
        if (which) {
            gr = bn + r;
        } else {
            gr = bm + r; if (gr >= M) gr = M - 1;
        }
        const __nv_bfloat16* gp = (which ? B : A) + (size_t)gr * K + k0 + g * 8;
        const uint32_t d = dbase + (uint32_t)(r * 128) + (uint32_t)(((g ^ (r & 7)) << 4));
        cpasync16(d, gp);
    }
}

template <int EPI, int OUTBF, int NC>
__global__ __launch_bounds__(256, 2) void gemm_mma(
        const __nv_bfloat16* __restrict__ A, const __nv_bfloat16* __restrict__ B,
        const float* __restrict__ bias, const float* __restrict__ res,
        void* __restrict__ Cout, int M, int N) {
    constexpr int K = NC * 64;
    extern __shared__ char smem[];
    const uint32_t smem_u = smem_to_u32(smem);
    const int tid = threadIdx.x;
    const int wid = tid >> 5;
    const int lane = tid & 31;
    const int wm = wid & 3;
    const int wn = wid >> 2;
    const int bm = blockIdx.y * 128;
    const int bn = blockIdx.x * 128;

    float acc[2][8][4];
#pragma unroll
    for (int mt = 0; mt < 2; mt++)
#pragma unroll
        for (int nt = 0; nt < 8; nt++)
#pragma unroll
            for (int e = 0; e < 4; e++) acc[mt][nt][e] = 0.f;

    fill_chunk_b<K>(smem_u, A, B, bm, bn, M, 0, tid);
    CP_COMMIT();
    fill_chunk_b<K>(smem_u + 32768, A, B, bm, bn, M, 64, tid);
    CP_COMMIT();

    // ldmatrix lane addressing
    const uint32_t laneRowOff = (uint32_t)((((lane & 7) + ((lane >> 3) & 1) * 8)) * 128);
    const int xr = lane & 7;
    const int gsel = lane >> 4;
    uint32_t swz[4];
#pragma unroll
    for (int ks = 0; ks < 4; ks++)
        swz[ks] = (uint32_t)(((ks * 2 + gsel) ^ xr) << 4);

    const uint32_t aBase0 = (uint32_t)((wm * 32) * 128) + laneRowOff;
    const uint32_t aBase1 = aBase0 + 16 * 128;
    uint32_t bBase[4];
#pragma unroll
    for (int j = 0; j < 4; j++)
        bBase[j] = 16384u + (uint32_t)((wn * 64 + j * 16) * 128) + laneRowOff;

#pragma unroll
    for (int i = 0; i < NC; i++) {
        const int stage = i % 3;
        if (i + 2 < NC) {
            const int fs = (i + 2) % 3;
            fill_chunk_b<K>(smem_u + (uint32_t)(fs * 32768), A, B, bm, bn, M, (i + 2) * 64, tid);
        }
        CP_COMMIT();
        asm volatile("cp.async.wait_group 2;" ::: "memory");
        __syncthreads();

        const uint32_t buf = smem_u + (uint32_t)(stage * 32768);

#pragma unroll
        for (int ks = 0; ks < 4; ks++) {
            const uint32_t s = swz[ks];
            uint32_t Af[2][4];
            ldmatrix_x4(Af[0][0], Af[0][1], Af[0][2], Af[0][3], buf + aBase0 + s);
            ldmatrix_x4(Af[1][0], Af[1][1], Af[1][2], Af[1][3], buf + aBase1 + s);
            uint32_t Bf[4][4];
#pragma unroll
            for (int j = 0; j < 4; j++)
                ldmatrix_x4(Bf[j][0], Bf[j][1], Bf[j][2], Bf[j][3], buf + bBase[j] + s);
#pragma unroll
            for (int mt = 0; mt < 2; mt++)
#pragma unroll
                for (int j = 0; j < 4; j++) {
                    mma_bf16(acc[mt][j * 2 + 0], Af[mt], Bf[j][0], Bf[j][2]);
                    mma_bf16(acc[mt][j * 2 + 1], Af[mt], Bf[j][1], Bf[j][3]);
                }
        }
        __syncthreads();
    }

    // ---- epilogue ----
    const int q = lane >> 2;
    const int ccol = bn + wn * 64;
    const float* biasp = bias + ccol;
    const int t2 = (lane & 3) * 2;
#pragma unroll
    for (int mt = 0; mt < 2; mt++) {
#pragma unroll
        for (int rs = 0; rs < 2; rs++) {
            const int r = bm + wm * 32 + mt * 16 + q + rs * 8;
            if (r >= M) continue;
            const float* rp = (EPI == 2) ? res + (size_t)r * N + ccol : nullptr;
#pragma unroll
            for (int nt = 0; nt < 8; nt++) {
                const int c = nt * 8 + t2;
                float vx = acc[mt][nt][rs * 2 + 0] + biasp[c];
                float vy = acc[mt][nt][rs * 2 + 1] + biasp[c + 1];
                if (EPI == 1) { vx = fmaxf(vx, 0.f); vy = fmaxf(vy, 0.f); }
                if (EPI == 2) { vx += rp[c]; vy += rp[c + 1]; }
                if (OUTBF) {
                    uint32_t* cp = (uint32_t*)((__nv_bfloat16*)Cout + (size_t)r * N + ccol + c);
                    *cp = pack_bf16(vx, vy);
                } else {
                    float* cp = (float*)Cout + (size_t)r * N + ccol + c;
                    *(float2*)cp = make_float2(vx, vy);
                }
            }
        }
    }
}

// ---------------- fused weight convert + bias concat ------------
struct WConvArgs {
    const float4* in[8];
    uint2* out[8];
    int off4[9];
    const float4* sob4;
    const float4* awb4;
    float4* bias384;
};
__global__ void wconv_kernel(WConvArgs a) {
    int i = blockIdx.x * blockDim.x + threadIdx.x;
    if (i < 96) {
        a.bias384[i] = (i < 64) ? a.sob4[i] : a.awb4[i - 64];
    }
    if (i >= a.off4[8]) return;
    int s = 0;
#pragma unroll
    for (int k = 1; k < 8; k++) s += (i >= a.off4[k]);
    int j = i - a.off4[s];
    float4 v = a.in[s][j];
    uint2 o;
    o.x = pack_bf16(v.x, v.y);
    o.y = pack_bf16(v.z, v.w);
    a.out[s][j] = o;
}

// ---------------- fp32 -> bf16 convert ----------------
__global__ void f2b_kernel(const float* __restrict__ in, __nv_bfloat16* __restrict__ out, int n4) {
    int i = blockIdx.x * blockDim.x + threadIdx.x;
    if (i < n4) {
        float4 v = ((const float4*)in)[i];
        uint2 o;
        o.x = pack_bf16(v.x, v.y);
        o.y = pack_bf16(v.z, v.w);
        ((uint2*)out)[i] = o;
    }
}

// ---------------- fused: qksum = bf16(tgt+pos), tgtb = bf16(tgt) ----------
__global__ void prep_kernel(const float* __restrict__ tgt, const float* __restrict__ pos,
                            __nv_bfloat16* __restrict__ qksum, __nv_bfloat16* __restrict__ tgtb,
                            int n4) {
    int i = blockIdx.x * blockDim.x + threadIdx.x;
    if (i < n4) {
        float4 x = ((const float4*)tgt)[i];
        float4 y = ((const float4*)pos)[i];
        uint2 t;
        t.x = pack_bf16(x.x, x.y);
        t.y = pack_bf16(x.z, x.w);
        ((uint2*)tgtb)[i] = t;
        uint2 o;
        o.x = pack_bf16(x.x + y.x, x.y + y.y);
        o.y = pack_bf16(x.z + y.z, x.w + y.w);
        ((uint2*)qksum)[i] = o;
    }
}

// ---------------- self-attention (lane = query), bf16 in/out ----------
__device__ __forceinline__ float bf_lo(uint32_t u) { return __uint_as_float(u << 16); }
__device__ __forceinline__ float bf_hi(uint32_t u) { return __uint_as_float(u & 0xFFFF0000u); }

__global__ __launch_bounds__(128) void attn_kernel(
        const __nv_bfloat16* __restrict__ qk, const __nv_bfloat16* __restrict__ v,
        __nv_bfloat16* __restrict__ out) {
    const int seq  = blockIdx.x >> 1;
    const int w    = threadIdx.x >> 5;
    const int h    = ((blockIdx.x & 1) << 2) + w;
    const int lane = threadIdx.x & 31;

    __shared__ float Ks[4][25][32];
    __shared__ float Vs[4][25][32];
    __shared__ float Os[4][25][36];

    const size_t tokbase = (size_t)seq * TSEQ;
    for (int i = lane; i < TSEQ * 32; i += 32) {
        int r = i >> 5;
        Ks[w][r][lane] = __bfloat162float(qk[(tokbase + r) * 512 + 256 + h * 32 + lane]);
        Vs[w][r][lane] = __bfloat162float(v[(tokbase + r) * 256 + h * 32 + lane]);
    }
    __syncwarp();

    if (lane < TSEQ) {
        float qv[32];
        const uint4* qp = (const uint4*)(qk + (tokbase + lane) * 512 + h * 32);
#pragma unroll
        for (int i = 0; i < 4; i++) {
            uint4 u = qp[i];
            uint32_t us[4] = {u.x, u.y, u.z, u.w};
#pragma unroll
            for (int j = 0; j < 4; j++) {
                qv[i * 8 + j * 2 + 0] = bf_lo(us[j]);
                qv[i * 8 + j * 2 + 1] = bf_hi(us[j]);
            }
        }

        const float scale = 0.1767766952966369f;
        float p[25];
        float m = -1e30f;
#pragma unroll
        for (int j = 0; j < TSEQ; j++) {
            const float* kp = Ks[w][j];
            float a = 0.f;
#pragma unroll
            for (int i = 0; i < 32; i++) a = fmaf(qv[i], kp[i], a);
            p[j] = a * scale;
            m = fmaxf(m, p[j]);
        }
        float sum = 0.f;
#pragma unroll
        for (int j = 0; j < TSEQ; j++) { p[j] = __expf(p[j] - m); sum += p[j]; }
        const float inv = 1.f / sum;
#pragma unroll
        for (int d4 = 0; d4 < 8; d4++) {
            float4 o = make_float4(0.f, 0.f, 0.f, 0.f);
#pragma unroll
            for (int j = 0; j < TSEQ; j++) {
                float4 v4 = ((const float4*)Vs[w][j])[d4];
                o.x = fmaf(p[j], v4.x, o.x); o.y = fmaf(p[j], v4.y, o.y);
                o.z = fmaf(p[j], v4.z, o.z); o.w = fmaf(p[j], v4.w, o.w);
            }
            float* orow = &Os[w][lane][d4 * 4];
            orow[0] = o.x * inv; orow[1] = o.y * inv;
            orow[2] = o.z * inv; orow[3] = o.w * inv;
        }
    }
    __syncwarp();
    for (int i = lane; i < TSEQ * 32; i += 32) {
        int r = i >> 5;
        out[(tokbase + r) * 256 + h * 32 + lane] = __float2bfloat16(Os[w][r][lane]);
    }
}

// ---------------- layernorm ----------------
__global__ void ln_kernel(const float* __restrict__ x, const float* __restrict__ g,
                          const float* __restrict__ b, float* __restrict__ y,
                          const float* __restrict__ pos, __nv_bfloat16* __restrict__ y2b,
                          __nv_bfloat16* __restrict__ yb) {
    const int row = blockIdx.x;
    const int c = threadIdx.x;
    const size_t idx = (size_t)row * 256 + c;
    float v = x[idx];

    __shared__ float red[8];
    float s = v;
#pragma unroll
    for (int o = 16; o; o >>= 1) s += __shfl_xor_sync(~0u, s, o);
    if ((c & 31) == 0) red[c >> 5] = s;
    __syncthreads();
    float tot = red[0] + red[1] + red[2] + red[3] + red[4] + red[5] + red[6] + red[7];
    float mean = tot * (1.f / 256.f);
    float d = v - mean;
    float s2 = d * d;
#pragma unroll
    for (int o = 16; o; o >>= 1) s2 += __shfl_xor_sync(~0u, s2, o);
    __syncthreads();
    if ((c & 31) == 0) red[c >> 5] = s2;
    __syncthreads();
    float var = (red[0] + red[1] + red[2] + red[3] + red[4] + red[5] + red[6] + red[7]) * (1.f / 256.f);
    float out = d * rsqrtf(var + 1e-5f) * g[c] + b[c];
    y[idx] = out;
    if (y2b) y2b[idx] = __float2bfloat16(out + pos[idx]);
    if (yb) yb[idx] = __float2bfloat16(out);
}

// ---------------- deformable sampling w/ fused aw softmax, bf16 value -------
__global__ __launch_bounds__(256) void deform_kernel(
        const float* __restrict__ ref,
        const int* __restrict__ shapes,
        const int* __restrict__ lstart,
        __nv_bfloat16* __restrict__ out) {
    const int token = blockIdx.x;
    const int h = threadIdx.x >> 5;
    const int lane = threadIdx.x & 31;
    const int b = token / LQTOT;
    const int lq = token - b * LQTOT;

    __shared__ float sAw[8][16];

    {
        float v = -1e30f;
        if (lane < 16) v = g_offaw[(size_t)token * 384 + 256 + h * 16 + lane];
        float m = v;
#pragma unroll
        for (int o = 8; o; o >>= 1) m = fmaxf(m, __shfl_xor_sync(~0u, m, o, 16));
        float e = (lane < 16) ? __expf(v - m) : 0.f;
        float s = e;
#pragma unroll
        for (int o = 8; o; o >>= 1) s += __shfl_xor_sync(~0u, s, o, 16);
        if (lane < 16) sAw[h][lane] = e / s;
    }
    __syncwarp();

    const float* offp = g_offaw + (size_t)token * 384 + h * 32;
    const float* awp  = sAw[h];
    const float* refp = ref + ((size_t)(b * LQTOT + lq) * NL) * 2;
    const size_t vbase = ((size_t)b * SVAL) * 256;

    float acc = 0.f;
#pragma unroll
    for (int l = 0; l < NL; l++) {
        const int Hl = shapes[l * 2];
        const int Wl = shapes[l * 2 + 1];
        const int st = lstart[l];
        const float rx = refp[l * 2];
        const float ry = refp[l * 2 + 1];
        const float fW = (float)Wl, fH = (float)Hl;
#pragma unroll
        for (int p = 0; p < 4; p++) {
            float ox = offp[l * 8 + p * 2];
            float oy = offp[l * 8 + p * 2 + 1];
            float aww = awp[l * 4 + p];
            float x = (rx + ox / fW) * fW - 0.5f;
            float y = (ry + oy / fH) * fH - 0.5f;
            float fx0 = floorf(x), fy0 = floorf(y);
            float wx = x - fx0, wy = y - fy0;
            int x0 = (int)fx0, y0 = (int)fy0;
            float tw[4] = {(1.f - wx) * (1.f - wy), wx * (1.f - wy),
                           (1.f - wx) * wy, wx * wy};
            int xs[4] = {x0, x0 + 1, x0, x0 + 1};
            int ys[4] = {y0, y0, y0 + 1, y0 + 1};
#pragma unroll
            for (int tgt = 0; tgt < 4; tgt++) {
                int xi = xs[tgt], yi = ys[tgt];
                if (xi >= 0 && xi < Wl && yi >= 0 && yi < Hl) {
                    size_t vi = vbase + ((size_t)(st + yi * Wl + xi)) * 256 + h * 32 + lane;
                    acc = fmaf(__bfloat162float(gb_value[vi]), tw[tgt] * aww, acc);
                }
            }
        }
    }
    out[(size_t)token * 256 + h * 32 + lane] = __float2bfloat16(acc);
}

// ---------------- launch ----------------
static void* sym(const void* s) {
    void* p = nullptr;
    cudaGetSymbolAddress(&p, s);
    return p;
}

template <int EPI, int OUTBF, int NC>
static void launch_gemm(const __nv_bfloat16* A, const __nv_bfloat16* B, const float* bias,
                        const float* res, void* C, int M, int N, cudaStream_t st) {
    static bool done = false;
    if (!done) {
        cudaFuncSetAttribute(gemm_mma<EPI, OUTBF, NC>, cudaFuncAttributeMaxDynamicSharedMemorySize, GEMM_SMEM);
        done = true;
    }
    dim3 grid(N / 128, (M + 127) / 128);
    gemm_mma<EPI, OUTBF, NC><<<grid, 256, GEMM_SMEM, st>>>(A, B, bias, res, C, M, N);
}

extern "C" void kernel_launch(void* const* d_in, const int* in_sizes, int n_in,
                              void* d_out, int out_size) {
    const float* tgt  = (const float*)d_in[0];
    const float* pos  = (const float*)d_in[1];
    const float* ref  = (const float*)d_in[2];
    const float* src  = (const float*)d_in[3];
    const int* shapes = (const int*)d_in[4];
    const int* lstart = (const int*)d_in[5];
    const float* in_proj_w  = (const float*)d_in[6];
    const float* in_proj_b  = (const float*)d_in[7];
    const float* out_proj_w = (const float*)d_in[8];
    const float* out_proj_b = (const float*)d_in[9];
    const float* ln1_g = (const float*)d_in[10];
    const float* ln1_b = (const float*)d_in[11];
    const float* samp_off_w = (const float*)d_in[12];
    const float* samp_off_b = (const float*)d_in[13];
    const float* aw_w = (const float*)d_in[14];
    const float* aw_b = (const float*)d_in[15];
    const float* vp_w = (const float*)d_in[16];
    const float* vp_b = (const float*)d_in[17];
    const float* op_w = (const float*)d_in[18];
    const float* op_b = (const float*)d_in[19];
    const float* ln2_g = (const float*)d_in[20];
    const float* ln2_b = (const float*)d_in[21];
    const float* ffn1_w = (const float*)d_in[22];
    const float* ffn1_b = (const float*)d_in[23];
    const float* ffn2_w = (const float*)d_in[24];
    const float* ffn2_b = (const float*)d_in[25];
    const float* ln3_g = (const float*)d_in[26];
    const float* ln3_b = (const float*)d_in[27];

    float* p_res1  = (float*)sym(g_res1);
    float* p_ln1   = (float*)sym(g_ln1);
    float* p_offaw = (float*)sym(g_offaw);
    float* p_res2  = (float*)sym(g_res2);
    float* p_ln2   = (float*)sym(g_ln2);
    float* p_res3  = (float*)sym(g_res3);
    float* p_b384  = (float*)sym(g_bias384);

    __nv_bfloat16* b_qk    = (__nv_bfloat16*)sym(gb_qk);
    __nv_bfloat16* b_v     = (__nv_bfloat16*)sym(gb_v);
    __nv_bfloat16* b_value = (__nv_bfloat16*)sym(gb_value);
    __nv_bfloat16* b_tgt   = (__nv_bfloat16*)sym(gb_tgt);
    __nv_bfloat16* b_qksum = (__nv_bfloat16*)sym(gb_qksum);
    __nv_bfloat16* b_attn  = (__nv_bfloat16*)sym(gb_attn);
    __nv_bfloat16* b_query = (__nv_bfloat16*)sym(gb_query);
    __nv_bfloat16* b_src   = (__nv_bfloat16*)sym(gb_src);
    __nv_bfloat16* b_accum = (__nv_bfloat16*)sym(gb_accum);
    __nv_bfloat16* b_ln2   = (__nv_bfloat16*)sym(gb_ln2);
    __nv_bfloat16* b_ffn1  = (__nv_bfloat16*)sym(gb_ffn1);
    __nv_bfloat16* b_inproj = (__nv_bfloat16*)sym(gb_inproj);
    __nv_bfloat16* b_outproj = (__nv_bfloat16*)sym(gb_outproj);
    __nv_bfloat16* b_soffaw = (__nv_bfloat16*)sym(gb_soffaw);
    __nv_bfloat16* b_vp    = (__nv_bfloat16*)sym(gb_vp);
    __nv_bfloat16* b_op    = (__nv_bfloat16*)sym(gb_op);
    __nv_bfloat16* b_f1w   = (__nv_bfloat16*)sym(gb_f1w);
    __nv_bfloat16* b_f2w   = (__nv_bfloat16*)sym(gb_f2w);

    static cudaStream_t s2 = nullptr, s3 = nullptr;
    static cudaEvent_t evPre = nullptr, evV = nullptr, evVp = nullptr;
    if (!s2) {
        cudaStreamCreateWithFlags(&s2, cudaStreamNonBlocking);
        cudaStreamCreateWithFlags(&s3, cudaStreamNonBlocking);
        cudaEventCreateWithFlags(&evPre, cudaEventDisableTiming);
        cudaEventCreateWithFlags(&evV, cudaEventDisableTiming);
        cudaEventCreateWithFlags(&evVp, cudaEventDisableTiming);
    }

    // ---- weight converts + bias concat ----
    {
        WConvArgs a;
        const float* ins[8] = {in_proj_w, out_proj_w, samp_off_w, aw_w, vp_w, op_w, ffn1_w, ffn2_w};
        __nv_bfloat16* outs[8] = {b_inproj, b_outproj, b_soffaw, b_soffaw + 256 * 256,
                                  b_vp, b_op, b_f1w, b_f2w};
        int ns[8] = {768 * 256, 256 * 256, 256 * 256, 128 * 256, 256 * 256, 256 * 256, 1024 * 256, 256 * 1024};
        int acc4 = 0;
        for (int i = 0; i < 8; i++) {
            a.in[i] = (const float4*)ins[i];
            a.out[i] = (uint2*)outs[i];
            a.off4[i] = acc4;
            acc4 += ns[i] / 4;
        }
        a.off4[8] = acc4;
        a.sob4 = (const float4*)samp_off_b;
        a.awb4 = (const float4*)aw_b;
        a.bias384 = (float4*)p_b384;
        wconv_kernel<<<(acc4 + 255) / 256, 256>>>(a);
    }

    const int n4 = NTOK * CDIM / 4;
    prep_kernel<<<(n4 + 255) / 256, 256>>>(tgt, pos, b_qksum, b_tgt, n4);
    const int s4 = BB * SVAL * CDIM / 4;
    f2b_kernel<<<(s4 + 255) / 256, 256>>>(src, b_src, s4);

    cudaEventRecord(evPre, 0);

    launch_gemm<0, 1, 4>(b_qksum, b_inproj, in_proj_b, nullptr, b_qk, NTOK, 512, 0);

    cudaStreamWaitEvent(s3, evPre, 0);
    launch_gemm<0, 1, 4>(b_tgt, b_inproj + 512 * 256, in_proj_b + 512, nullptr, b_v, NTOK, 256, s3);
    cudaEventRecord(evV, s3);

    cudaStreamWaitEvent(s2, evPre, 0);
    launch_gemm<0, 1, 4>(b_src, b_vp, vp_b, nullptr, b_value, BB * SVAL, 256, s2);
    cudaEventRecord(evVp, s2);

    cudaStreamWaitEvent(0, evV, 0);
    attn_kernel<<<NSEQ * 2, 128>>>(b_qk, b_v, b_attn);

    launch_gemm<2, 0, 4>(b_attn, b_outproj, out_proj_b, tgt, p_res1, NTOK, 256, 0);
    ln_kernel<<<NTOK, 256>>>(p_res1, ln1_g, ln1_b, p_ln1, pos, b_query, nullptr);

    launch_gemm<0, 0, 4>(b_query, b_soffaw, p_b384, nullptr, p_offaw, NTOK, 384, 0);

    cudaStreamWaitEvent(0, evVp, 0);
    deform_kernel<<<NTOK, 256>>>(ref, shapes, lstart, b_accum);

    launch_gemm<2, 0, 4>(b_accum, b_op, op_b, p_ln1, p_res2, NTOK, 256, 0);
    ln_kernel<<<NTOK, 256>>>(p_res2, ln2_g, ln2_b, p_ln2, nullptr, nullptr, b_ln2);

    launch_gemm<1, 1, 4>(b_ln2, b_f1w, ffn1_b, nullptr, b_ffn1, NTOK, DFF, 0);
    launch_gemm<2, 0, 16>(b_ffn1, b_f2w, ffn2_b, p_ln2, p_res3, NTOK, 256, 0);
    ln_kernel<<<NTOK, 256>>>(p_res3, ln3_g, ln3_b, (float*)d_out, nullptr, nullptr, nullptr);
}